// round 1
// baseline (speedup 1.0000x reference)
#include <cuda_runtime.h>
#include <math.h>

#define Bq 2
#define T 2048
#define C 1024
#define H 16
#define D 64
#define E 4
#define BT (Bq*T)
#define FF (4*C)
#define GROUP_CAP (BT + E*128)
#define NTILES (GROUP_CAP/128)
#define EPS_RMS 1.1920929e-07f

// ---------------- scratch (static device globals; no allocation) ----------------
__device__ float g_h1[BT*C];
__device__ float g_q[BT*C];
__device__ float g_k[BT*C];
__device__ float g_v[BT*C];
__device__ float g_y[BT*C];
__device__ float g_x2[BT*C];
__device__ float g_h2[BT*C];
__device__ float g_h2g[GROUP_CAP*C];
__device__ float g_hid[GROUP_CAP*FF];
__device__ float g_outg[GROUP_CAP*C];
__device__ int   g_expert[BT];
__device__ int   g_counts[E];
__device__ int   g_cursor[E];
__device__ int   g_segstart[E];
__device__ int   g_tileExpert[NTILES];
__device__ int   g_tokenOfRow[GROUP_CAP];
__device__ double g_expsum[E];
__device__ double g_zsum;
__device__ double g_entsum;

// ---------------- reset (graph replays must be idempotent) ----------------
__global__ void reset_kernel() {
    int i = blockIdx.x * blockDim.x + threadIdx.x;
    if (i < E) { g_counts[i] = 0; g_cursor[i] = 0; g_expsum[i] = 0.0; }
    if (i == 0) { g_zsum = 0.0; g_entsum = 0.0; }
    if (i < NTILES) g_tileExpert[i] = -1;
    if (i < GROUP_CAP) g_tokenOfRow[i] = -1;
}

__global__ void zero_h2g_kernel() {
    // one block per row, 256 threads, one float4 each (C/4 = 256)
    ((float4*)(g_h2g + (size_t)blockIdx.x * C))[threadIdx.x] =
        make_float4(0.f, 0.f, 0.f, 0.f);
}

// ---------------- RMSNorm over C (one block / token, 256 threads) ----------------
__global__ void rmsnorm_kernel(const float* __restrict__ in, float* __restrict__ out) {
    int t = blockIdx.x;
    const float4* ip = (const float4*)(in + (size_t)t * C);
    float4* op = (float4*)(out + (size_t)t * C);
    __shared__ float red[8];
    float4 v = ip[threadIdx.x];
    float ss = v.x*v.x + v.y*v.y + v.z*v.z + v.w*v.w;
    #pragma unroll
    for (int o = 16; o; o >>= 1) ss += __shfl_xor_sync(0xffffffffu, ss, o);
    if ((threadIdx.x & 31) == 0) red[threadIdx.x >> 5] = ss;
    __syncthreads();
    if (threadIdx.x == 0) {
        float s = 0.f;
        #pragma unroll
        for (int w = 0; w < 8; w++) s += red[w];
        red[0] = s;
    }
    __syncthreads();
    float r = rsqrtf(red[0] / (float)C + EPS_RMS);
    op[threadIdx.x] = make_float4(v.x*r, v.y*r, v.z*r, v.w*r);
}

// ---------------- per-head RMSNorm + RoPE for q and k ----------------
// grid = BT blocks, 512 threads = 16 warps (one warp per head); lane d in [0,32)
__global__ void qk_rope_kernel(float* __restrict__ q, float* __restrict__ k) {
    int tok  = blockIdx.x;
    int head = threadIdx.x >> 5;
    int lane = threadIdx.x & 31;
    int tpos = tok % T;
    float ex  = (float)(2 * lane) / 64.0f;
    float inv = 1.0f / powf(10000.0f, ex);
    float ang = (float)tpos * inv;
    float c = cosf(ang), s = sinf(ang);
    float* ptrs[2] = { q, k };
    #pragma unroll
    for (int m = 0; m < 2; m++) {
        float* base = ptrs[m] + (size_t)tok * C + head * D;
        float x1 = base[lane], x2 = base[lane + 32];
        float ss = x1*x1 + x2*x2;
        #pragma unroll
        for (int o = 16; o; o >>= 1) ss += __shfl_xor_sync(0xffffffffu, ss, o);
        float r = rsqrtf(ss / (float)D + EPS_RMS);
        x1 *= r; x2 *= r;
        base[lane]      =  x1 * c + x2 * s;
        base[lane + 32] = -x1 * s + x2 * c;
    }
}

// ---------------- flash attention (fp32, online softmax) ----------------
// grid (T/128, B*H), 128 threads; thread owns one query row.
#define QT 128
#define KT 32
__global__ void __launch_bounds__(128) attn_kernel(
    const float* __restrict__ q, const float* __restrict__ k,
    const float* __restrict__ v, float* __restrict__ y)
{
    __shared__ __align__(16) float Ks[KT][D];
    __shared__ __align__(16) float Vs[KT][D];
    int bh = blockIdx.y;
    int b = bh / H, h = bh % H;
    int q0 = blockIdx.x * QT;
    int row = q0 + threadIdx.x;                 // position within T
    const float4* qp = (const float4*)(q + ((size_t)(b*T + row) * C + h * D));
    float qr[D];
    #pragma unroll
    for (int i = 0; i < D/4; i++) {
        float4 t4 = qp[i];
        qr[4*i] = t4.x; qr[4*i+1] = t4.y; qr[4*i+2] = t4.z; qr[4*i+3] = t4.w;
    }
    float acc[D];
    #pragma unroll
    for (int d = 0; d < D; d++) acc[d] = 0.f;
    float mrun = -INFINITY, lrun = 0.f;

    int kend = q0 + QT;
    for (int k0 = 0; k0 < kend; k0 += KT) {
        __syncthreads();
        #pragma unroll
        for (int i = 0; i < 4; i++) {
            int lin = threadIdx.x + i * 128;       // 0..511 float4 units
            int r = lin >> 4, c4 = lin & 15;
            const float4* kp = (const float4*)(k + ((size_t)(b*T + k0 + r) * C + h * D));
            const float4* vp = (const float4*)(v + ((size_t)(b*T + k0 + r) * C + h * D));
            ((float4*)&Ks[r][0])[c4] = kp[c4];
            ((float4*)&Vs[r][0])[c4] = vp[c4];
        }
        __syncthreads();

        float s[KT];
        #pragma unroll
        for (int kk = 0; kk < KT; kk++) {
            const float4* kr = (const float4*)&Ks[kk][0];
            float d0 = 0.f, d1 = 0.f, d2 = 0.f, d3 = 0.f;
            #pragma unroll
            for (int i = 0; i < 16; i += 4) {
                float4 a = kr[i], bb = kr[i+1], cc = kr[i+2], dd = kr[i+3];
                d0 += qr[4*i+0]*a.x + qr[4*i+1]*a.y + qr[4*i+2]*a.z + qr[4*i+3]*a.w;
                d1 += qr[4*i+4]*bb.x + qr[4*i+5]*bb.y + qr[4*i+6]*bb.z + qr[4*i+7]*bb.w;
                d2 += qr[4*i+8]*cc.x + qr[4*i+9]*cc.y + qr[4*i+10]*cc.z + qr[4*i+11]*cc.w;
                d3 += qr[4*i+12]*dd.x + qr[4*i+13]*dd.y + qr[4*i+14]*dd.z + qr[4*i+15]*dd.w;
            }
            float dot = (d0 + d1) + (d2 + d3);
            s[kk] = (k0 + kk <= row) ? dot * 0.125f : -INFINITY;
        }
        float tm = -INFINITY;
        #pragma unroll
        for (int kk = 0; kk < KT; kk++) tm = fmaxf(tm, s[kk]);
        float nm = fmaxf(mrun, tm);
        float scale = expf(mrun - nm);     // first tile: exp(-inf)=0
        float psum = 0.f;
        #pragma unroll
        for (int kk = 0; kk < KT; kk++) { s[kk] = expf(s[kk] - nm); psum += s[kk]; }
        #pragma unroll
        for (int d = 0; d < D; d++) acc[d] *= scale;
        #pragma unroll
        for (int kk = 0; kk < KT; kk++) {
            float pk = s[kk];
            const float4* vr = (const float4*)&Vs[kk][0];
            #pragma unroll
            for (int i = 0; i < 16; i++) {
                float4 vv = vr[i];
                acc[4*i+0] += pk * vv.x; acc[4*i+1] += pk * vv.y;
                acc[4*i+2] += pk * vv.z; acc[4*i+3] += pk * vv.w;
            }
        }
        lrun = lrun * scale + psum;
        mrun = nm;
    }
    float inv_l = 1.0f / lrun;
    float4* yp = (float4*)(y + ((size_t)(b*T + row) * C + h * D));
    #pragma unroll
    for (int i = 0; i < 16; i++)
        yp[i] = make_float4(acc[4*i]*inv_l, acc[4*i+1]*inv_l, acc[4*i+2]*inv_l, acc[4*i+3]*inv_l);
}

// ---------------- 128x128x8 fp32 SGEMM, optional expert indirection + epilogue ----
// epi: 0 plain, 1 C = acc + resid, 2 C = relu(acc)^2
__global__ void __launch_bounds__(256) sgemm128(
    const float* __restrict__ A,
    const float* __restrict__ Bb, size_t bstride,
    float* __restrict__ Cc,
    const float* __restrict__ resid,
    const int* __restrict__ tileExpert,
    int N, int K, int epi)
{
    int by = blockIdx.y, bx = blockIdx.x;
    int e = 0;
    if (tileExpert) { e = tileExpert[by]; if (e < 0) return; }
    const float* Bm = Bb + (size_t)e * bstride;

    __shared__ __align__(16) float As[8][128];
    __shared__ __align__(16) float Bs[8][128];

    int tid = threadIdx.x;
    int tx = tid & 15, ty = tid >> 4;
    int row0 = by * 128, col0 = bx * 128;

    float acc[8][8];
    #pragma unroll
    for (int i = 0; i < 8; i++)
        #pragma unroll
        for (int j = 0; j < 8; j++) acc[i][j] = 0.f;

    int arow = tid >> 1, acol4 = (tid & 1) * 4;
    int brow = tid >> 5, bcol4 = (tid & 31) * 4;
    const float* Aptr = A  + (size_t)(row0 + arow) * K + acol4;
    const float* Bptr = Bm + (size_t)brow * N + col0 + bcol4;

    for (int k0 = 0; k0 < K; k0 += 8) {
        float4 av = *(const float4*)Aptr; Aptr += 8;
        float4 bv = *(const float4*)Bptr; Bptr += (size_t)8 * N;
        __syncthreads();
        As[acol4+0][arow] = av.x; As[acol4+1][arow] = av.y;
        As[acol4+2][arow] = av.z; As[acol4+3][arow] = av.w;
        *(float4*)&Bs[brow][bcol4] = bv;
        __syncthreads();
        #pragma unroll
        for (int kk = 0; kk < 8; kk++) {
            float ar[8], br[8];
            *(float4*)&ar[0] = *(const float4*)&As[kk][ty*8];
            *(float4*)&ar[4] = *(const float4*)&As[kk][ty*8+4];
            *(float4*)&br[0] = *(const float4*)&Bs[kk][tx*8];
            *(float4*)&br[4] = *(const float4*)&Bs[kk][tx*8+4];
            #pragma unroll
            for (int i = 0; i < 8; i++)
                #pragma unroll
                for (int j = 0; j < 8; j++)
                    acc[i][j] = fmaf(ar[i], br[j], acc[i][j]);
        }
    }

    #pragma unroll
    for (int i = 0; i < 8; i++) {
        size_t r = (size_t)(row0 + ty*8 + i);
        float* crow = Cc + r * N + col0 + tx*8;
        float4 v0 = make_float4(acc[i][0], acc[i][1], acc[i][2], acc[i][3]);
        float4 v1 = make_float4(acc[i][4], acc[i][5], acc[i][6], acc[i][7]);
        if (epi == 1) {
            const float4 r0 = *(const float4*)(resid + r * N + col0 + tx*8);
            const float4 r1 = *(const float4*)(resid + r * N + col0 + tx*8 + 4);
            v0.x += r0.x; v0.y += r0.y; v0.z += r0.z; v0.w += r0.w;
            v1.x += r1.x; v1.y += r1.y; v1.z += r1.z; v1.w += r1.w;
        } else if (epi == 2) {
            v0.x = fmaxf(v0.x, 0.f); v0.x *= v0.x;
            v0.y = fmaxf(v0.y, 0.f); v0.y *= v0.y;
            v0.z = fmaxf(v0.z, 0.f); v0.z *= v0.z;
            v0.w = fmaxf(v0.w, 0.f); v0.w *= v0.w;
            v1.x = fmaxf(v1.x, 0.f); v1.x *= v1.x;
            v1.y = fmaxf(v1.y, 0.f); v1.y *= v1.y;
            v1.z = fmaxf(v1.z, 0.f); v1.z *= v1.z;
            v1.w = fmaxf(v1.w, 0.f); v1.w *= v1.w;
        }
        *(float4*)crow = v0;
        *(float4*)(crow + 4) = v1;
    }
}

// ---------------- router: logits, softmax, argmax, aux stats ----------------
__global__ void router_kernel(const float* __restrict__ h2, const float* __restrict__ Wr) {
    int t = blockIdx.x;
    __shared__ float red[16];   // 4 warps x 4 experts
    float a0 = 0.f, a1 = 0.f, a2 = 0.f, a3 = 0.f;
    const float* hp = h2 + (size_t)t * C;
    for (int c = threadIdx.x; c < C; c += 128) {
        float hv = hp[c];
        const float4 w = *(const float4*)(Wr + (size_t)c * E);
        a0 += hv * w.x; a1 += hv * w.y; a2 += hv * w.z; a3 += hv * w.w;
    }
    #pragma unroll
    for (int o = 16; o; o >>= 1) {
        a0 += __shfl_xor_sync(0xffffffffu, a0, o);
        a1 += __shfl_xor_sync(0xffffffffu, a1, o);
        a2 += __shfl_xor_sync(0xffffffffu, a2, o);
        a3 += __shfl_xor_sync(0xffffffffu, a3, o);
    }
    if ((threadIdx.x & 31) == 0) {
        int w = threadIdx.x >> 5;
        red[w*4+0] = a0; red[w*4+1] = a1; red[w*4+2] = a2; red[w*4+3] = a3;
    }
    __syncthreads();
    if (threadIdx.x == 0) {
        float lg[4];
        #pragma unroll
        for (int e = 0; e < 4; e++)
            lg[e] = red[e] + red[4+e] + red[8+e] + red[12+e];
        int arg = 0;
        #pragma unroll
        for (int e = 1; e < 4; e++) if (lg[e] > lg[arg]) arg = e;
        float m = fmaxf(fmaxf(lg[0], lg[1]), fmaxf(lg[2], lg[3]));
        float ez[4]; float sum = 0.f;
        #pragma unroll
        for (int e = 0; e < 4; e++) { ez[e] = expf(lg[e] - m); sum += ez[e]; }
        float p[4];
        #pragma unroll
        for (int e = 0; e < 4; e++) p[e] = ez[e] / sum;
        g_expert[t] = arg;
        atomicAdd(&g_counts[arg], 1);
        #pragma unroll
        for (int e = 0; e < 4; e++) atomicAdd(&g_expsum[e], (double)p[e]);
        float lse = m + logf(sum);
        atomicAdd(&g_zsum, (double)lse * (double)lse);
        float ent = 0.f;
        #pragma unroll
        for (int e = 0; e < 4; e++) ent -= p[e] * logf(p[e] + 1e-9f);
        atomicAdd(&g_entsum, (double)ent);
    }
}

// ---------------- segment offsets + tile->expert map (1 thread) ----------------
__global__ void offsets_kernel() {
    if (threadIdx.x == 0 && blockIdx.x == 0) {
        int off = 0;
        for (int e = 0; e < E; e++) {
            g_segstart[e] = off;
            int padded = (g_counts[e] + 127) & ~127;
            for (int i = 0; i < padded / 128; i++)
                g_tileExpert[off / 128 + i] = e;
            off += padded;
        }
    }
}

// ---------------- gather tokens into grouped buffer ----------------
__global__ void assign_kernel(const float* __restrict__ h2) {
    int t = blockIdx.x;
    __shared__ int slot_s;
    if (threadIdx.x == 0) {
        int e = g_expert[t];
        int slot = g_segstart[e] + atomicAdd(&g_cursor[e], 1);
        g_tokenOfRow[slot] = t;
        slot_s = slot;
    }
    __syncthreads();
    int s = slot_s;
    ((float4*)(g_h2g + (size_t)s * C))[threadIdx.x] =
        ((const float4*)(h2 + (size_t)t * C))[threadIdx.x];
}

// ---------------- scatter: x_out = x2 + moe_out ----------------
__global__ void scatter_kernel(const float* __restrict__ x2, float* __restrict__ out) {
    int r = blockIdx.x;
    int t = g_tokenOfRow[r];
    if (t < 0) return;
    float4 a = ((const float4*)(x2 + (size_t)t * C))[threadIdx.x];
    float4 b = ((const float4*)(g_outg + (size_t)r * C))[threadIdx.x];
    ((float4*)(out + (size_t)t * C))[threadIdx.x] =
        make_float4(a.x + b.x, a.y + b.y, a.z + b.z, a.w + b.w);
}

// ---------------- aux scalars ----------------
__global__ void scalars_kernel(float* __restrict__ out) {
    if (threadIdx.x == 0 && blockIdx.x == 0) {
        const double NTOK = (double)BT;
        double aux = 0.0;
        for (int e = 0; e < E; e++) {
            double actual = (double)g_counts[e] / NTOK;
            double expd   = g_expsum[e] / NTOK;
            aux += actual * expd;
        }
        size_t base = (size_t)BT * C;
        out[base + 0] = (float)((double)E * aux);
        out[base + 1] = (float)(g_zsum / NTOK);
        out[base + 2] = (float)((g_entsum / NTOK) / log((double)E));
        for (int e = 0; e < E; e++)
            out[base + 3 + e] = (float)((double)g_counts[e] / NTOK);
    }
}

// ---------------- launch ----------------
static void* sym(const void* s) { void* p = nullptr; cudaGetSymbolAddress(&p, s); return p; }

extern "C" void kernel_launch(void* const* d_in, const int* in_sizes, int n_in,
                              void* d_out, int out_size)
{
    const float* x     = (const float*)d_in[0];
    const float* Wq    = (const float*)d_in[1];
    const float* Wk    = (const float*)d_in[2];
    const float* Wv    = (const float*)d_in[3];
    const float* Wo    = (const float*)d_in[4];
    const float* Wr    = (const float*)d_in[5];
    const float* Wfc   = (const float*)d_in[6];
    const float* Wproj = (const float*)d_in[7];
    float* out = (float*)d_out;

    float* h1   = (float*)sym(g_h1);
    float* qb   = (float*)sym(g_q);
    float* kb   = (float*)sym(g_k);
    float* vb   = (float*)sym(g_v);
    float* yb   = (float*)sym(g_y);
    float* x2   = (float*)sym(g_x2);
    float* h2   = (float*)sym(g_h2);
    float* h2g  = (float*)sym(g_h2g);
    float* hid  = (float*)sym(g_hid);
    float* outg = (float*)sym(g_outg);
    int*   tileE = (int*)sym(g_tileExpert);

    reset_kernel<<<(GROUP_CAP + 255) / 256, 256>>>();

    // h1 = rmsnorm(x)
    rmsnorm_kernel<<<BT, 256>>>(x, h1);

    // q/k/v projections
    dim3 gq(C / 128, BT / 128);
    sgemm128<<<gq, 256>>>(h1, Wq, 0, qb, nullptr, nullptr, C, C, 0);
    sgemm128<<<gq, 256>>>(h1, Wk, 0, kb, nullptr, nullptr, C, C, 0);
    sgemm128<<<gq, 256>>>(h1, Wv, 0, vb, nullptr, nullptr, C, C, 0);

    // per-head rmsnorm + rope
    qk_rope_kernel<<<BT, 512>>>(qb, kb);

    // attention
    attn_kernel<<<dim3(T / QT, Bq * H), 128>>>(qb, kb, vb, yb);

    // x2 = x + y @ Wo
    sgemm128<<<gq, 256>>>(yb, Wo, 0, x2, x, nullptr, C, C, 1);

    // h2 = rmsnorm(x2)
    rmsnorm_kernel<<<BT, 256>>>(x2, h2);

    // router + grouping
    router_kernel<<<BT, 128>>>(h2, Wr);
    offsets_kernel<<<1, 32>>>();
    zero_h2g_kernel<<<GROUP_CAP, 256>>>();
    assign_kernel<<<BT, 256>>>(h2);

    // MoE: hid = relu(h2g @ Wfc[e])^2 ; outg = hid @ Wproj[e]
    sgemm128<<<dim3(FF / 128, NTILES), 256>>>(h2g, Wfc, (size_t)C * FF, hid,
                                              nullptr, tileE, FF, C, 2);
    sgemm128<<<dim3(C / 128, NTILES), 256>>>(hid, Wproj, (size_t)FF * C, outg,
                                             nullptr, tileE, C, FF, 0);

    // x_out = x2 + moe_out (per routed row); aux scalars
    scatter_kernel<<<GROUP_CAP, 256>>>(x2, out);
    scalars_kernel<<<1, 32>>>(out);
}

// round 3
// speedup vs baseline: 1.6447x; 1.6447x over previous
#include <cuda_runtime.h>
#include <cuda_bf16.h>
#include <cstdint>
#include <math.h>

#define Bq 2
#define T 2048
#define C 1024
#define H 16
#define D 64
#define E 4
#define BT (Bq*T)
#define FF (4*C)
#define GROUP_CAP (BT + E*128)
#define NTILES (GROUP_CAP/128)
#define EPS_RMS 1.1920929e-07f

#define SMEM_SWIZZLE_128B(b) ((b) ^ (((b) >> 3) & 0x70))

__device__ __forceinline__ uint32_t smem_to_u32(const void* p) {
    uint32_t a;
    asm("{ .reg .u64 t; cvta.to.shared.u64 t, %1; cvt.u32.u64 %0, t; }" : "=r"(a) : "l"(p));
    return a;
}
__device__ __forceinline__ void ldsm4(uint32_t* r, uint32_t addr) {
    asm volatile("ldmatrix.sync.aligned.m8n8.x4.shared.b16 {%0,%1,%2,%3}, [%4];"
                 : "=r"(r[0]), "=r"(r[1]), "=r"(r[2]), "=r"(r[3]) : "r"(addr));
}
__device__ __forceinline__ void mma_bf16(float* c, const uint32_t* a, const uint32_t* b) {
    asm volatile("mma.sync.aligned.m16n8k16.row.col.f32.bf16.bf16.f32 "
        "{%0,%1,%2,%3}, {%4,%5,%6,%7}, {%8,%9}, {%0,%1,%2,%3};"
        : "+f"(c[0]), "+f"(c[1]), "+f"(c[2]), "+f"(c[3])
        : "r"(a[0]), "r"(a[1]), "r"(a[2]), "r"(a[3]), "r"(b[0]), "r"(b[1]));
}
#define CP16(s, g) asm volatile("cp.async.cg.shared.global [%0], [%1], 16;" \
                                :: "r"(s), "l"(g) : "memory")

// ======================= scratch (static device globals) =======================
__device__ __nv_bfloat16 g_h1_hi[BT*C], g_h1_lo[BT*C];
__device__ float g_q[BT*C], g_k[BT*C], g_v[BT*C];
__device__ __nv_bfloat16 g_y_hi[BT*C], g_y_lo[BT*C];
__device__ float g_x2[BT*C], g_h2[BT*C];
__device__ __nv_bfloat16 g_h2g_hi[GROUP_CAP*C], g_h2g_lo[GROUP_CAP*C];
__device__ __nv_bfloat16 g_hid_hi[(size_t)GROUP_CAP*FF], g_hid_lo[(size_t)GROUP_CAP*FF];
__device__ float g_outg[GROUP_CAP*C];
__device__ __nv_bfloat16 g_wq_hi[C*C], g_wq_lo[C*C];
__device__ __nv_bfloat16 g_wk_hi[C*C], g_wk_lo[C*C];
__device__ __nv_bfloat16 g_wv_hi[C*C], g_wv_lo[C*C];
__device__ __nv_bfloat16 g_wo_hi[C*C], g_wo_lo[C*C];
__device__ __nv_bfloat16 g_wfc_hi[(size_t)E*C*FF], g_wfc_lo[(size_t)E*C*FF];   // [E][FF,C]
__device__ __nv_bfloat16 g_wpj_hi[(size_t)E*FF*C], g_wpj_lo[(size_t)E*FF*C];   // [E][C,FF]
__device__ int   g_expert[BT];
__device__ int   g_counts[E];
__device__ int   g_cursor[E];
__device__ int   g_segstart[E];
__device__ int   g_tileExpert[NTILES];
__device__ int   g_tokenOfRow[GROUP_CAP];
__device__ double g_expsum[E];
__device__ double g_zsum;
__device__ double g_entsum;

__device__ __forceinline__ void bsplit(float v, __nv_bfloat16& h, __nv_bfloat16& l) {
    h = __float2bfloat16(v);
    l = __float2bfloat16(v - __bfloat162float(h));
}

// ======================= small kernels =======================
__global__ void reset_kernel() {
    int i = blockIdx.x * blockDim.x + threadIdx.x;
    if (i < E) { g_counts[i] = 0; g_cursor[i] = 0; g_expsum[i] = 0.0; }
    if (i == 0) { g_zsum = 0.0; g_entsum = 0.0; }
    if (i < NTILES) g_tileExpert[i] = -1;
    if (i < GROUP_CAP) g_tokenOfRow[i] = -1;
}

__global__ void zero_h2g_pair_kernel() {
    int r = blockIdx.x;
    uint2 z = make_uint2(0u, 0u);
    ((uint2*)(g_h2g_hi + (size_t)r * C))[threadIdx.x] = z;
    ((uint2*)(g_h2g_lo + (size_t)r * C))[threadIdx.x] = z;
}

// transpose + bf16-split weights: W [Kd, Nd] fp32 -> T [Nd, Kd] bf16 hi/lo, batched over z
__global__ void wconv_kernel(const float* __restrict__ W,
                             __nv_bfloat16* __restrict__ Thi, __nv_bfloat16* __restrict__ Tlo,
                             int Kd, int Nd) {
    __shared__ float tile[32][33];
    int b = blockIdx.z;
    const float* Wb = W + (size_t)b * Kd * Nd;
    __nv_bfloat16* Th = Thi + (size_t)b * Kd * Nd;
    __nv_bfloat16* Tl = Tlo + (size_t)b * Kd * Nd;
    int n0 = blockIdx.x * 32, k0 = blockIdx.y * 32;
    int tx = threadIdx.x, ty = threadIdx.y;
    #pragma unroll
    for (int i = 0; i < 4; i++)
        tile[ty + 8*i][tx] = Wb[(size_t)(k0 + ty + 8*i) * Nd + n0 + tx];
    __syncthreads();
    #pragma unroll
    for (int i = 0; i < 4; i++) {
        int n = n0 + ty + 8*i, k = k0 + tx;
        float v = tile[tx][ty + 8*i];
        __nv_bfloat16 h, l; bsplit(v, h, l);
        Th[(size_t)n * Kd + k] = h;
        Tl[(size_t)n * Kd + k] = l;
    }
}

// RMSNorm over C; optional fp32 out, optional bf16 hi/lo pair out
__global__ void rmsnorm_kernel(const float* __restrict__ in, float* __restrict__ outf,
                               __nv_bfloat16* __restrict__ ohi, __nv_bfloat16* __restrict__ olo) {
    int t = blockIdx.x;
    const float4* ip = (const float4*)(in + (size_t)t * C);
    __shared__ float red[8];
    float4 v = ip[threadIdx.x];
    float ss = v.x*v.x + v.y*v.y + v.z*v.z + v.w*v.w;
    #pragma unroll
    for (int o = 16; o; o >>= 1) ss += __shfl_xor_sync(0xffffffffu, ss, o);
    if ((threadIdx.x & 31) == 0) red[threadIdx.x >> 5] = ss;
    __syncthreads();
    if (threadIdx.x == 0) {
        float s = 0.f;
        #pragma unroll
        for (int w = 0; w < 8; w++) s += red[w];
        red[0] = s;
    }
    __syncthreads();
    float r = rsqrtf(red[0] / (float)C + EPS_RMS);
    float4 o = make_float4(v.x*r, v.y*r, v.z*r, v.w*r);
    if (outf) ((float4*)(outf + (size_t)t * C))[threadIdx.x] = o;
    if (ohi) {
        __nv_bfloat16 h0,l0,h1,l1,h2,l2,h3,l3;
        bsplit(o.x,h0,l0); bsplit(o.y,h1,l1); bsplit(o.z,h2,l2); bsplit(o.w,h3,l3);
        __nv_bfloat162* hp = (__nv_bfloat162*)(ohi + (size_t)t * C);
        __nv_bfloat162* lp = (__nv_bfloat162*)(olo + (size_t)t * C);
        hp[threadIdx.x*2]   = __nv_bfloat162(h0, h1);
        hp[threadIdx.x*2+1] = __nv_bfloat162(h2, h3);
        lp[threadIdx.x*2]   = __nv_bfloat162(l0, l1);
        lp[threadIdx.x*2+1] = __nv_bfloat162(l2, l3);
    }
}

// per-head RMSNorm + RoPE for q and k (fp32 in/out)
__global__ void qk_rope_kernel(float* __restrict__ q, float* __restrict__ k) {
    int tok  = blockIdx.x;
    int head = threadIdx.x >> 5;
    int lane = threadIdx.x & 31;
    int tpos = tok % T;
    float ex  = (float)(2 * lane) / 64.0f;
    float inv = 1.0f / powf(10000.0f, ex);
    float ang = (float)tpos * inv;
    float c = cosf(ang), s = sinf(ang);
    float* ptrs[2] = { q, k };
    #pragma unroll
    for (int m = 0; m < 2; m++) {
        float* base = ptrs[m] + (size_t)tok * C + head * D;
        float x1 = base[lane], x2 = base[lane + 32];
        float ss = x1*x1 + x2*x2;
        #pragma unroll
        for (int o = 16; o; o >>= 1) ss += __shfl_xor_sync(0xffffffffu, ss, o);
        float r = rsqrtf(ss / (float)D + EPS_RMS);
        x1 *= r; x2 *= r;
        base[lane]      =  x1 * c + x2 * s;
        base[lane + 32] = -x1 * s + x2 * c;
    }
}

// ======================= flash attention (fp32) -> y bf16 pair =======================
#define QT 128
#define KT 32
__global__ void __launch_bounds__(128) attn_kernel(
    const float* __restrict__ q, const float* __restrict__ k,
    const float* __restrict__ v,
    __nv_bfloat16* __restrict__ yhi, __nv_bfloat16* __restrict__ ylo)
{
    __shared__ __align__(16) float Ks[KT][D];
    __shared__ __align__(16) float Vs[KT][D];
    int bh = blockIdx.y;
    int b = bh / H, h = bh % H;
    int q0 = blockIdx.x * QT;
    int row = q0 + threadIdx.x;
    const float4* qp = (const float4*)(q + ((size_t)(b*T + row) * C + h * D));
    float qr[D];
    #pragma unroll
    for (int i = 0; i < D/4; i++) {
        float4 t4 = qp[i];
        qr[4*i] = t4.x; qr[4*i+1] = t4.y; qr[4*i+2] = t4.z; qr[4*i+3] = t4.w;
    }
    float acc[D];
    #pragma unroll
    for (int d = 0; d < D; d++) acc[d] = 0.f;
    float mrun = -INFINITY, lrun = 0.f;

    int kend = q0 + QT;
    for (int k0 = 0; k0 < kend; k0 += KT) {
        __syncthreads();
        #pragma unroll
        for (int i = 0; i < 4; i++) {
            int lin = threadIdx.x + i * 128;
            int r = lin >> 4, c4 = lin & 15;
            const float4* kp = (const float4*)(k + ((size_t)(b*T + k0 + r) * C + h * D));
            const float4* vp = (const float4*)(v + ((size_t)(b*T + k0 + r) * C + h * D));
            ((float4*)&Ks[r][0])[c4] = kp[c4];
            ((float4*)&Vs[r][0])[c4] = vp[c4];
        }
        __syncthreads();

        float s[KT];
        #pragma unroll
        for (int kk = 0; kk < KT; kk++) {
            const float4* kr = (const float4*)&Ks[kk][0];
            float d0 = 0.f, d1 = 0.f, d2 = 0.f, d3 = 0.f;
            #pragma unroll
            for (int i = 0; i < 16; i += 4) {
                float4 a = kr[i], bb = kr[i+1], cc = kr[i+2], dd = kr[i+3];
                d0 += qr[4*i+0]*a.x + qr[4*i+1]*a.y + qr[4*i+2]*a.z + qr[4*i+3]*a.w;
                d1 += qr[4*i+4]*bb.x + qr[4*i+5]*bb.y + qr[4*i+6]*bb.z + qr[4*i+7]*bb.w;
                d2 += qr[4*i+8]*cc.x + qr[4*i+9]*cc.y + qr[4*i+10]*cc.z + qr[4*i+11]*cc.w;
                d3 += qr[4*i+12]*dd.x + qr[4*i+13]*dd.y + qr[4*i+14]*dd.z + qr[4*i+15]*dd.w;
            }
            float dot = (d0 + d1) + (d2 + d3);
            s[kk] = (k0 + kk <= row) ? dot * 0.125f : -INFINITY;
        }
        float tm = -INFINITY;
        #pragma unroll
        for (int kk = 0; kk < KT; kk++) tm = fmaxf(tm, s[kk]);
        float nm = fmaxf(mrun, tm);
        float scale = expf(mrun - nm);
        float psum = 0.f;
        #pragma unroll
        for (int kk = 0; kk < KT; kk++) { s[kk] = expf(s[kk] - nm); psum += s[kk]; }
        #pragma unroll
        for (int d = 0; d < D; d++) acc[d] *= scale;
        #pragma unroll
        for (int kk = 0; kk < KT; kk++) {
            float pk = s[kk];
            const float4* vr = (const float4*)&Vs[kk][0];
            #pragma unroll
            for (int i = 0; i < 16; i++) {
                float4 vv = vr[i];
                acc[4*i+0] += pk * vv.x; acc[4*i+1] += pk * vv.y;
                acc[4*i+2] += pk * vv.z; acc[4*i+3] += pk * vv.w;
            }
        }
        lrun = lrun * scale + psum;
        mrun = nm;
    }
    float inv_l = 1.0f / lrun;
    size_t base = (size_t)(b*T + row) * C + h * D;
    __nv_bfloat162* hp = (__nv_bfloat162*)(yhi + base);
    __nv_bfloat162* lp = (__nv_bfloat162*)(ylo + base);
    #pragma unroll
    for (int i = 0; i < 32; i++) {
        float v0 = acc[2*i] * inv_l, v1 = acc[2*i+1] * inv_l;
        __nv_bfloat16 h0,l0,h1,l1;
        bsplit(v0,h0,l0); bsplit(v1,h1,l1);
        hp[i] = __nv_bfloat162(h0, h1);
        lp[i] = __nv_bfloat162(l0, l1);
    }
}

// ======================= HMMA bf16x3 GEMM =======================
// D[128 tile, 128 tile] = A (rows [M,K], K-major) x B^T (rows [N,K], K-major)
// 3-term bf16 emulation of fp32: hi*hi + hi*lo + lo*hi, fp32 accumulate.
// epi: 0 -> Cout fp32; 1 -> Cout = acc + resid; 2 -> relu(acc)^2 as bf16 hi/lo pair
#define KTILE 64
#define OFF_AH 0
#define OFF_AL 16384
#define OFF_BH 32768
#define OFF_BL 49152
#define STAGE_BYTES 65536
#define SMEM_GEMM_BYTES (2*STAGE_BYTES)

__global__ void __launch_bounds__(256) gemm_bf16x3(
    const __nv_bfloat16* __restrict__ Ahi, const __nv_bfloat16* __restrict__ Alo,
    const __nv_bfloat16* __restrict__ Bhi, const __nv_bfloat16* __restrict__ Blo,
    size_t bstride,
    float* __restrict__ Cout,
    __nv_bfloat16* __restrict__ Ohi, __nv_bfloat16* __restrict__ Olo,
    const float* __restrict__ resid,
    const int* __restrict__ tileExpert,
    int N, int K, int epi)
{
    extern __shared__ __align__(1024) char smem[];
    int by = blockIdx.y, bx = blockIdx.x;
    int e = 0;
    if (tileExpert) { e = tileExpert[by]; if (e < 0) return; }
    const __nv_bfloat16* Bh = Bhi + (size_t)e * bstride;
    const __nv_bfloat16* Bl = Blo + (size_t)e * bstride;

    uint32_t sb = smem_to_u32(smem);
    int tid = threadIdx.x, wid = tid >> 5, lid = tid & 31;
    int wm = wid & 1, wn = wid >> 1;
    int row0 = by * 128, col0 = bx * 128;
    int nkt = K / KTILE;

    float acc[4][4][4];
    #pragma unroll
    for (int i = 0; i < 4; i++)
        #pragma unroll
        for (int j = 0; j < 4; j++)
            #pragma unroll
            for (int r = 0; r < 4; r++) acc[i][j][r] = 0.f;

    int lr = tid >> 3, lc = tid & 7;     // loader: row-lane, 16B-chunk lane
    uint32_t lso = SMEM_SWIZZLE_128B((uint32_t)(lr * 128 + lc * 16));

    // ---- preload stage 0 ----
    {
        int k0 = 0;
        #pragma unroll
        for (int i = 0; i < 4; i++) {
            int r = lr + i * 32;
            uint32_t so = SMEM_SWIZZLE_128B((uint32_t)(r * 128 + lc * 16));
            size_t ga = (size_t)(row0 + r) * K + k0 + lc * 8;
            size_t gb = (size_t)(col0 + r) * K + k0 + lc * 8;
            CP16(sb + OFF_AH + so, Ahi + ga);
            CP16(sb + OFF_AL + so, Alo + ga);
            CP16(sb + OFF_BH + so, Bh + gb);
            CP16(sb + OFF_BL + so, Bl + gb);
        }
        asm volatile("cp.async.commit_group;" ::: "memory");
    }

    for (int kt = 0; kt < nkt; kt++) {
        uint32_t cur = (uint32_t)(kt & 1) * STAGE_BYTES;
        if (kt + 1 < nkt) {
            uint32_t nxt = (uint32_t)((kt + 1) & 1) * STAGE_BYTES;
            int k0 = (kt + 1) * KTILE;
            #pragma unroll
            for (int i = 0; i < 4; i++) {
                int r = lr + i * 32;
                uint32_t so = SMEM_SWIZZLE_128B((uint32_t)(r * 128 + lc * 16));
                size_t ga = (size_t)(row0 + r) * K + k0 + lc * 8;
                size_t gb = (size_t)(col0 + r) * K + k0 + lc * 8;
                CP16(sb + nxt + OFF_AH + so, Ahi + ga);
                CP16(sb + nxt + OFF_AL + so, Alo + ga);
                CP16(sb + nxt + OFF_BH + so, Bh + gb);
                CP16(sb + nxt + OFF_BL + so, Bl + gb);
            }
            asm volatile("cp.async.commit_group;" ::: "memory");
            asm volatile("cp.async.wait_group 1;" ::: "memory");
        } else {
            asm volatile("cp.async.wait_group 0;" ::: "memory");
        }
        __syncthreads();

        uint32_t sAH = sb + cur + OFF_AH, sAL = sb + cur + OFF_AL;
        uint32_t sBH = sb + cur + OFF_BH, sBL = sb + cur + OFF_BL;
        #pragma unroll
        for (int kk = 0; kk < 4; kk++) {
            int colb = (kk * 16 + (lid >> 4) * 8) * 2;
            uint32_t a_hi[4][4], a_lo[4][4];
            #pragma unroll
            for (int mf = 0; mf < 4; mf++) {
                int rowm = wm * 64 + mf * 16 + (lid & 15);
                uint32_t so = SMEM_SWIZZLE_128B((uint32_t)(rowm * 128 + colb));
                ldsm4(a_hi[mf], sAH + so);
                ldsm4(a_lo[mf], sAL + so);
            }
            uint32_t b_hi[4][2], b_lo[4][2];
            #pragma unroll
            for (int g = 0; g < 2; g++) {
                int rown = wn * 32 + g * 16 + (lid & 15);
                uint32_t so = SMEM_SWIZZLE_128B((uint32_t)(rown * 128 + colb));
                uint32_t r4[4];
                ldsm4(r4, sBH + so);
                b_hi[2*g][0] = r4[0]; b_hi[2*g+1][0] = r4[1];
                b_hi[2*g][1] = r4[2]; b_hi[2*g+1][1] = r4[3];
                ldsm4(r4, sBL + so);
                b_lo[2*g][0] = r4[0]; b_lo[2*g+1][0] = r4[1];
                b_lo[2*g][1] = r4[2]; b_lo[2*g+1][1] = r4[3];
            }
            #pragma unroll
            for (int mf = 0; mf < 4; mf++)
                #pragma unroll
                for (int nf = 0; nf < 4; nf++) {
                    mma_bf16(acc[mf][nf], a_hi[mf], b_hi[nf]);
                    mma_bf16(acc[mf][nf], a_hi[mf], b_lo[nf]);
                    mma_bf16(acc[mf][nf], a_lo[mf], b_hi[nf]);
                }
        }
        __syncthreads();
    }

    // ---- epilogue: direct fragment stores ----
    int qr = lid >> 2, qc = (lid & 3) * 2;
    #pragma unroll
    for (int mf = 0; mf < 4; mf++) {
        #pragma unroll
        for (int nf = 0; nf < 4; nf++) {
            float* cc = acc[mf][nf];
            int col = col0 + wn * 32 + nf * 8 + qc;
            #pragma unroll
            for (int half = 0; half < 2; half++) {
                int row = row0 + wm * 64 + mf * 16 + qr + half * 8;
                size_t idx = (size_t)row * N + col;
                float v0 = cc[2*half], v1 = cc[2*half + 1];
                if (epi == 0) {
                    *(float2*)(Cout + idx) = make_float2(v0, v1);
                } else if (epi == 1) {
                    float2 rr = *(const float2*)(resid + idx);
                    *(float2*)(Cout + idx) = make_float2(v0 + rr.x, v1 + rr.y);
                } else {
                    float r0 = fmaxf(v0, 0.f); r0 *= r0;
                    float r1 = fmaxf(v1, 0.f); r1 *= r1;
                    __nv_bfloat16 h0, l0, h1, l1;
                    bsplit(r0, h0, l0); bsplit(r1, h1, l1);
                    *(__nv_bfloat162*)(Ohi + idx) = __nv_bfloat162(h0, h1);
                    *(__nv_bfloat162*)(Olo + idx) = __nv_bfloat162(l0, l1);
                }
            }
        }
    }
}

// ======================= router / grouping / scatter / scalars =======================
__global__ void router_kernel(const float* __restrict__ h2, const float* __restrict__ Wr) {
    int t = blockIdx.x;
    __shared__ float red[16];
    float a0 = 0.f, a1 = 0.f, a2 = 0.f, a3 = 0.f;
    const float* hp = h2 + (size_t)t * C;
    for (int c = threadIdx.x; c < C; c += 128) {
        float hv = hp[c];
        const float4 w = *(const float4*)(Wr + (size_t)c * E);
        a0 += hv * w.x; a1 += hv * w.y; a2 += hv * w.z; a3 += hv * w.w;
    }
    #pragma unroll
    for (int o = 16; o; o >>= 1) {
        a0 += __shfl_xor_sync(0xffffffffu, a0, o);
        a1 += __shfl_xor_sync(0xffffffffu, a1, o);
        a2 += __shfl_xor_sync(0xffffffffu, a2, o);
        a3 += __shfl_xor_sync(0xffffffffu, a3, o);
    }
    if ((threadIdx.x & 31) == 0) {
        int w = threadIdx.x >> 5;
        red[w*4+0] = a0; red[w*4+1] = a1; red[w*4+2] = a2; red[w*4+3] = a3;
    }
    __syncthreads();
    if (threadIdx.x == 0) {
        float lg[4];
        #pragma unroll
        for (int e = 0; e < 4; e++)
            lg[e] = red[e] + red[4+e] + red[8+e] + red[12+e];
        int arg = 0;
        #pragma unroll
        for (int e = 1; e < 4; e++) if (lg[e] > lg[arg]) arg = e;
        float m = fmaxf(fmaxf(lg[0], lg[1]), fmaxf(lg[2], lg[3]));
        float ez[4]; float sum = 0.f;
        #pragma unroll
        for (int e = 0; e < 4; e++) { ez[e] = expf(lg[e] - m); sum += ez[e]; }
        float p[4];
        #pragma unroll
        for (int e = 0; e < 4; e++) p[e] = ez[e] / sum;
        g_expert[t] = arg;
        atomicAdd(&g_counts[arg], 1);
        #pragma unroll
        for (int e = 0; e < 4; e++) atomicAdd(&g_expsum[e], (double)p[e]);
        float lse = m + logf(sum);
        atomicAdd(&g_zsum, (double)lse * (double)lse);
        float ent = 0.f;
        #pragma unroll
        for (int e = 0; e < 4; e++) ent -= p[e] * logf(p[e] + 1e-9f);
        atomicAdd(&g_entsum, (double)ent);
    }
}

__global__ void offsets_kernel() {
    if (threadIdx.x == 0 && blockIdx.x == 0) {
        int off = 0;
        for (int e = 0; e < E; e++) {
            g_segstart[e] = off;
            int padded = (g_counts[e] + 127) & ~127;
            for (int i = 0; i < padded / 128; i++)
                g_tileExpert[off / 128 + i] = e;
            off += padded;
        }
    }
}

__global__ void assign_kernel(const float* __restrict__ h2) {
    int t = blockIdx.x;
    __shared__ int slot_s;
    if (threadIdx.x == 0) {
        int e = g_expert[t];
        int slot = g_segstart[e] + atomicAdd(&g_cursor[e], 1);
        g_tokenOfRow[slot] = t;
        slot_s = slot;
    }
    __syncthreads();
    int s = slot_s;
    float4 v = ((const float4*)(h2 + (size_t)t * C))[threadIdx.x];
    __nv_bfloat16 h0,l0,h1,l1,h2b,l2,h3,l3;
    bsplit(v.x,h0,l0); bsplit(v.y,h1,l1); bsplit(v.z,h2b,l2); bsplit(v.w,h3,l3);
    __nv_bfloat162* hp = (__nv_bfloat162*)(g_h2g_hi + (size_t)s * C);
    __nv_bfloat162* lp = (__nv_bfloat162*)(g_h2g_lo + (size_t)s * C);
    hp[threadIdx.x*2]   = __nv_bfloat162(h0, h1);
    hp[threadIdx.x*2+1] = __nv_bfloat162(h2b, h3);
    lp[threadIdx.x*2]   = __nv_bfloat162(l0, l1);
    lp[threadIdx.x*2+1] = __nv_bfloat162(l2, l3);
}

__global__ void scatter_kernel(const float* __restrict__ x2, float* __restrict__ out) {
    int r = blockIdx.x;
    int t = g_tokenOfRow[r];
    if (t < 0) return;
    float4 a = ((const float4*)(x2 + (size_t)t * C))[threadIdx.x];
    float4 b = ((const float4*)(g_outg + (size_t)r * C))[threadIdx.x];
    ((float4*)(out + (size_t)t * C))[threadIdx.x] =
        make_float4(a.x + b.x, a.y + b.y, a.z + b.z, a.w + b.w);
}

__global__ void scalars_kernel(float* __restrict__ out) {
    if (threadIdx.x == 0 && blockIdx.x == 0) {
        const double NTOK = (double)BT;
        double aux = 0.0;
        for (int e = 0; e < E; e++) {
            double actual = (double)g_counts[e] / NTOK;
            double expd   = g_expsum[e] / NTOK;
            aux += actual * expd;
        }
        size_t base = (size_t)BT * C;
        out[base + 0] = (float)((double)E * aux);
        out[base + 1] = (float)(g_zsum / NTOK);
        out[base + 2] = (float)((g_entsum / NTOK) / log((double)E));
        for (int e = 0; e < E; e++)
            out[base + 3 + e] = (float)((double)g_counts[e] / NTOK);
    }
}

// ======================= launch =======================
static void* sym(const void* s) { void* p = nullptr; cudaGetSymbolAddress(&p, s); return p; }

extern "C" void kernel_launch(void* const* d_in, const int* in_sizes, int n_in,
                              void* d_out, int out_size)
{
    const float* x     = (const float*)d_in[0];
    const float* Wq    = (const float*)d_in[1];
    const float* Wk    = (const float*)d_in[2];
    const float* Wv    = (const float*)d_in[3];
    const float* Wo    = (const float*)d_in[4];
    const float* Wr    = (const float*)d_in[5];
    const float* Wfc   = (const float*)d_in[6];
    const float* Wproj = (const float*)d_in[7];
    float* out = (float*)d_out;

    static bool attr_set = false;
    if (!attr_set) {
        cudaFuncSetAttribute(gemm_bf16x3, cudaFuncAttributeMaxDynamicSharedMemorySize, SMEM_GEMM_BYTES);
        attr_set = true;
    }

    __nv_bfloat16* h1h = (__nv_bfloat16*)sym(g_h1_hi);
    __nv_bfloat16* h1l = (__nv_bfloat16*)sym(g_h1_lo);
    float* qb = (float*)sym(g_q);
    float* kb = (float*)sym(g_k);
    float* vb = (float*)sym(g_v);
    __nv_bfloat16* yh = (__nv_bfloat16*)sym(g_y_hi);
    __nv_bfloat16* yl = (__nv_bfloat16*)sym(g_y_lo);
    float* x2 = (float*)sym(g_x2);
    float* h2 = (float*)sym(g_h2);
    __nv_bfloat16* h2gh = (__nv_bfloat16*)sym(g_h2g_hi);
    __nv_bfloat16* h2gl = (__nv_bfloat16*)sym(g_h2g_lo);
    __nv_bfloat16* hidh = (__nv_bfloat16*)sym(g_hid_hi);
    __nv_bfloat16* hidl = (__nv_bfloat16*)sym(g_hid_lo);
    float* outg = (float*)sym(g_outg);
    __nv_bfloat16* wqh = (__nv_bfloat16*)sym(g_wq_hi); __nv_bfloat16* wql = (__nv_bfloat16*)sym(g_wq_lo);
    __nv_bfloat16* wkh = (__nv_bfloat16*)sym(g_wk_hi); __nv_bfloat16* wkl = (__nv_bfloat16*)sym(g_wk_lo);
    __nv_bfloat16* wvh = (__nv_bfloat16*)sym(g_wv_hi); __nv_bfloat16* wvl = (__nv_bfloat16*)sym(g_wv_lo);
    __nv_bfloat16* woh = (__nv_bfloat16*)sym(g_wo_hi); __nv_bfloat16* wol = (__nv_bfloat16*)sym(g_wo_lo);
    __nv_bfloat16* wfh = (__nv_bfloat16*)sym(g_wfc_hi); __nv_bfloat16* wfl = (__nv_bfloat16*)sym(g_wfc_lo);
    __nv_bfloat16* wph = (__nv_bfloat16*)sym(g_wpj_hi); __nv_bfloat16* wpl = (__nv_bfloat16*)sym(g_wpj_lo);
    int* tileE = (int*)sym(g_tileExpert);

    reset_kernel<<<(GROUP_CAP + 255) / 256, 256>>>();

    // weight transpose + bf16 split
    dim3 wb(32, 8);
    wconv_kernel<<<dim3(C/32,  C/32,  1), wb>>>(Wq,    wqh, wql, C,  C);
    wconv_kernel<<<dim3(C/32,  C/32,  1), wb>>>(Wk,    wkh, wkl, C,  C);
    wconv_kernel<<<dim3(C/32,  C/32,  1), wb>>>(Wv,    wvh, wvl, C,  C);
    wconv_kernel<<<dim3(C/32,  C/32,  1), wb>>>(Wo,    woh, wol, C,  C);
    wconv_kernel<<<dim3(FF/32, C/32,  E), wb>>>(Wfc,   wfh, wfl, C,  FF);
    wconv_kernel<<<dim3(C/32,  FF/32, E), wb>>>(Wproj, wph, wpl, FF, C);

    // h1 = rmsnorm(x) -> bf16 pair only
    rmsnorm_kernel<<<BT, 256>>>(x, nullptr, h1h, h1l);

    // q/k/v projections (fp32 out)
    dim3 gq(C / 128, BT / 128);
    gemm_bf16x3<<<gq, 256, SMEM_GEMM_BYTES>>>(h1h, h1l, wqh, wql, 0, qb, nullptr, nullptr, nullptr, nullptr, C, C, 0);
    gemm_bf16x3<<<gq, 256, SMEM_GEMM_BYTES>>>(h1h, h1l, wkh, wkl, 0, kb, nullptr, nullptr, nullptr, nullptr, C, C, 0);
    gemm_bf16x3<<<gq, 256, SMEM_GEMM_BYTES>>>(h1h, h1l, wvh, wvl, 0, vb, nullptr, nullptr, nullptr, nullptr, C, C, 0);

    qk_rope_kernel<<<BT, 512>>>(qb, kb);
    attn_kernel<<<dim3(T / QT, Bq * H), 128>>>(qb, kb, vb, yh, yl);

    // x2 = x + y @ Wo
    gemm_bf16x3<<<gq, 256, SMEM_GEMM_BYTES>>>(yh, yl, woh, wol, 0, x2, nullptr, nullptr, x, nullptr, C, C, 1);

    // h2 = rmsnorm(x2) (fp32)
    rmsnorm_kernel<<<BT, 256>>>(x2, h2, nullptr, nullptr);

    // router + grouping
    router_kernel<<<BT, 128>>>(h2, Wr);
    offsets_kernel<<<1, 32>>>();
    zero_h2g_pair_kernel<<<GROUP_CAP, 256>>>();
    assign_kernel<<<BT, 256>>>(h2);

    // MoE: hid = relu(h2g @ Wfc[e])^2 (bf16 pair out) ; outg = hid @ Wproj[e]
    gemm_bf16x3<<<dim3(FF / 128, NTILES), 256, SMEM_GEMM_BYTES>>>(
        h2gh, h2gl, wfh, wfl, (size_t)FF * C, nullptr, hidh, hidl, nullptr, tileE, FF, C, 2);
    gemm_bf16x3<<<dim3(C / 128, NTILES), 256, SMEM_GEMM_BYTES>>>(
        hidh, hidl, wph, wpl, (size_t)C * FF, outg, nullptr, nullptr, nullptr, tileE, C, FF, 0);

    scatter_kernel<<<GROUP_CAP, 256>>>(x2, out);
    scalars_kernel<<<1, 32>>>(out);
}

// round 5
// speedup vs baseline: 2.9613x; 1.8005x over previous
#include <cuda_runtime.h>
#include <cuda_bf16.h>
#include <cstdint>
#include <math.h>

#define Bq 2
#define T 2048
#define C 1024
#define H 16
#define D 64
#define E 4
#define BT (Bq*T)
#define FF (4*C)
#define GROUP_CAP (BT + E*128)
#define NTILES (GROUP_CAP/128)
#define EPS_RMS 1.1920929e-07f

#define SMEM_SWIZZLE_128B(b) ((b) ^ (((b) >> 3) & 0x70))

__device__ __forceinline__ uint32_t smem_to_u32(const void* p) {
    uint32_t a;
    asm("{ .reg .u64 t; cvta.to.shared.u64 t, %1; cvt.u32.u64 %0, t; }" : "=r"(a) : "l"(p));
    return a;
}
__device__ __forceinline__ void ldsm4(uint32_t* r, uint32_t addr) {
    asm volatile("ldmatrix.sync.aligned.m8n8.x4.shared.b16 {%0,%1,%2,%3}, [%4];"
                 : "=r"(r[0]), "=r"(r[1]), "=r"(r[2]), "=r"(r[3]) : "r"(addr));
}
__device__ __forceinline__ void ldsm4t(uint32_t* r, uint32_t addr) {
    asm volatile("ldmatrix.sync.aligned.m8n8.x4.trans.shared.b16 {%0,%1,%2,%3}, [%4];"
                 : "=r"(r[0]), "=r"(r[1]), "=r"(r[2]), "=r"(r[3]) : "r"(addr));
}
__device__ __forceinline__ void mma_bf16(float* c, const uint32_t* a, const uint32_t* b) {
    asm volatile("mma.sync.aligned.m16n8k16.row.col.f32.bf16.bf16.f32 "
        "{%0,%1,%2,%3}, {%4,%5,%6,%7}, {%8,%9}, {%0,%1,%2,%3};"
        : "+f"(c[0]), "+f"(c[1]), "+f"(c[2]), "+f"(c[3])
        : "r"(a[0]), "r"(a[1]), "r"(a[2]), "r"(a[3]), "r"(b[0]), "r"(b[1]));
}
__device__ __forceinline__ float ex2f(float x) {
    float y; asm("ex2.approx.ftz.f32 %0, %1;" : "=f"(y) : "f"(x)); return y;
}
#define CP16(s, g) asm volatile("cp.async.cg.shared.global [%0], [%1], 16;" \
                                :: "r"(s), "l"(g) : "memory")

// ======================= scratch (static device globals) =======================
__device__ __nv_bfloat16 g_h1_hi[BT*C], g_h1_lo[BT*C];
__device__ float g_q[BT*C], g_k[BT*C];
__device__ __nv_bfloat16 g_qhi[BT*C], g_qlo[BT*C];
__device__ __nv_bfloat16 g_khi[BT*C], g_klo[BT*C];
__device__ __nv_bfloat16 g_vhi[BT*C], g_vlo[BT*C];
__device__ __nv_bfloat16 g_y_hi[BT*C], g_y_lo[BT*C];
__device__ float g_x2[BT*C], g_h2[BT*C];
__device__ __nv_bfloat16 g_h2g_hi[GROUP_CAP*C], g_h2g_lo[GROUP_CAP*C];
__device__ __nv_bfloat16 g_hid_hi[(size_t)GROUP_CAP*FF], g_hid_lo[(size_t)GROUP_CAP*FF];
__device__ float g_outg[GROUP_CAP*C];
__device__ __nv_bfloat16 g_wq_hi[C*C], g_wq_lo[C*C];
__device__ __nv_bfloat16 g_wk_hi[C*C], g_wk_lo[C*C];
__device__ __nv_bfloat16 g_wv_hi[C*C], g_wv_lo[C*C];
__device__ __nv_bfloat16 g_wo_hi[C*C], g_wo_lo[C*C];
__device__ __nv_bfloat16 g_wfc_hi[(size_t)E*C*FF], g_wfc_lo[(size_t)E*C*FF];   // [E][FF,C]
__device__ __nv_bfloat16 g_wpj_hi[(size_t)E*FF*C], g_wpj_lo[(size_t)E*FF*C];   // [E][C,FF]
__device__ int   g_expert[BT];
__device__ int   g_counts[E];
__device__ int   g_cursor[E];
__device__ int   g_segstart[E];
__device__ int   g_tileExpert[NTILES];
__device__ int   g_tokenOfRow[GROUP_CAP];
__device__ double g_expsum[E];
__device__ double g_zsum;
__device__ double g_entsum;

__device__ __forceinline__ void bsplit(float v, __nv_bfloat16& h, __nv_bfloat16& l) {
    h = __float2bfloat16(v);
    l = __float2bfloat16(v - __bfloat162float(h));
}
__device__ __forceinline__ void packsplit(float v0, float v1, uint32_t& hi, uint32_t& lo) {
    __nv_bfloat16 h0, l0, h1, l1;
    bsplit(v0, h0, l0); bsplit(v1, h1, l1);
    __nv_bfloat162 hh(h0, h1), ll(l0, l1);
    hi = *reinterpret_cast<uint32_t*>(&hh);
    lo = *reinterpret_cast<uint32_t*>(&ll);
}

// ======================= small kernels =======================
__global__ void reset_kernel() {
    int i = blockIdx.x * blockDim.x + threadIdx.x;
    if (i < E) { g_counts[i] = 0; g_cursor[i] = 0; g_expsum[i] = 0.0; }
    if (i == 0) { g_zsum = 0.0; g_entsum = 0.0; }
    if (i < NTILES) g_tileExpert[i] = -1;
    if (i < GROUP_CAP) g_tokenOfRow[i] = -1;
}

__global__ void zero_h2g_pair_kernel() {
    int r = blockIdx.x;
    uint2 z = make_uint2(0u, 0u);
    ((uint2*)(g_h2g_hi + (size_t)r * C))[threadIdx.x] = z;
    ((uint2*)(g_h2g_lo + (size_t)r * C))[threadIdx.x] = z;
}

// transpose + bf16-split weights: W [Kd, Nd] fp32 -> T [Nd, Kd] bf16 hi/lo
__global__ void wconv_kernel(const float* __restrict__ W,
                             __nv_bfloat16* __restrict__ Thi, __nv_bfloat16* __restrict__ Tlo,
                             int Kd, int Nd) {
    __shared__ float tile[32][33];
    int b = blockIdx.z;
    const float* Wb = W + (size_t)b * Kd * Nd;
    __nv_bfloat16* Th = Thi + (size_t)b * Kd * Nd;
    __nv_bfloat16* Tl = Tlo + (size_t)b * Kd * Nd;
    int n0 = blockIdx.x * 32, k0 = blockIdx.y * 32;
    int tx = threadIdx.x, ty = threadIdx.y;
    #pragma unroll
    for (int i = 0; i < 4; i++)
        tile[ty + 8*i][tx] = Wb[(size_t)(k0 + ty + 8*i) * Nd + n0 + tx];
    __syncthreads();
    #pragma unroll
    for (int i = 0; i < 4; i++) {
        int n = n0 + ty + 8*i, k = k0 + tx;
        float v = tile[tx][ty + 8*i];
        __nv_bfloat16 h, l; bsplit(v, h, l);
        Th[(size_t)n * Kd + k] = h;
        Tl[(size_t)n * Kd + k] = l;
    }
}

// RMSNorm over C; optional fp32 out, optional bf16 hi/lo pair out
__global__ void rmsnorm_kernel(const float* __restrict__ in, float* __restrict__ outf,
                               __nv_bfloat16* __restrict__ ohi, __nv_bfloat16* __restrict__ olo) {
    int t = blockIdx.x;
    const float4* ip = (const float4*)(in + (size_t)t * C);
    __shared__ float red[8];
    float4 v = ip[threadIdx.x];
    float ss = v.x*v.x + v.y*v.y + v.z*v.z + v.w*v.w;
    #pragma unroll
    for (int o = 16; o; o >>= 1) ss += __shfl_xor_sync(0xffffffffu, ss, o);
    if ((threadIdx.x & 31) == 0) red[threadIdx.x >> 5] = ss;
    __syncthreads();
    if (threadIdx.x == 0) {
        float s = 0.f;
        #pragma unroll
        for (int w = 0; w < 8; w++) s += red[w];
        red[0] = s;
    }
    __syncthreads();
    float r = rsqrtf(red[0] / (float)C + EPS_RMS);
    float4 o = make_float4(v.x*r, v.y*r, v.z*r, v.w*r);
    if (outf) ((float4*)(outf + (size_t)t * C))[threadIdx.x] = o;
    if (ohi) {
        __nv_bfloat16 h0,l0,h1,l1,h2,l2,h3,l3;
        bsplit(o.x,h0,l0); bsplit(o.y,h1,l1); bsplit(o.z,h2,l2); bsplit(o.w,h3,l3);
        __nv_bfloat162* hp = (__nv_bfloat162*)(ohi + (size_t)t * C);
        __nv_bfloat162* lp = (__nv_bfloat162*)(olo + (size_t)t * C);
        hp[threadIdx.x*2]   = __nv_bfloat162(h0, h1);
        hp[threadIdx.x*2+1] = __nv_bfloat162(h2, h3);
        lp[threadIdx.x*2]   = __nv_bfloat162(l0, l1);
        lp[threadIdx.x*2+1] = __nv_bfloat162(l2, l3);
    }
}

// per-head RMSNorm + RoPE for q and k; fp32 in -> bf16 hi/lo out
__global__ void qk_rope_kernel(const float* __restrict__ q, const float* __restrict__ k,
                               __nv_bfloat16* __restrict__ qhi, __nv_bfloat16* __restrict__ qlo,
                               __nv_bfloat16* __restrict__ khi, __nv_bfloat16* __restrict__ klo) {
    int tok  = blockIdx.x;
    int head = threadIdx.x >> 5;
    int lane = threadIdx.x & 31;
    int tpos = tok % T;
    float ex  = (float)(2 * lane) / 64.0f;
    float inv = 1.0f / powf(10000.0f, ex);
    float ang = (float)tpos * inv;
    float c = cosf(ang), s = sinf(ang);
    size_t base = (size_t)tok * C + head * D;
    #pragma unroll
    for (int m = 0; m < 2; m++) {
        const float* src = (m == 0 ? q : k) + base;
        __nv_bfloat16* dh = (m == 0 ? qhi : khi) + base;
        __nv_bfloat16* dl = (m == 0 ? qlo : klo) + base;
        float x1 = src[lane], x2 = src[lane + 32];
        float ss = x1*x1 + x2*x2;
        #pragma unroll
        for (int o = 16; o; o >>= 1) ss += __shfl_xor_sync(0xffffffffu, ss, o);
        float r = rsqrtf(ss / (float)D + EPS_RMS);
        x1 *= r; x2 *= r;
        float o1 =  x1 * c + x2 * s;
        float o2 = -x1 * s + x2 * c;
        __nv_bfloat16 h, l;
        bsplit(o1, h, l); dh[lane] = h;      dl[lane] = l;
        bsplit(o2, h, l); dh[lane + 32] = h; dl[lane + 32] = l;
    }
}

// ======================= HMMA flash attention (bf16x3) =======================
// CTA: 128 q rows x one (b,h); 8 warps, each 16 q rows. Key tiles of 64.
#define AT_QHI 0
#define AT_QLO 16384
#define AT_STG 32768
#define AT_STGSZ 32768
#define AT_KHI 0
#define AT_KLO 8192
#define AT_VHI 16384
#define AT_VLO 24576
#define ATT_SMEM (32768 + 2*32768)

__global__ void __launch_bounds__(256) attn_mma_kernel(
    const __nv_bfloat16* __restrict__ qhi, const __nv_bfloat16* __restrict__ qlo,
    const __nv_bfloat16* __restrict__ khi, const __nv_bfloat16* __restrict__ klo,
    const __nv_bfloat16* __restrict__ vhi, const __nv_bfloat16* __restrict__ vlo,
    __nv_bfloat16* __restrict__ yhi, __nv_bfloat16* __restrict__ ylo)
{
    extern __shared__ __align__(1024) char smem[];
    uint32_t sb = smem_to_u32(smem);
    int bh = blockIdx.y;
    int b = bh / H, hh = bh % H;
    int qb = blockIdx.x;
    int q0 = qb * 128;
    int tid = threadIdx.x, wid = tid >> 5, lid = tid & 31;
    int nkt = 2 * qb + 2;

    // --- cp.async Q tile (128 rows x 128B, hi+lo) : group 0 ---
    #pragma unroll
    for (int i = 0; i < 4; i++) {
        int lin = tid + i * 256;             // 0..1023 chunks of 16B
        int r = lin >> 3, ch = lin & 7;
        uint32_t so = SMEM_SWIZZLE_128B((uint32_t)(r * 128 + ch * 16));
        size_t g = (size_t)(b*T + q0 + r) * C + hh * D + ch * 8;
        CP16(sb + AT_QHI + so, qhi + g);
        CP16(sb + AT_QLO + so, qlo + g);
    }
    asm volatile("cp.async.commit_group;" ::: "memory");
    // --- cp.async K/V stage 0 (64 rows x 128B each of 4 operands) : group 1 ---
    #pragma unroll
    for (int i = 0; i < 2; i++) {
        int lin = tid + i * 256;             // 0..511 chunks
        int r = lin >> 3, ch = lin & 7;
        uint32_t so = SMEM_SWIZZLE_128B((uint32_t)(r * 128 + ch * 16));
        size_t g = (size_t)(b*T + r) * C + hh * D + ch * 8;
        uint32_t st = sb + AT_STG;
        CP16(st + AT_KHI + so, khi + g);
        CP16(st + AT_KLO + so, klo + g);
        CP16(st + AT_VHI + so, vhi + g);
        CP16(st + AT_VLO + so, vlo + g);
    }
    asm volatile("cp.async.commit_group;" ::: "memory");

    uint32_t qa_hi[4][4], qa_lo[4][4];
    float oac[8][4];
    #pragma unroll
    for (int j = 0; j < 8; j++)
        #pragma unroll
        for (int r = 0; r < 4; r++) oac[j][r] = 0.f;
    float m0 = -1e30f, m1 = -1e30f, l0 = 0.f, l1 = 0.f;

    int off = lid & 7, part = lid >> 3;
    int qr = lid >> 2, qc = (lid & 3) * 2;
    const float SC2 = 0.18033688011112042f;   // 0.125 * log2(e)

    for (int kt = 0; kt < nkt; kt++) {
        if (kt + 1 < nkt) {
            #pragma unroll
            for (int i = 0; i < 2; i++) {
                int lin = tid + i * 256;
                int r = lin >> 3, ch = lin & 7;
                uint32_t so = SMEM_SWIZZLE_128B((uint32_t)(r * 128 + ch * 16));
                size_t g = (size_t)(b*T + (kt + 1) * 64 + r) * C + hh * D + ch * 8;
                uint32_t st = sb + AT_STG + (uint32_t)((kt + 1) & 1) * AT_STGSZ;
                CP16(st + AT_KHI + so, khi + g);
                CP16(st + AT_KLO + so, klo + g);
                CP16(st + AT_VHI + so, vhi + g);
                CP16(st + AT_VLO + so, vlo + g);
            }
            asm volatile("cp.async.commit_group;" ::: "memory");
            asm volatile("cp.async.wait_group 1;" ::: "memory");
        } else {
            asm volatile("cp.async.wait_group 0;" ::: "memory");
        }
        __syncthreads();

        if (kt == 0) {
            #pragma unroll
            for (int kk = 0; kk < 4; kk++) {
                int row = wid * 16 + (part & 1) * 8 + off;
                int colb = kk * 32 + (part & 2) * 8;
                uint32_t so = SMEM_SWIZZLE_128B((uint32_t)(row * 128 + colb));
                ldsm4(qa_hi[kk], sb + AT_QHI + so);
                ldsm4(qa_lo[kk], sb + AT_QLO + so);
            }
        }

        uint32_t st = sb + AT_STG + (uint32_t)(kt & 1) * AT_STGSZ;

        // ---- S = Q K^T ----
        float s[8][4];
        #pragma unroll
        for (int j = 0; j < 8; j++)
            #pragma unroll
            for (int r = 0; r < 4; r++) s[j][r] = 0.f;
        #pragma unroll
        for (int kk = 0; kk < 4; kk++) {
            #pragma unroll
            for (int jj = 0; jj < 4; jj++) {
                int row = jj * 16 + (part & 2) * 4 + off;
                int colb = kk * 32 + (part & 1) * 16;
                uint32_t so = SMEM_SWIZZLE_128B((uint32_t)(row * 128 + colb));
                uint32_t kh[4], kl[4];
                ldsm4(kh, st + AT_KHI + so);
                ldsm4(kl, st + AT_KLO + so);
                mma_bf16(s[2*jj],     qa_hi[kk], kh);
                mma_bf16(s[2*jj],     qa_hi[kk], kl);
                mma_bf16(s[2*jj],     qa_lo[kk], kh);
                mma_bf16(s[2*jj+1],   qa_hi[kk], kh + 2);
                mma_bf16(s[2*jj+1],   qa_hi[kk], kl + 2);
                mma_bf16(s[2*jj+1],   qa_lo[kk], kh + 2);
            }
        }

        // ---- scale + causal mask (exp2 domain) ----
        bool domask = (kt >= nkt - 2);
        #pragma unroll
        for (int j = 0; j < 8; j++) {
            #pragma unroll
            for (int r = 0; r < 4; r++) {
                float v = s[j][r] * SC2;
                if (domask) {
                    int key = kt * 64 + j * 8 + qc + (r & 1);
                    int row = q0 + wid * 16 + qr + (r & 2) * 4;
                    if (key > row) v = -1e30f;
                }
                s[j][r] = v;
            }
        }

        // ---- online softmax ----
        float mx0 = -1e30f, mx1 = -1e30f;
        #pragma unroll
        for (int j = 0; j < 8; j++) {
            mx0 = fmaxf(mx0, fmaxf(s[j][0], s[j][1]));
            mx1 = fmaxf(mx1, fmaxf(s[j][2], s[j][3]));
        }
        mx0 = fmaxf(mx0, __shfl_xor_sync(0xffffffffu, mx0, 1));
        mx0 = fmaxf(mx0, __shfl_xor_sync(0xffffffffu, mx0, 2));
        mx1 = fmaxf(mx1, __shfl_xor_sync(0xffffffffu, mx1, 1));
        mx1 = fmaxf(mx1, __shfl_xor_sync(0xffffffffu, mx1, 2));
        float mn0 = fmaxf(m0, mx0), mn1 = fmaxf(m1, mx1);
        float al0 = ex2f(m0 - mn0), al1 = ex2f(m1 - mn1);
        float sm0 = 0.f, sm1 = 0.f;
        #pragma unroll
        for (int j = 0; j < 8; j++) {
            s[j][0] = ex2f(s[j][0] - mn0); sm0 += s[j][0];
            s[j][1] = ex2f(s[j][1] - mn0); sm0 += s[j][1];
            s[j][2] = ex2f(s[j][2] - mn1); sm1 += s[j][2];
            s[j][3] = ex2f(s[j][3] - mn1); sm1 += s[j][3];
        }
        sm0 += __shfl_xor_sync(0xffffffffu, sm0, 1);
        sm0 += __shfl_xor_sync(0xffffffffu, sm0, 2);
        sm1 += __shfl_xor_sync(0xffffffffu, sm1, 1);
        sm1 += __shfl_xor_sync(0xffffffffu, sm1, 2);
        l0 = l0 * al0 + sm0;  l1 = l1 * al1 + sm1;
        m0 = mn0;  m1 = mn1;
        #pragma unroll
        for (int j = 0; j < 8; j++) {
            oac[j][0] *= al0; oac[j][1] *= al0;
            oac[j][2] *= al1; oac[j][3] *= al1;
        }

        // ---- O += P V ----
        #pragma unroll
        for (int kk = 0; kk < 4; kk++) {
            uint32_t pah[4], pal[4];
            packsplit(s[2*kk][0],   s[2*kk][1],   pah[0], pal[0]);
            packsplit(s[2*kk][2],   s[2*kk][3],   pah[1], pal[1]);
            packsplit(s[2*kk+1][0], s[2*kk+1][1], pah[2], pal[2]);
            packsplit(s[2*kk+1][2], s[2*kk+1][3], pah[3], pal[3]);
            #pragma unroll
            for (int jj = 0; jj < 4; jj++) {
                int row = kk * 16 + (part & 1) * 8 + off;
                int colb = jj * 32 + (part & 2) * 8;
                uint32_t so = SMEM_SWIZZLE_128B((uint32_t)(row * 128 + colb));
                uint32_t vh[4], vl[4];
                ldsm4t(vh, st + AT_VHI + so);
                ldsm4t(vl, st + AT_VLO + so);
                mma_bf16(oac[2*jj],   pah, vh);
                mma_bf16(oac[2*jj],   pah, vl);
                mma_bf16(oac[2*jj],   pal, vh);
                mma_bf16(oac[2*jj+1], pah, vh + 2);
                mma_bf16(oac[2*jj+1], pah, vl + 2);
                mma_bf16(oac[2*jj+1], pal, vh + 2);
            }
        }
        __syncthreads();
    }

    // ---- epilogue: normalize + bf16 split + store ----
    float inv0 = 1.f / l0, inv1 = 1.f / l1;
    #pragma unroll
    for (int j = 0; j < 8; j++) {
        size_t i0 = (size_t)(b*T + q0 + wid*16 + qr) * C + hh * D + j * 8 + qc;
        size_t i1 = (size_t)(b*T + q0 + wid*16 + qr + 8) * C + hh * D + j * 8 + qc;
        uint32_t ph, pl;
        packsplit(oac[j][0] * inv0, oac[j][1] * inv0, ph, pl);
        *(uint32_t*)(yhi + i0) = ph;  *(uint32_t*)(ylo + i0) = pl;
        packsplit(oac[j][2] * inv1, oac[j][3] * inv1, ph, pl);
        *(uint32_t*)(yhi + i1) = ph;  *(uint32_t*)(ylo + i1) = pl;
    }
}

// ======================= HMMA bf16x3 GEMM =======================
// epi: 0 fp32; 1 fp32 + resid; 2 relu(acc)^2 -> bf16 pair; 3 acc -> bf16 pair
#define KTILE 64
#define OFF_AH 0
#define OFF_AL 16384
#define OFF_BH 32768
#define OFF_BL 49152
#define STAGE_BYTES 65536
#define SMEM_GEMM_BYTES (2*STAGE_BYTES)

__global__ void __launch_bounds__(256) gemm_bf16x3(
    const __nv_bfloat16* __restrict__ Ahi, const __nv_bfloat16* __restrict__ Alo,
    const __nv_bfloat16* __restrict__ Bhi, const __nv_bfloat16* __restrict__ Blo,
    size_t bstride,
    float* __restrict__ Cout,
    __nv_bfloat16* __restrict__ Ohi, __nv_bfloat16* __restrict__ Olo,
    const float* __restrict__ resid,
    const int* __restrict__ tileExpert,
    int N, int K, int epi)
{
    extern __shared__ __align__(1024) char smem[];
    int by = blockIdx.y, bx = blockIdx.x;
    int e = 0;
    if (tileExpert) { e = tileExpert[by]; if (e < 0) return; }
    const __nv_bfloat16* Bh = Bhi + (size_t)e * bstride;
    const __nv_bfloat16* Bl = Blo + (size_t)e * bstride;

    uint32_t sb = smem_to_u32(smem);
    int tid = threadIdx.x, wid = tid >> 5, lid = tid & 31;
    int wm = wid & 1, wn = wid >> 1;
    int row0 = by * 128, col0 = bx * 128;
    int nkt = K / KTILE;

    float acc[4][4][4];
    #pragma unroll
    for (int i = 0; i < 4; i++)
        #pragma unroll
        for (int j = 0; j < 4; j++)
            #pragma unroll
            for (int r = 0; r < 4; r++) acc[i][j][r] = 0.f;

    int lr = tid >> 3, lc = tid & 7;

    {
        #pragma unroll
        for (int i = 0; i < 4; i++) {
            int r = lr + i * 32;
            uint32_t so = SMEM_SWIZZLE_128B((uint32_t)(r * 128 + lc * 16));
            size_t ga = (size_t)(row0 + r) * K + lc * 8;
            size_t gb = (size_t)(col0 + r) * K + lc * 8;
            CP16(sb + OFF_AH + so, Ahi + ga);
            CP16(sb + OFF_AL + so, Alo + ga);
            CP16(sb + OFF_BH + so, Bh + gb);
            CP16(sb + OFF_BL + so, Bl + gb);
        }
        asm volatile("cp.async.commit_group;" ::: "memory");
    }

    for (int kt = 0; kt < nkt; kt++) {
        uint32_t cur = (uint32_t)(kt & 1) * STAGE_BYTES;
        if (kt + 1 < nkt) {
            uint32_t nxt = (uint32_t)((kt + 1) & 1) * STAGE_BYTES;
            int k0 = (kt + 1) * KTILE;
            #pragma unroll
            for (int i = 0; i < 4; i++) {
                int r = lr + i * 32;
                uint32_t so = SMEM_SWIZZLE_128B((uint32_t)(r * 128 + lc * 16));
                size_t ga = (size_t)(row0 + r) * K + k0 + lc * 8;
                size_t gb = (size_t)(col0 + r) * K + k0 + lc * 8;
                CP16(sb + nxt + OFF_AH + so, Ahi + ga);
                CP16(sb + nxt + OFF_AL + so, Alo + ga);
                CP16(sb + nxt + OFF_BH + so, Bh + gb);
                CP16(sb + nxt + OFF_BL + so, Bl + gb);
            }
            asm volatile("cp.async.commit_group;" ::: "memory");
            asm volatile("cp.async.wait_group 1;" ::: "memory");
        } else {
            asm volatile("cp.async.wait_group 0;" ::: "memory");
        }
        __syncthreads();

        uint32_t sAH = sb + cur + OFF_AH, sAL = sb + cur + OFF_AL;
        uint32_t sBH = sb + cur + OFF_BH, sBL = sb + cur + OFF_BL;
        #pragma unroll
        for (int kk = 0; kk < 4; kk++) {
            int colb = (kk * 16 + (lid >> 4) * 8) * 2;
            uint32_t a_hi[4][4], a_lo[4][4];
            #pragma unroll
            for (int mf = 0; mf < 4; mf++) {
                int rowm = wm * 64 + mf * 16 + (lid & 15);
                uint32_t so = SMEM_SWIZZLE_128B((uint32_t)(rowm * 128 + colb));
                ldsm4(a_hi[mf], sAH + so);
                ldsm4(a_lo[mf], sAL + so);
            }
            uint32_t b_hi[4][2], b_lo[4][2];
            #pragma unroll
            for (int g = 0; g < 2; g++) {
                int rown = wn * 32 + g * 16 + (lid & 15);
                uint32_t so = SMEM_SWIZZLE_128B((uint32_t)(rown * 128 + colb));
                uint32_t r4[4];
                ldsm4(r4, sBH + so);
                b_hi[2*g][0] = r4[0]; b_hi[2*g+1][0] = r4[1];
                b_hi[2*g][1] = r4[2]; b_hi[2*g+1][1] = r4[3];
                ldsm4(r4, sBL + so);
                b_lo[2*g][0] = r4[0]; b_lo[2*g+1][0] = r4[1];
                b_lo[2*g][1] = r4[2]; b_lo[2*g+1][1] = r4[3];
            }
            #pragma unroll
            for (int mf = 0; mf < 4; mf++)
                #pragma unroll
                for (int nf = 0; nf < 4; nf++) {
                    mma_bf16(acc[mf][nf], a_hi[mf], b_hi[nf]);
                    mma_bf16(acc[mf][nf], a_hi[mf], b_lo[nf]);
                    mma_bf16(acc[mf][nf], a_lo[mf], b_hi[nf]);
                }
        }
        __syncthreads();
    }

    int qr = lid >> 2, qc = (lid & 3) * 2;
    #pragma unroll
    for (int mf = 0; mf < 4; mf++) {
        #pragma unroll
        for (int nf = 0; nf < 4; nf++) {
            float* cc = acc[mf][nf];
            int col = col0 + wn * 32 + nf * 8 + qc;
            #pragma unroll
            for (int half = 0; half < 2; half++) {
                int row = row0 + wm * 64 + mf * 16 + qr + half * 8;
                size_t idx = (size_t)row * N + col;
                float v0 = cc[2*half], v1 = cc[2*half + 1];
                if (epi == 0) {
                    *(float2*)(Cout + idx) = make_float2(v0, v1);
                } else if (epi == 1) {
                    float2 rr = *(const float2*)(resid + idx);
                    *(float2*)(Cout + idx) = make_float2(v0 + rr.x, v1 + rr.y);
                } else {
                    if (epi == 2) {
                        v0 = fmaxf(v0, 0.f); v0 *= v0;
                        v1 = fmaxf(v1, 0.f); v1 *= v1;
                    }
                    uint32_t ph, pl;
                    packsplit(v0, v1, ph, pl);
                    *(uint32_t*)(Ohi + idx) = ph;
                    *(uint32_t*)(Olo + idx) = pl;
                }
            }
        }
    }
}

// ======================= router / grouping / scatter / scalars =======================
__global__ void router_kernel(const float* __restrict__ h2, const float* __restrict__ Wr) {
    int t = blockIdx.x;
    __shared__ float red[16];
    float a0 = 0.f, a1 = 0.f, a2 = 0.f, a3 = 0.f;
    const float* hp = h2 + (size_t)t * C;
    for (int c = threadIdx.x; c < C; c += 128) {
        float hv = hp[c];
        const float4 w = *(const float4*)(Wr + (size_t)c * E);
        a0 += hv * w.x; a1 += hv * w.y; a2 += hv * w.z; a3 += hv * w.w;
    }
    #pragma unroll
    for (int o = 16; o; o >>= 1) {
        a0 += __shfl_xor_sync(0xffffffffu, a0, o);
        a1 += __shfl_xor_sync(0xffffffffu, a1, o);
        a2 += __shfl_xor_sync(0xffffffffu, a2, o);
        a3 += __shfl_xor_sync(0xffffffffu, a3, o);
    }
    if ((threadIdx.x & 31) == 0) {
        int w = threadIdx.x >> 5;
        red[w*4+0] = a0; red[w*4+1] = a1; red[w*4+2] = a2; red[w*4+3] = a3;
    }
    __syncthreads();
    if (threadIdx.x == 0) {
        float lg[4];
        #pragma unroll
        for (int e = 0; e < 4; e++)
            lg[e] = red[e] + red[4+e] + red[8+e] + red[12+e];
        int arg = 0;
        #pragma unroll
        for (int e = 1; e < 4; e++) if (lg[e] > lg[arg]) arg = e;
        float m = fmaxf(fmaxf(lg[0], lg[1]), fmaxf(lg[2], lg[3]));
        float ez[4]; float sum = 0.f;
        #pragma unroll
        for (int e = 0; e < 4; e++) { ez[e] = expf(lg[e] - m); sum += ez[e]; }
        float p[4];
        #pragma unroll
        for (int e = 0; e < 4; e++) p[e] = ez[e] / sum;
        g_expert[t] = arg;
        atomicAdd(&g_counts[arg], 1);
        #pragma unroll
        for (int e = 0; e < 4; e++) atomicAdd(&g_expsum[e], (double)p[e]);
        float lse = m + logf(sum);
        atomicAdd(&g_zsum, (double)lse * (double)lse);
        float ent = 0.f;
        #pragma unroll
        for (int e = 0; e < 4; e++) ent -= p[e] * logf(p[e] + 1e-9f);
        atomicAdd(&g_entsum, (double)ent);
    }
}

__global__ void offsets_kernel() {
    if (threadIdx.x == 0 && blockIdx.x == 0) {
        int off = 0;
        for (int e = 0; e < E; e++) {
            g_segstart[e] = off;
            int padded = (g_counts[e] + 127) & ~127;
            for (int i = 0; i < padded / 128; i++)
                g_tileExpert[off / 128 + i] = e;
            off += padded;
        }
    }
}

__global__ void assign_kernel(const float* __restrict__ h2) {
    int t = blockIdx.x;
    __shared__ int slot_s;
    if (threadIdx.x == 0) {
        int e = g_expert[t];
        int slot = g_segstart[e] + atomicAdd(&g_cursor[e], 1);
        g_tokenOfRow[slot] = t;
        slot_s = slot;
    }
    __syncthreads();
    int s = slot_s;
    float4 v = ((const float4*)(h2 + (size_t)t * C))[threadIdx.x];
    __nv_bfloat16 h0,l0,h1,l1,h2b,l2,h3,l3;
    bsplit(v.x,h0,l0); bsplit(v.y,h1,l1); bsplit(v.z,h2b,l2); bsplit(v.w,h3,l3);
    __nv_bfloat162* hp = (__nv_bfloat162*)(g_h2g_hi + (size_t)s * C);
    __nv_bfloat162* lp = (__nv_bfloat162*)(g_h2g_lo + (size_t)s * C);
    hp[threadIdx.x*2]   = __nv_bfloat162(h0, h1);
    hp[threadIdx.x*2+1] = __nv_bfloat162(h2b, h3);
    lp[threadIdx.x*2]   = __nv_bfloat162(l0, l1);
    lp[threadIdx.x*2+1] = __nv_bfloat162(l2, l3);
}

__global__ void scatter_kernel(const float* __restrict__ x2, float* __restrict__ out) {
    int r = blockIdx.x;
    int t = g_tokenOfRow[r];
    if (t < 0) return;
    float4 a = ((const float4*)(x2 + (size_t)t * C))[threadIdx.x];
    float4 b = ((const float4*)(g_outg + (size_t)r * C))[threadIdx.x];
    ((float4*)(out + (size_t)t * C))[threadIdx.x] =
        make_float4(a.x + b.x, a.y + b.y, a.z + b.z, a.w + b.w);
}

__global__ void scalars_kernel(float* __restrict__ out) {
    if (threadIdx.x == 0 && blockIdx.x == 0) {
        const double NTOK = (double)BT;
        double aux = 0.0;
        for (int e = 0; e < E; e++) {
            double actual = (double)g_counts[e] / NTOK;
            double expd   = g_expsum[e] / NTOK;
            aux += actual * expd;
        }
        size_t base = (size_t)BT * C;
        out[base + 0] = (float)((double)E * aux);
        out[base + 1] = (float)(g_zsum / NTOK);
        out[base + 2] = (float)((g_entsum / NTOK) / log((double)E));
        for (int e = 0; e < E; e++)
            out[base + 3 + e] = (float)((double)g_counts[e] / NTOK);
    }
}

// ======================= launch =======================
static void* sym(const void* s) { void* p = nullptr; cudaGetSymbolAddress(&p, s); return p; }

extern "C" void kernel_launch(void* const* d_in, const int* in_sizes, int n_in,
                              void* d_out, int out_size)
{
    const float* x     = (const float*)d_in[0];
    const float* Wq    = (const float*)d_in[1];
    const float* Wk    = (const float*)d_in[2];
    const float* Wv    = (const float*)d_in[3];
    const float* Wo    = (const float*)d_in[4];
    const float* Wr    = (const float*)d_in[5];
    const float* Wfc   = (const float*)d_in[6];
    const float* Wproj = (const float*)d_in[7];
    float* out = (float*)d_out;

    static bool attr_set = false;
    if (!attr_set) {
        cudaFuncSetAttribute(gemm_bf16x3, cudaFuncAttributeMaxDynamicSharedMemorySize, SMEM_GEMM_BYTES);
        cudaFuncSetAttribute(attn_mma_kernel, cudaFuncAttributeMaxDynamicSharedMemorySize, ATT_SMEM);
        attr_set = true;
    }

    __nv_bfloat16* h1h = (__nv_bfloat16*)sym(g_h1_hi);
    __nv_bfloat16* h1l = (__nv_bfloat16*)sym(g_h1_lo);
    float* qb = (float*)sym(g_q);
    float* kb = (float*)sym(g_k);
    __nv_bfloat16* qh = (__nv_bfloat16*)sym(g_qhi); __nv_bfloat16* ql = (__nv_bfloat16*)sym(g_qlo);
    __nv_bfloat16* kh = (__nv_bfloat16*)sym(g_khi); __nv_bfloat16* kl = (__nv_bfloat16*)sym(g_klo);
    __nv_bfloat16* vh = (__nv_bfloat16*)sym(g_vhi); __nv_bfloat16* vl = (__nv_bfloat16*)sym(g_vlo);
    __nv_bfloat16* yh = (__nv_bfloat16*)sym(g_y_hi);
    __nv_bfloat16* yl = (__nv_bfloat16*)sym(g_y_lo);
    float* x2 = (float*)sym(g_x2);
    float* h2 = (float*)sym(g_h2);
    __nv_bfloat16* h2gh = (__nv_bfloat16*)sym(g_h2g_hi);
    __nv_bfloat16* h2gl = (__nv_bfloat16*)sym(g_h2g_lo);
    __nv_bfloat16* hidh = (__nv_bfloat16*)sym(g_hid_hi);
    __nv_bfloat16* hidl = (__nv_bfloat16*)sym(g_hid_lo);
    float* outg = (float*)sym(g_outg);
    __nv_bfloat16* wqh = (__nv_bfloat16*)sym(g_wq_hi); __nv_bfloat16* wql = (__nv_bfloat16*)sym(g_wq_lo);
    __nv_bfloat16* wkh = (__nv_bfloat16*)sym(g_wk_hi); __nv_bfloat16* wkl = (__nv_bfloat16*)sym(g_wk_lo);
    __nv_bfloat16* wvh = (__nv_bfloat16*)sym(g_wv_hi); __nv_bfloat16* wvl = (__nv_bfloat16*)sym(g_wv_lo);
    __nv_bfloat16* woh = (__nv_bfloat16*)sym(g_wo_hi); __nv_bfloat16* wol = (__nv_bfloat16*)sym(g_wo_lo);
    __nv_bfloat16* wfh = (__nv_bfloat16*)sym(g_wfc_hi); __nv_bfloat16* wfl = (__nv_bfloat16*)sym(g_wfc_lo);
    __nv_bfloat16* wph = (__nv_bfloat16*)sym(g_wpj_hi); __nv_bfloat16* wpl = (__nv_bfloat16*)sym(g_wpj_lo);
    int* tileE = (int*)sym(g_tileExpert);

    dim3 wb(32, 8);
    dim3 gq(C / 128, BT / 128);

    // ordered so launch #6 (ncu -s 5 -c 1) is the Q-projection GEMM
    reset_kernel<<<(GROUP_CAP + 255) / 256, 256>>>();                       // 1
    wconv_kernel<<<dim3(C/32, C/32, 1), wb>>>(Wq, wqh, wql, C, C);          // 2
    wconv_kernel<<<dim3(C/32, C/32, 1), wb>>>(Wk, wkh, wkl, C, C);          // 3
    wconv_kernel<<<dim3(C/32, C/32, 1), wb>>>(Wv, wvh, wvl, C, C);          // 4
    rmsnorm_kernel<<<BT, 256>>>(x, nullptr, h1h, h1l);                      // 5
    gemm_bf16x3<<<gq, 256, SMEM_GEMM_BYTES>>>(h1h, h1l, wqh, wql, 0, qb,    // 6 <- profiled
        nullptr, nullptr, nullptr, nullptr, C, C, 0);
    gemm_bf16x3<<<gq, 256, SMEM_GEMM_BYTES>>>(h1h, h1l, wkh, wkl, 0, kb,    // 7
        nullptr, nullptr, nullptr, nullptr, C, C, 0);
    gemm_bf16x3<<<gq, 256, SMEM_GEMM_BYTES>>>(h1h, h1l, wvh, wvl, 0,        // 8 (V -> bf16 pair)
        nullptr, vh, vl, nullptr, nullptr, C, C, 3);
    wconv_kernel<<<dim3(C/32,  C/32,  1), wb>>>(Wo,    woh, wol, C,  C);    // 9
    wconv_kernel<<<dim3(FF/32, C/32,  E), wb>>>(Wfc,   wfh, wfl, C,  FF);   // 10
    wconv_kernel<<<dim3(C/32,  FF/32, E), wb>>>(Wproj, wph, wpl, FF, C);    // 11
    qk_rope_kernel<<<BT, 512>>>(qb, kb, qh, ql, kh, kl);                    // 12
    attn_mma_kernel<<<dim3(T/128, Bq*H), 256, ATT_SMEM>>>(                  // 13
        qh, ql, kh, kl, vh, vl, yh, yl);
    gemm_bf16x3<<<gq, 256, SMEM_GEMM_BYTES>>>(yh, yl, woh, wol, 0, x2,      // 14
        nullptr, nullptr, x, nullptr, C, C, 1);
    rmsnorm_kernel<<<BT, 256>>>(x2, h2, nullptr, nullptr);                  // 15
    router_kernel<<<BT, 128>>>(h2, Wr);                                     // 16
    offsets_kernel<<<1, 32>>>();                                            // 17
    zero_h2g_pair_kernel<<<GROUP_CAP, 256>>>();                             // 18
    assign_kernel<<<BT, 256>>>(h2);                                         // 19
    gemm_bf16x3<<<dim3(FF/128, NTILES), 256, SMEM_GEMM_BYTES>>>(            // 20
        h2gh, h2gl, wfh, wfl, (size_t)FF * C, nullptr, hidh, hidl, nullptr, tileE, FF, C, 2);
    gemm_bf16x3<<<dim3(C/128, NTILES), 256, SMEM_GEMM_BYTES>>>(             // 21
        hidh, hidl, wph, wpl, (size_t)C * FF, outg, nullptr, nullptr, nullptr, tileE, C, FF, 0);
    scatter_kernel<<<GROUP_CAP, 256>>>(x2, out);                            // 22
    scalars_kernel<<<1, 32>>>(out);                                         // 23
}

// round 6
// speedup vs baseline: 2.9771x; 1.0053x over previous
#include <cuda_runtime.h>
#include <cuda_bf16.h>
#include <cstdint>
#include <math.h>

#define Bq 2
#define T 2048
#define C 1024
#define H 16
#define D 64
#define E 4
#define BT (Bq*T)
#define FF (4*C)
#define GROUP_CAP (BT + E*128)
#define NTILES (GROUP_CAP/128)
#define EPS_RMS 1.1920929e-07f

#define SMEM_SWIZZLE_128B(b) ((b) ^ (((b) >> 3) & 0x70))

__device__ __forceinline__ uint32_t smem_to_u32(const void* p) {
    uint32_t a;
    asm("{ .reg .u64 t; cvta.to.shared.u64 t, %1; cvt.u32.u64 %0, t; }" : "=r"(a) : "l"(p));
    return a;
}
__device__ __forceinline__ void ldsm4(uint32_t* r, uint32_t addr) {
    asm volatile("ldmatrix.sync.aligned.m8n8.x4.shared.b16 {%0,%1,%2,%3}, [%4];"
                 : "=r"(r[0]), "=r"(r[1]), "=r"(r[2]), "=r"(r[3]) : "r"(addr));
}
__device__ __forceinline__ void ldsm4t(uint32_t* r, uint32_t addr) {
    asm volatile("ldmatrix.sync.aligned.m8n8.x4.trans.shared.b16 {%0,%1,%2,%3}, [%4];"
                 : "=r"(r[0]), "=r"(r[1]), "=r"(r[2]), "=r"(r[3]) : "r"(addr));
}
__device__ __forceinline__ void mma_bf16(float* c, const uint32_t* a, const uint32_t* b) {
    asm volatile("mma.sync.aligned.m16n8k16.row.col.f32.bf16.bf16.f32 "
        "{%0,%1,%2,%3}, {%4,%5,%6,%7}, {%8,%9}, {%0,%1,%2,%3};"
        : "+f"(c[0]), "+f"(c[1]), "+f"(c[2]), "+f"(c[3])
        : "r"(a[0]), "r"(a[1]), "r"(a[2]), "r"(a[3]), "r"(b[0]), "r"(b[1]));
}
__device__ __forceinline__ float ex2f(float x) {
    float y; asm("ex2.approx.ftz.f32 %0, %1;" : "=f"(y) : "f"(x)); return y;
}
#define CP16(s, g) asm volatile("cp.async.cg.shared.global [%0], [%1], 16;" \
                                :: "r"(s), "l"(g) : "memory")

// ======================= scratch (static device globals) =======================
__device__ __nv_bfloat16 g_h1_hi[BT*C], g_h1_lo[BT*C];
__device__ float g_q[BT*C], g_k[BT*C];
__device__ __nv_bfloat16 g_qhi[BT*C], g_qlo[BT*C];
__device__ __nv_bfloat16 g_khi[BT*C], g_klo[BT*C];
__device__ __nv_bfloat16 g_vhi[BT*C], g_vlo[BT*C];
__device__ __nv_bfloat16 g_y_hi[BT*C], g_y_lo[BT*C];
__device__ float g_x2[BT*C], g_h2[BT*C];
__device__ __nv_bfloat16 g_h2g_hi[GROUP_CAP*C], g_h2g_lo[GROUP_CAP*C];
__device__ __nv_bfloat16 g_hid_hi[(size_t)GROUP_CAP*FF], g_hid_lo[(size_t)GROUP_CAP*FF];
__device__ float g_outg[GROUP_CAP*C];
__device__ __nv_bfloat16 g_wq_hi[C*C], g_wq_lo[C*C];
__device__ __nv_bfloat16 g_wk_hi[C*C], g_wk_lo[C*C];
__device__ __nv_bfloat16 g_wv_hi[C*C], g_wv_lo[C*C];
__device__ __nv_bfloat16 g_wo_hi[C*C], g_wo_lo[C*C];
__device__ __nv_bfloat16 g_wfc_hi[(size_t)E*C*FF], g_wfc_lo[(size_t)E*C*FF];   // [E][FF,C]
__device__ __nv_bfloat16 g_wpj_hi[(size_t)E*FF*C], g_wpj_lo[(size_t)E*FF*C];   // [E][C,FF]
__device__ int   g_expert[BT];
__device__ int   g_counts[E];
__device__ int   g_cursor[E];
__device__ int   g_segstart[E];
__device__ int   g_tileExpert[NTILES];
__device__ int   g_tokenOfRow[GROUP_CAP];
__device__ double g_expsum[E];
__device__ double g_zsum;
__device__ double g_entsum;

__device__ __forceinline__ void bsplit(float v, __nv_bfloat16& h, __nv_bfloat16& l) {
    h = __float2bfloat16(v);
    l = __float2bfloat16(v - __bfloat162float(h));
}
__device__ __forceinline__ void packsplit(float v0, float v1, uint32_t& hi, uint32_t& lo) {
    __nv_bfloat16 h0, l0, h1, l1;
    bsplit(v0, h0, l0); bsplit(v1, h1, l1);
    __nv_bfloat162 hh(h0, h1), ll(l0, l1);
    hi = *reinterpret_cast<uint32_t*>(&hh);
    lo = *reinterpret_cast<uint32_t*>(&ll);
}

// ======================= small kernels =======================
__global__ void reset_kernel() {
    int i = blockIdx.x * blockDim.x + threadIdx.x;
    if (i < E) { g_counts[i] = 0; g_cursor[i] = 0; g_expsum[i] = 0.0; }
    if (i == 0) { g_zsum = 0.0; g_entsum = 0.0; }
    if (i < NTILES) g_tileExpert[i] = -1;
    if (i < GROUP_CAP) g_tokenOfRow[i] = -1;
}

// zero only pad rows (tokenOfRow < 0); run AFTER assign_kernel
__global__ void zero_pad_kernel() {
    int r = blockIdx.x;
    if (g_tokenOfRow[r] >= 0) return;
    uint2 z = make_uint2(0u, 0u);
    ((uint2*)(g_h2g_hi + (size_t)r * C))[threadIdx.x] = z;
    ((uint2*)(g_h2g_lo + (size_t)r * C))[threadIdx.x] = z;
}

// transpose + bf16-split weights: W [Kd, Nd] fp32 -> T [Nd, Kd] bf16 hi/lo
// 64x64 tile, float4 loads, uint2 (4x bf16) stores: 128B contiguous warp segments
__global__ void __launch_bounds__(256) wconv_kernel(
    const float* __restrict__ W,
    __nv_bfloat16* __restrict__ Thi, __nv_bfloat16* __restrict__ Tlo,
    int Kd, int Nd) {
    __shared__ float tile[64][65];
    int b = blockIdx.z;
    const float* Wb = W + (size_t)b * Kd * Nd;
    __nv_bfloat16* Th = Thi + (size_t)b * Kd * Nd;
    __nv_bfloat16* Tl = Tlo + (size_t)b * Kd * Nd;
    int n0 = blockIdx.x * 64, k0 = blockIdx.y * 64;
    int tid = threadIdx.x;
    int lr = tid >> 4, lc = (tid & 15) * 4;
    #pragma unroll
    for (int i = 0; i < 4; i++) {
        int k = lr + i * 16;
        float4 v = *(const float4*)(Wb + (size_t)(k0 + k) * Nd + n0 + lc);
        tile[k][lc] = v.x; tile[k][lc+1] = v.y; tile[k][lc+2] = v.z; tile[k][lc+3] = v.w;
    }
    __syncthreads();
    int wn = tid >> 4, wk = (tid & 15) * 4;
    #pragma unroll
    for (int i = 0; i < 4; i++) {
        int n = wn + i * 16;
        float v0 = tile[wk][n],   v1 = tile[wk+1][n];
        float v2 = tile[wk+2][n], v3 = tile[wk+3][n];
        uint32_t h01, l01, h23, l23;
        packsplit(v0, v1, h01, l01);
        packsplit(v2, v3, h23, l23);
        size_t o = (size_t)(n0 + n) * Kd + k0 + wk;
        *(uint2*)(Th + o) = make_uint2(h01, h23);
        *(uint2*)(Tl + o) = make_uint2(l01, l23);
    }
}

// RMSNorm over C; optional fp32 out, optional bf16 hi/lo pair out
__global__ void rmsnorm_kernel(const float* __restrict__ in, float* __restrict__ outf,
                               __nv_bfloat16* __restrict__ ohi, __nv_bfloat16* __restrict__ olo) {
    int t = blockIdx.x;
    const float4* ip = (const float4*)(in + (size_t)t * C);
    __shared__ float red[8];
    float4 v = ip[threadIdx.x];
    float ss = v.x*v.x + v.y*v.y + v.z*v.z + v.w*v.w;
    #pragma unroll
    for (int o = 16; o; o >>= 1) ss += __shfl_xor_sync(0xffffffffu, ss, o);
    if ((threadIdx.x & 31) == 0) red[threadIdx.x >> 5] = ss;
    __syncthreads();
    if (threadIdx.x == 0) {
        float s = 0.f;
        #pragma unroll
        for (int w = 0; w < 8; w++) s += red[w];
        red[0] = s;
    }
    __syncthreads();
    float r = rsqrtf(red[0] / (float)C + EPS_RMS);
    float4 o = make_float4(v.x*r, v.y*r, v.z*r, v.w*r);
    if (outf) ((float4*)(outf + (size_t)t * C))[threadIdx.x] = o;
    if (ohi) {
        __nv_bfloat16 h0,l0,h1,l1,h2,l2,h3,l3;
        bsplit(o.x,h0,l0); bsplit(o.y,h1,l1); bsplit(o.z,h2,l2); bsplit(o.w,h3,l3);
        __nv_bfloat162* hp = (__nv_bfloat162*)(ohi + (size_t)t * C);
        __nv_bfloat162* lp = (__nv_bfloat162*)(olo + (size_t)t * C);
        hp[threadIdx.x*2]   = __nv_bfloat162(h0, h1);
        hp[threadIdx.x*2+1] = __nv_bfloat162(h2, h3);
        lp[threadIdx.x*2]   = __nv_bfloat162(l0, l1);
        lp[threadIdx.x*2+1] = __nv_bfloat162(l2, l3);
    }
}

// per-head RMSNorm + RoPE for q and k; fp32 in -> bf16 hi/lo out
__global__ void qk_rope_kernel(const float* __restrict__ q, const float* __restrict__ k,
                               __nv_bfloat16* __restrict__ qhi, __nv_bfloat16* __restrict__ qlo,
                               __nv_bfloat16* __restrict__ khi, __nv_bfloat16* __restrict__ klo) {
    int tok  = blockIdx.x;
    int head = threadIdx.x >> 5;
    int lane = threadIdx.x & 31;
    int tpos = tok % T;
    float ex  = (float)(2 * lane) / 64.0f;
    float inv = 1.0f / powf(10000.0f, ex);
    float ang = (float)tpos * inv;
    float c = cosf(ang), s = sinf(ang);
    size_t base = (size_t)tok * C + head * D;
    #pragma unroll
    for (int m = 0; m < 2; m++) {
        const float* src = (m == 0 ? q : k) + base;
        __nv_bfloat16* dh = (m == 0 ? qhi : khi) + base;
        __nv_bfloat16* dl = (m == 0 ? qlo : klo) + base;
        float x1 = src[lane], x2 = src[lane + 32];
        float ss = x1*x1 + x2*x2;
        #pragma unroll
        for (int o = 16; o; o >>= 1) ss += __shfl_xor_sync(0xffffffffu, ss, o);
        float r = rsqrtf(ss / (float)D + EPS_RMS);
        x1 *= r; x2 *= r;
        float o1 =  x1 * c + x2 * s;
        float o2 = -x1 * s + x2 * c;
        __nv_bfloat16 h, l;
        bsplit(o1, h, l); dh[lane] = h;      dl[lane] = l;
        bsplit(o2, h, l); dh[lane + 32] = h; dl[lane + 32] = l;
    }
}

// ======================= HMMA flash attention (bf16x3) =======================
#define AT_QHI 0
#define AT_QLO 16384
#define AT_STG 32768
#define AT_STGSZ 32768
#define AT_KHI 0
#define AT_KLO 8192
#define AT_VHI 16384
#define AT_VLO 24576
#define ATT_SMEM (32768 + 2*32768)

__global__ void __launch_bounds__(256) attn_mma_kernel(
    const __nv_bfloat16* __restrict__ qhi, const __nv_bfloat16* __restrict__ qlo,
    const __nv_bfloat16* __restrict__ khi, const __nv_bfloat16* __restrict__ klo,
    const __nv_bfloat16* __restrict__ vhi, const __nv_bfloat16* __restrict__ vlo,
    __nv_bfloat16* __restrict__ yhi, __nv_bfloat16* __restrict__ ylo)
{
    extern __shared__ __align__(1024) char smem[];
    uint32_t sb = smem_to_u32(smem);
    int bh = blockIdx.y;
    int b = bh / H, hh = bh % H;
    int qb = blockIdx.x;
    int q0 = qb * 128;
    int tid = threadIdx.x, wid = tid >> 5, lid = tid & 31;
    int nkt = 2 * qb + 2;

    #pragma unroll
    for (int i = 0; i < 4; i++) {
        int lin = tid + i * 256;
        int r = lin >> 3, ch = lin & 7;
        uint32_t so = SMEM_SWIZZLE_128B((uint32_t)(r * 128 + ch * 16));
        size_t g = (size_t)(b*T + q0 + r) * C + hh * D + ch * 8;
        CP16(sb + AT_QHI + so, qhi + g);
        CP16(sb + AT_QLO + so, qlo + g);
    }
    asm volatile("cp.async.commit_group;" ::: "memory");
    #pragma unroll
    for (int i = 0; i < 2; i++) {
        int lin = tid + i * 256;
        int r = lin >> 3, ch = lin & 7;
        uint32_t so = SMEM_SWIZZLE_128B((uint32_t)(r * 128 + ch * 16));
        size_t g = (size_t)(b*T + r) * C + hh * D + ch * 8;
        uint32_t st = sb + AT_STG;
        CP16(st + AT_KHI + so, khi + g);
        CP16(st + AT_KLO + so, klo + g);
        CP16(st + AT_VHI + so, vhi + g);
        CP16(st + AT_VLO + so, vlo + g);
    }
    asm volatile("cp.async.commit_group;" ::: "memory");

    uint32_t qa_hi[4][4], qa_lo[4][4];
    float oac[8][4];
    #pragma unroll
    for (int j = 0; j < 8; j++)
        #pragma unroll
        for (int r = 0; r < 4; r++) oac[j][r] = 0.f;
    float m0 = -1e30f, m1 = -1e30f, l0 = 0.f, l1 = 0.f;

    int off = lid & 7, part = lid >> 3;
    int qr = lid >> 2, qc = (lid & 3) * 2;
    const float SC2 = 0.18033688011112042f;   // 0.125 * log2(e)

    for (int kt = 0; kt < nkt; kt++) {
        if (kt + 1 < nkt) {
            #pragma unroll
            for (int i = 0; i < 2; i++) {
                int lin = tid + i * 256;
                int r = lin >> 3, ch = lin & 7;
                uint32_t so = SMEM_SWIZZLE_128B((uint32_t)(r * 128 + ch * 16));
                size_t g = (size_t)(b*T + (kt + 1) * 64 + r) * C + hh * D + ch * 8;
                uint32_t st = sb + AT_STG + (uint32_t)((kt + 1) & 1) * AT_STGSZ;
                CP16(st + AT_KHI + so, khi + g);
                CP16(st + AT_KLO + so, klo + g);
                CP16(st + AT_VHI + so, vhi + g);
                CP16(st + AT_VLO + so, vlo + g);
            }
            asm volatile("cp.async.commit_group;" ::: "memory");
            asm volatile("cp.async.wait_group 1;" ::: "memory");
        } else {
            asm volatile("cp.async.wait_group 0;" ::: "memory");
        }
        __syncthreads();

        if (kt == 0) {
            #pragma unroll
            for (int kk = 0; kk < 4; kk++) {
                int row = wid * 16 + (part & 1) * 8 + off;
                int colb = kk * 32 + (part & 2) * 8;
                uint32_t so = SMEM_SWIZZLE_128B((uint32_t)(row * 128 + colb));
                ldsm4(qa_hi[kk], sb + AT_QHI + so);
                ldsm4(qa_lo[kk], sb + AT_QLO + so);
            }
        }

        uint32_t st = sb + AT_STG + (uint32_t)(kt & 1) * AT_STGSZ;

        float s[8][4];
        #pragma unroll
        for (int j = 0; j < 8; j++)
            #pragma unroll
            for (int r = 0; r < 4; r++) s[j][r] = 0.f;
        #pragma unroll
        for (int kk = 0; kk < 4; kk++) {
            #pragma unroll
            for (int jj = 0; jj < 4; jj++) {
                int row = jj * 16 + (part & 2) * 4 + off;
                int colb = kk * 32 + (part & 1) * 16;
                uint32_t so = SMEM_SWIZZLE_128B((uint32_t)(row * 128 + colb));
                uint32_t kh[4], kl[4];
                ldsm4(kh, st + AT_KHI + so);
                ldsm4(kl, st + AT_KLO + so);
                mma_bf16(s[2*jj],     qa_hi[kk], kh);
                mma_bf16(s[2*jj],     qa_hi[kk], kl);
                mma_bf16(s[2*jj],     qa_lo[kk], kh);
                mma_bf16(s[2*jj+1],   qa_hi[kk], kh + 2);
                mma_bf16(s[2*jj+1],   qa_hi[kk], kl + 2);
                mma_bf16(s[2*jj+1],   qa_lo[kk], kh + 2);
            }
        }

        bool domask = (kt >= nkt - 2);
        #pragma unroll
        for (int j = 0; j < 8; j++) {
            #pragma unroll
            for (int r = 0; r < 4; r++) {
                float v = s[j][r] * SC2;
                if (domask) {
                    int key = kt * 64 + j * 8 + qc + (r & 1);
                    int row = q0 + wid * 16 + qr + (r & 2) * 4;
                    if (key > row) v = -1e30f;
                }
                s[j][r] = v;
            }
        }

        float mx0 = -1e30f, mx1 = -1e30f;
        #pragma unroll
        for (int j = 0; j < 8; j++) {
            mx0 = fmaxf(mx0, fmaxf(s[j][0], s[j][1]));
            mx1 = fmaxf(mx1, fmaxf(s[j][2], s[j][3]));
        }
        mx0 = fmaxf(mx0, __shfl_xor_sync(0xffffffffu, mx0, 1));
        mx0 = fmaxf(mx0, __shfl_xor_sync(0xffffffffu, mx0, 2));
        mx1 = fmaxf(mx1, __shfl_xor_sync(0xffffffffu, mx1, 1));
        mx1 = fmaxf(mx1, __shfl_xor_sync(0xffffffffu, mx1, 2));
        float mn0 = fmaxf(m0, mx0), mn1 = fmaxf(m1, mx1);
        float al0 = ex2f(m0 - mn0), al1 = ex2f(m1 - mn1);
        float sm0 = 0.f, sm1 = 0.f;
        #pragma unroll
        for (int j = 0; j < 8; j++) {
            s[j][0] = ex2f(s[j][0] - mn0); sm0 += s[j][0];
            s[j][1] = ex2f(s[j][1] - mn0); sm0 += s[j][1];
            s[j][2] = ex2f(s[j][2] - mn1); sm1 += s[j][2];
            s[j][3] = ex2f(s[j][3] - mn1); sm1 += s[j][3];
        }
        sm0 += __shfl_xor_sync(0xffffffffu, sm0, 1);
        sm0 += __shfl_xor_sync(0xffffffffu, sm0, 2);
        sm1 += __shfl_xor_sync(0xffffffffu, sm1, 1);
        sm1 += __shfl_xor_sync(0xffffffffu, sm1, 2);
        l0 = l0 * al0 + sm0;  l1 = l1 * al1 + sm1;
        m0 = mn0;  m1 = mn1;
        #pragma unroll
        for (int j = 0; j < 8; j++) {
            oac[j][0] *= al0; oac[j][1] *= al0;
            oac[j][2] *= al1; oac[j][3] *= al1;
        }

        #pragma unroll
        for (int kk = 0; kk < 4; kk++) {
            uint32_t pah[4], pal[4];
            packsplit(s[2*kk][0],   s[2*kk][1],   pah[0], pal[0]);
            packsplit(s[2*kk][2],   s[2*kk][3],   pah[1], pal[1]);
            packsplit(s[2*kk+1][0], s[2*kk+1][1], pah[2], pal[2]);
            packsplit(s[2*kk+1][2], s[2*kk+1][3], pah[3], pal[3]);
            #pragma unroll
            for (int jj = 0; jj < 4; jj++) {
                int row = kk * 16 + (part & 1) * 8 + off;
                int colb = jj * 32 + (part & 2) * 8;
                uint32_t so = SMEM_SWIZZLE_128B((uint32_t)(row * 128 + colb));
                uint32_t vh[4], vl[4];
                ldsm4t(vh, st + AT_VHI + so);
                ldsm4t(vl, st + AT_VLO + so);
                mma_bf16(oac[2*jj],   pah, vh);
                mma_bf16(oac[2*jj],   pah, vl);
                mma_bf16(oac[2*jj],   pal, vh);
                mma_bf16(oac[2*jj+1], pah, vh + 2);
                mma_bf16(oac[2*jj+1], pah, vl + 2);
                mma_bf16(oac[2*jj+1], pal, vh + 2);
            }
        }
        __syncthreads();
    }

    float inv0 = 1.f / l0, inv1 = 1.f / l1;
    #pragma unroll
    for (int j = 0; j < 8; j++) {
        size_t i0 = (size_t)(b*T + q0 + wid*16 + qr) * C + hh * D + j * 8 + qc;
        size_t i1 = (size_t)(b*T + q0 + wid*16 + qr + 8) * C + hh * D + j * 8 + qc;
        uint32_t ph, pl;
        packsplit(oac[j][0] * inv0, oac[j][1] * inv0, ph, pl);
        *(uint32_t*)(yhi + i0) = ph;  *(uint32_t*)(ylo + i0) = pl;
        packsplit(oac[j][2] * inv1, oac[j][3] * inv1, ph, pl);
        *(uint32_t*)(yhi + i1) = ph;  *(uint32_t*)(ylo + i1) = pl;
    }
}

// ======================= HMMA bf16x3 GEMM =======================
// epi: 0 fp32; 1 fp32 + resid; 2 relu(acc)^2 -> bf16 pair; 3 acc -> bf16 pair
#define KTILE 64
#define OFF_AH 0
#define OFF_AL 16384
#define OFF_BH 32768
#define OFF_BL 49152
#define STAGE_BYTES 65536
#define SMEM_GEMM_BYTES (2*STAGE_BYTES)

__global__ void __launch_bounds__(256) gemm_bf16x3(
    const __nv_bfloat16* __restrict__ Ahi, const __nv_bfloat16* __restrict__ Alo,
    const __nv_bfloat16* __restrict__ Bhi, const __nv_bfloat16* __restrict__ Blo,
    size_t bstride,
    float* __restrict__ Cout,
    __nv_bfloat16* __restrict__ Ohi, __nv_bfloat16* __restrict__ Olo,
    const float* __restrict__ resid,
    const int* __restrict__ tileExpert,
    int N, int K, int epi)
{
    extern __shared__ __align__(1024) char smem[];
    int by = blockIdx.y, bx = blockIdx.x;
    int e = 0;
    if (tileExpert) { e = tileExpert[by]; if (e < 0) return; }
    const __nv_bfloat16* Bh = Bhi + (size_t)e * bstride;
    const __nv_bfloat16* Bl = Blo + (size_t)e * bstride;

    uint32_t sb = smem_to_u32(smem);
    int tid = threadIdx.x, wid = tid >> 5, lid = tid & 31;
    int wm = wid & 1, wn = wid >> 1;
    int row0 = by * 128, col0 = bx * 128;
    int nkt = K / KTILE;

    float acc[4][4][4];
    #pragma unroll
    for (int i = 0; i < 4; i++)
        #pragma unroll
        for (int j = 0; j < 4; j++)
            #pragma unroll
            for (int r = 0; r < 4; r++) acc[i][j][r] = 0.f;

    int lr = tid >> 3, lc = tid & 7;

    {
        #pragma unroll
        for (int i = 0; i < 4; i++) {
            int r = lr + i * 32;
            uint32_t so = SMEM_SWIZZLE_128B((uint32_t)(r * 128 + lc * 16));
            size_t ga = (size_t)(row0 + r) * K + lc * 8;
            size_t gb = (size_t)(col0 + r) * K + lc * 8;
            CP16(sb + OFF_AH + so, Ahi + ga);
            CP16(sb + OFF_AL + so, Alo + ga);
            CP16(sb + OFF_BH + so, Bh + gb);
            CP16(sb + OFF_BL + so, Bl + gb);
        }
        asm volatile("cp.async.commit_group;" ::: "memory");
    }

    for (int kt = 0; kt < nkt; kt++) {
        uint32_t cur = (uint32_t)(kt & 1) * STAGE_BYTES;
        if (kt + 1 < nkt) {
            uint32_t nxt = (uint32_t)((kt + 1) & 1) * STAGE_BYTES;
            int k0 = (kt + 1) * KTILE;
            #pragma unroll
            for (int i = 0; i < 4; i++) {
                int r = lr + i * 32;
                uint32_t so = SMEM_SWIZZLE_128B((uint32_t)(r * 128 + lc * 16));
                size_t ga = (size_t)(row0 + r) * K + k0 + lc * 8;
                size_t gb = (size_t)(col0 + r) * K + k0 + lc * 8;
                CP16(sb + nxt + OFF_AH + so, Ahi + ga);
                CP16(sb + nxt + OFF_AL + so, Alo + ga);
                CP16(sb + nxt + OFF_BH + so, Bh + gb);
                CP16(sb + nxt + OFF_BL + so, Bl + gb);
            }
            asm volatile("cp.async.commit_group;" ::: "memory");
            asm volatile("cp.async.wait_group 1;" ::: "memory");
        } else {
            asm volatile("cp.async.wait_group 0;" ::: "memory");
        }
        __syncthreads();

        uint32_t sAH = sb + cur + OFF_AH, sAL = sb + cur + OFF_AL;
        uint32_t sBH = sb + cur + OFF_BH, sBL = sb + cur + OFF_BL;
        #pragma unroll
        for (int kk = 0; kk < 4; kk++) {
            int colb = (kk * 16 + (lid >> 4) * 8) * 2;
            uint32_t a_hi[4][4], a_lo[4][4];
            #pragma unroll
            for (int mf = 0; mf < 4; mf++) {
                int rowm = wm * 64 + mf * 16 + (lid & 15);
                uint32_t so = SMEM_SWIZZLE_128B((uint32_t)(rowm * 128 + colb));
                ldsm4(a_hi[mf], sAH + so);
                ldsm4(a_lo[mf], sAL + so);
            }
            uint32_t b_hi[4][2], b_lo[4][2];
            #pragma unroll
            for (int g = 0; g < 2; g++) {
                int rown = wn * 32 + g * 16 + (lid & 15);
                uint32_t so = SMEM_SWIZZLE_128B((uint32_t)(rown * 128 + colb));
                uint32_t r4[4];
                ldsm4(r4, sBH + so);
                b_hi[2*g][0] = r4[0]; b_hi[2*g+1][0] = r4[1];
                b_hi[2*g][1] = r4[2]; b_hi[2*g+1][1] = r4[3];
                ldsm4(r4, sBL + so);
                b_lo[2*g][0] = r4[0]; b_lo[2*g+1][0] = r4[1];
                b_lo[2*g][1] = r4[2]; b_lo[2*g+1][1] = r4[3];
            }
            #pragma unroll
            for (int mf = 0; mf < 4; mf++)
                #pragma unroll
                for (int nf = 0; nf < 4; nf++) {
                    mma_bf16(acc[mf][nf], a_hi[mf], b_hi[nf]);
                    mma_bf16(acc[mf][nf], a_hi[mf], b_lo[nf]);
                    mma_bf16(acc[mf][nf], a_lo[mf], b_hi[nf]);
                }
        }
        __syncthreads();
    }

    int qr = lid >> 2, qc = (lid & 3) * 2;
    #pragma unroll
    for (int mf = 0; mf < 4; mf++) {
        #pragma unroll
        for (int nf = 0; nf < 4; nf++) {
            float* cc = acc[mf][nf];
            int col = col0 + wn * 32 + nf * 8 + qc;
            #pragma unroll
            for (int half = 0; half < 2; half++) {
                int row = row0 + wm * 64 + mf * 16 + qr + half * 8;
                size_t idx = (size_t)row * N + col;
                float v0 = cc[2*half], v1 = cc[2*half + 1];
                if (epi == 0) {
                    *(float2*)(Cout + idx) = make_float2(v0, v1);
                } else if (epi == 1) {
                    float2 rr = *(const float2*)(resid + idx);
                    *(float2*)(Cout + idx) = make_float2(v0 + rr.x, v1 + rr.y);
                } else {
                    if (epi == 2) {
                        v0 = fmaxf(v0, 0.f); v0 *= v0;
                        v1 = fmaxf(v1, 0.f); v1 *= v1;
                    }
                    uint32_t ph, pl;
                    packsplit(v0, v1, ph, pl);
                    *(uint32_t*)(Ohi + idx) = ph;
                    *(uint32_t*)(Olo + idx) = pl;
                }
            }
        }
    }
}

// ======================= router / grouping / scatter / scalars =======================
__global__ void router_kernel(const float* __restrict__ h2, const float* __restrict__ Wr) {
    int t = blockIdx.x;
    __shared__ float red[16];
    float a0 = 0.f, a1 = 0.f, a2 = 0.f, a3 = 0.f;
    const float* hp = h2 + (size_t)t * C;
    for (int c = threadIdx.x; c < C; c += 128) {
        float hv = hp[c];
        const float4 w = *(const float4*)(Wr + (size_t)c * E);
        a0 += hv * w.x; a1 += hv * w.y; a2 += hv * w.z; a3 += hv * w.w;
    }
    #pragma unroll
    for (int o = 16; o; o >>= 1) {
        a0 += __shfl_xor_sync(0xffffffffu, a0, o);
        a1 += __shfl_xor_sync(0xffffffffu, a1, o);
        a2 += __shfl_xor_sync(0xffffffffu, a2, o);
        a3 += __shfl_xor_sync(0xffffffffu, a3, o);
    }
    if ((threadIdx.x & 31) == 0) {
        int w = threadIdx.x >> 5;
        red[w*4+0] = a0; red[w*4+1] = a1; red[w*4+2] = a2; red[w*4+3] = a3;
    }
    __syncthreads();
    if (threadIdx.x == 0) {
        float lg[4];
        #pragma unroll
        for (int e = 0; e < 4; e++)
            lg[e] = red[e] + red[4+e] + red[8+e] + red[12+e];
        int arg = 0;
        #pragma unroll
        for (int e = 1; e < 4; e++) if (lg[e] > lg[arg]) arg = e;
        float m = fmaxf(fmaxf(lg[0], lg[1]), fmaxf(lg[2], lg[3]));
        float ez[4]; float sum = 0.f;
        #pragma unroll
        for (int e = 0; e < 4; e++) { ez[e] = expf(lg[e] - m); sum += ez[e]; }
        float p[4];
        #pragma unroll
        for (int e = 0; e < 4; e++) p[e] = ez[e] / sum;
        g_expert[t] = arg;
        atomicAdd(&g_counts[arg], 1);
        #pragma unroll
        for (int e = 0; e < 4; e++) atomicAdd(&g_expsum[e], (double)p[e]);
        float lse = m + logf(sum);
        atomicAdd(&g_zsum, (double)lse * (double)lse);
        float ent = 0.f;
        #pragma unroll
        for (int e = 0; e < 4; e++) ent -= p[e] * logf(p[e] + 1e-9f);
        atomicAdd(&g_entsum, (double)ent);
    }
}

__global__ void offsets_kernel() {
    if (threadIdx.x == 0 && blockIdx.x == 0) {
        int off = 0;
        for (int e = 0; e < E; e++) {
            g_segstart[e] = off;
            int padded = (g_counts[e] + 127) & ~127;
            for (int i = 0; i < padded / 128; i++)
                g_tileExpert[off / 128 + i] = e;
            off += padded;
        }
    }
}

__global__ void assign_kernel(const float* __restrict__ h2) {
    int t = blockIdx.x;
    __shared__ int slot_s;
    if (threadIdx.x == 0) {
        int e = g_expert[t];
        int slot = g_segstart[e] + atomicAdd(&g_cursor[e], 1);
        g_tokenOfRow[slot] = t;
        slot_s = slot;
    }
    __syncthreads();
    int s = slot_s;
    float4 v = ((const float4*)(h2 + (size_t)t * C))[threadIdx.x];
    __nv_bfloat16 h0,l0,h1,l1,h2b,l2,h3,l3;
    bsplit(v.x,h0,l0); bsplit(v.y,h1,l1); bsplit(v.z,h2b,l2); bsplit(v.w,h3,l3);
    __nv_bfloat162* hp = (__nv_bfloat162*)(g_h2g_hi + (size_t)s * C);
    __nv_bfloat162* lp = (__nv_bfloat162*)(g_h2g_lo + (size_t)s * C);
    hp[threadIdx.x*2]   = __nv_bfloat162(h0, h1);
    hp[threadIdx.x*2+1] = __nv_bfloat162(h2b, h3);
    lp[threadIdx.x*2]   = __nv_bfloat162(l0, l1);
    lp[threadIdx.x*2+1] = __nv_bfloat162(l2, l3);
}

__global__ void scatter_kernel(const float* __restrict__ x2, float* __restrict__ out) {
    int r = blockIdx.x;
    int t = g_tokenOfRow[r];
    if (t < 0) return;
    float4 a = ((const float4*)(x2 + (size_t)t * C))[threadIdx.x];
    float4 b = ((const float4*)(g_outg + (size_t)r * C))[threadIdx.x];
    ((float4*)(out + (size_t)t * C))[threadIdx.x] =
        make_float4(a.x + b.x, a.y + b.y, a.z + b.z, a.w + b.w);
}

__global__ void scalars_kernel(float* __restrict__ out) {
    if (threadIdx.x == 0 && blockIdx.x == 0) {
        const double NTOK = (double)BT;
        double aux = 0.0;
        for (int e = 0; e < E; e++) {
            double actual = (double)g_counts[e] / NTOK;
            double expd   = g_expsum[e] / NTOK;
            aux += actual * expd;
        }
        size_t base = (size_t)BT * C;
        out[base + 0] = (float)((double)E * aux);
        out[base + 1] = (float)(g_zsum / NTOK);
        out[base + 2] = (float)((g_entsum / NTOK) / log((double)E));
        for (int e = 0; e < E; e++)
            out[base + 3 + e] = (float)((double)g_counts[e] / NTOK);
    }
}

// ======================= launch =======================
static void* sym(const void* s) { void* p = nullptr; cudaGetSymbolAddress(&p, s); return p; }

extern "C" void kernel_launch(void* const* d_in, const int* in_sizes, int n_in,
                              void* d_out, int out_size)
{
    const float* x     = (const float*)d_in[0];
    const float* Wq    = (const float*)d_in[1];
    const float* Wk    = (const float*)d_in[2];
    const float* Wv    = (const float*)d_in[3];
    const float* Wo    = (const float*)d_in[4];
    const float* Wr    = (const float*)d_in[5];
    const float* Wfc   = (const float*)d_in[6];
    const float* Wproj = (const float*)d_in[7];
    float* out = (float*)d_out;

    static bool attr_set = false;
    if (!attr_set) {
        cudaFuncSetAttribute(gemm_bf16x3, cudaFuncAttributeMaxDynamicSharedMemorySize, SMEM_GEMM_BYTES);
        cudaFuncSetAttribute(attn_mma_kernel, cudaFuncAttributeMaxDynamicSharedMemorySize, ATT_SMEM);
        attr_set = true;
    }

    __nv_bfloat16* h1h = (__nv_bfloat16*)sym(g_h1_hi);
    __nv_bfloat16* h1l = (__nv_bfloat16*)sym(g_h1_lo);
    float* qb = (float*)sym(g_q);
    float* kb = (float*)sym(g_k);
    __nv_bfloat16* qh = (__nv_bfloat16*)sym(g_qhi); __nv_bfloat16* ql = (__nv_bfloat16*)sym(g_qlo);
    __nv_bfloat16* kh = (__nv_bfloat16*)sym(g_khi); __nv_bfloat16* kl = (__nv_bfloat16*)sym(g_klo);
    __nv_bfloat16* vh = (__nv_bfloat16*)sym(g_vhi); __nv_bfloat16* vl = (__nv_bfloat16*)sym(g_vlo);
    __nv_bfloat16* yh = (__nv_bfloat16*)sym(g_y_hi);
    __nv_bfloat16* yl = (__nv_bfloat16*)sym(g_y_lo);
    float* x2 = (float*)sym(g_x2);
    float* h2 = (float*)sym(g_h2);
    __nv_bfloat16* h2gh = (__nv_bfloat16*)sym(g_h2g_hi);
    __nv_bfloat16* h2gl = (__nv_bfloat16*)sym(g_h2g_lo);
    __nv_bfloat16* hidh = (__nv_bfloat16*)sym(g_hid_hi);
    __nv_bfloat16* hidl = (__nv_bfloat16*)sym(g_hid_lo);
    float* outg = (float*)sym(g_outg);
    __nv_bfloat16* wqh = (__nv_bfloat16*)sym(g_wq_hi); __nv_bfloat16* wql = (__nv_bfloat16*)sym(g_wq_lo);
    __nv_bfloat16* wkh = (__nv_bfloat16*)sym(g_wk_hi); __nv_bfloat16* wkl = (__nv_bfloat16*)sym(g_wk_lo);
    __nv_bfloat16* wvh = (__nv_bfloat16*)sym(g_wv_hi); __nv_bfloat16* wvl = (__nv_bfloat16*)sym(g_wv_lo);
    __nv_bfloat16* woh = (__nv_bfloat16*)sym(g_wo_hi); __nv_bfloat16* wol = (__nv_bfloat16*)sym(g_wo_lo);
    __nv_bfloat16* wfh = (__nv_bfloat16*)sym(g_wfc_hi); __nv_bfloat16* wfl = (__nv_bfloat16*)sym(g_wfc_lo);
    __nv_bfloat16* wph = (__nv_bfloat16*)sym(g_wpj_hi); __nv_bfloat16* wpl = (__nv_bfloat16*)sym(g_wpj_lo);
    int* tileE = (int*)sym(g_tileExpert);

    dim3 gq(C / 128, BT / 128);

    reset_kernel<<<(GROUP_CAP + 255) / 256, 256>>>();                        // 1
    wconv_kernel<<<dim3(C/64, C/64, 1), 256>>>(Wq, wqh, wql, C, C);          // 2
    wconv_kernel<<<dim3(C/64, C/64, 1), 256>>>(Wk, wkh, wkl, C, C);          // 3
    wconv_kernel<<<dim3(C/64, C/64, 1), 256>>>(Wv, wvh, wvl, C, C);          // 4
    rmsnorm_kernel<<<BT, 256>>>(x, nullptr, h1h, h1l);                       // 5
    gemm_bf16x3<<<gq, 256, SMEM_GEMM_BYTES>>>(h1h, h1l, wqh, wql, 0, qb,     // 6
        nullptr, nullptr, nullptr, nullptr, C, C, 0);
    gemm_bf16x3<<<gq, 256, SMEM_GEMM_BYTES>>>(h1h, h1l, wkh, wkl, 0, kb,     // 7
        nullptr, nullptr, nullptr, nullptr, C, C, 0);
    gemm_bf16x3<<<gq, 256, SMEM_GEMM_BYTES>>>(h1h, h1l, wvh, wvl, 0,         // 8 (V -> bf16 pair)
        nullptr, vh, vl, nullptr, nullptr, C, C, 3);
    wconv_kernel<<<dim3(C/64,  C/64,  1), 256>>>(Wo,    woh, wol, C,  C);    // 9
    wconv_kernel<<<dim3(FF/64, C/64,  E), 256>>>(Wfc,   wfh, wfl, C,  FF);   // 10
    wconv_kernel<<<dim3(C/64,  FF/64, E), 256>>>(Wproj, wph, wpl, FF, C);    // 11
    qk_rope_kernel<<<BT, 512>>>(qb, kb, qh, ql, kh, kl);                     // 12
    attn_mma_kernel<<<dim3(T/128, Bq*H), 256, ATT_SMEM>>>(                   // 13
        qh, ql, kh, kl, vh, vl, yh, yl);
    gemm_bf16x3<<<gq, 256, SMEM_GEMM_BYTES>>>(yh, yl, woh, wol, 0, x2,       // 14
        nullptr, nullptr, x, nullptr, C, C, 1);
    rmsnorm_kernel<<<BT, 256>>>(x2, h2, nullptr, nullptr);                   // 15
    router_kernel<<<BT, 128>>>(h2, Wr);                                      // 16
    offsets_kernel<<<1, 32>>>();                                             // 17
    assign_kernel<<<BT, 256>>>(h2);                                          // 18
    zero_pad_kernel<<<GROUP_CAP, 256>>>();                                   // 19 (pad rows only)
    gemm_bf16x3<<<dim3(FF/128, NTILES), 256, SMEM_GEMM_BYTES>>>(             // 20
        h2gh, h2gl, wfh, wfl, (size_t)FF * C, nullptr, hidh, hidl, nullptr, tileE, FF, C, 2);
    gemm_bf16x3<<<dim3(C/128, NTILES), 256, SMEM_GEMM_BYTES>>>(              // 21
        hidh, hidl, wph, wpl, (size_t)C * FF, outg, nullptr, nullptr, nullptr, tileE, C, FF, 0);
    scatter_kernel<<<GROUP_CAP, 256>>>(x2, out);                             // 22
    scalars_kernel<<<1, 32>>>(out);                                          // 23
}

// round 7
// speedup vs baseline: 3.0032x; 1.0088x over previous
#include <cuda_runtime.h>
#include <cuda_bf16.h>
#include <cstdint>
#include <math.h>

#define Bq 2
#define T 2048
#define C 1024
#define H 16
#define D 64
#define E 4
#define BT (Bq*T)
#define FF (4*C)
#define GROUP_CAP (BT + E*128)
#define NTILES (GROUP_CAP/128)
#define EPS_RMS 1.1920929e-07f

#define SMEM_SWIZZLE_128B(b) ((b) ^ (((b) >> 3) & 0x70))

__device__ __forceinline__ uint32_t smem_to_u32(const void* p) {
    uint32_t a;
    asm("{ .reg .u64 t; cvta.to.shared.u64 t, %1; cvt.u32.u64 %0, t; }" : "=r"(a) : "l"(p));
    return a;
}
__device__ __forceinline__ void ldsm4(uint32_t* r, uint32_t addr) {
    asm volatile("ldmatrix.sync.aligned.m8n8.x4.shared.b16 {%0,%1,%2,%3}, [%4];"
                 : "=r"(r[0]), "=r"(r[1]), "=r"(r[2]), "=r"(r[3]) : "r"(addr));
}
__device__ __forceinline__ void ldsm4t(uint32_t* r, uint32_t addr) {
    asm volatile("ldmatrix.sync.aligned.m8n8.x4.trans.shared.b16 {%0,%1,%2,%3}, [%4];"
                 : "=r"(r[0]), "=r"(r[1]), "=r"(r[2]), "=r"(r[3]) : "r"(addr));
}
__device__ __forceinline__ void mma_bf16(float* c, const uint32_t* a, const uint32_t* b) {
    asm volatile("mma.sync.aligned.m16n8k16.row.col.f32.bf16.bf16.f32 "
        "{%0,%1,%2,%3}, {%4,%5,%6,%7}, {%8,%9}, {%0,%1,%2,%3};"
        : "+f"(c[0]), "+f"(c[1]), "+f"(c[2]), "+f"(c[3])
        : "r"(a[0]), "r"(a[1]), "r"(a[2]), "r"(a[3]), "r"(b[0]), "r"(b[1]));
}
__device__ __forceinline__ float ex2f(float x) {
    float y; asm("ex2.approx.ftz.f32 %0, %1;" : "=f"(y) : "f"(x)); return y;
}
#define CP16(s, g) asm volatile("cp.async.cg.shared.global [%0], [%1], 16;" \
                                :: "r"(s), "l"(g) : "memory")

// ======================= scratch (static device globals) =======================
__device__ __nv_bfloat16 g_h1_hi[BT*C], g_h1_lo[BT*C];
__device__ float g_qk[BT*2*C];                      // q cols [0,1024), k cols [1024,2048)
__device__ __nv_bfloat16 g_qhi[BT*C], g_qlo[BT*C];
__device__ __nv_bfloat16 g_khi[BT*C], g_klo[BT*C];
__device__ __nv_bfloat16 g_vhi[BT*C], g_vlo[BT*C];
__device__ __nv_bfloat16 g_y_hi[BT*C], g_y_lo[BT*C];
__device__ float g_x2[BT*C], g_h2[BT*C];
__device__ __nv_bfloat16 g_h2g_hi[GROUP_CAP*C], g_h2g_lo[GROUP_CAP*C];
__device__ __nv_bfloat16 g_hid_hi[(size_t)GROUP_CAP*FF], g_hid_lo[(size_t)GROUP_CAP*FF];
__device__ float g_outg[GROUP_CAP*C];
__device__ __nv_bfloat16 g_wqkv_hi[3*C*C], g_wqkv_lo[3*C*C];   // rows: [q 0..1023 | k | v]
__device__ __nv_bfloat16 g_wo_hi[C*C], g_wo_lo[C*C];
__device__ __nv_bfloat16 g_wfc_hi[(size_t)E*C*FF], g_wfc_lo[(size_t)E*C*FF];   // [E][FF,C]
__device__ __nv_bfloat16 g_wpj_hi[(size_t)E*FF*C], g_wpj_lo[(size_t)E*FF*C];   // [E][C,FF]
__device__ int   g_expert[BT];
__device__ int   g_counts[E];
__device__ int   g_cursor[E];
__device__ int   g_segstart[E];
__device__ int   g_tileExpert[NTILES];
__device__ int   g_tokenOfRow[GROUP_CAP];
__device__ double g_expsum[E];
__device__ double g_zsum;
__device__ double g_entsum;

__device__ __forceinline__ void bsplit(float v, __nv_bfloat16& h, __nv_bfloat16& l) {
    h = __float2bfloat16(v);
    l = __float2bfloat16(v - __bfloat162float(h));
}
__device__ __forceinline__ void packsplit(float v0, float v1, uint32_t& hi, uint32_t& lo) {
    __nv_bfloat16 h0, l0, h1, l1;
    bsplit(v0, h0, l0); bsplit(v1, h1, l1);
    __nv_bfloat162 hh(h0, h1), ll(l0, l1);
    hi = *reinterpret_cast<uint32_t*>(&hh);
    lo = *reinterpret_cast<uint32_t*>(&ll);
}

// ======================= small kernels =======================
__global__ void reset_kernel() {
    int i = blockIdx.x * blockDim.x + threadIdx.x;
    if (i < E) { g_counts[i] = 0; g_cursor[i] = 0; g_expsum[i] = 0.0; }
    if (i == 0) { g_zsum = 0.0; g_entsum = 0.0; }
    if (i < NTILES) g_tileExpert[i] = -1;
    if (i < GROUP_CAP) g_tokenOfRow[i] = -1;
}

__global__ void zero_pad_kernel() {
    int r = blockIdx.x;
    if (g_tokenOfRow[r] >= 0) return;
    uint2 z = make_uint2(0u, 0u);
    ((uint2*)(g_h2g_hi + (size_t)r * C))[threadIdx.x] = z;
    ((uint2*)(g_h2g_lo + (size_t)r * C))[threadIdx.x] = z;
}

// transpose + bf16-split weights: W [Kd, Nd] fp32 -> T [Nd, Kd] bf16 hi/lo
__global__ void __launch_bounds__(256) wconv_kernel(
    const float* __restrict__ W,
    __nv_bfloat16* __restrict__ Thi, __nv_bfloat16* __restrict__ Tlo,
    int Kd, int Nd) {
    __shared__ float tile[64][65];
    int b = blockIdx.z;
    const float* Wb = W + (size_t)b * Kd * Nd;
    __nv_bfloat16* Th = Thi + (size_t)b * Kd * Nd;
    __nv_bfloat16* Tl = Tlo + (size_t)b * Kd * Nd;
    int n0 = blockIdx.x * 64, k0 = blockIdx.y * 64;
    int tid = threadIdx.x;
    int lr = tid >> 4, lc = (tid & 15) * 4;
    #pragma unroll
    for (int i = 0; i < 4; i++) {
        int k = lr + i * 16;
        float4 v = *(const float4*)(Wb + (size_t)(k0 + k) * Nd + n0 + lc);
        tile[k][lc] = v.x; tile[k][lc+1] = v.y; tile[k][lc+2] = v.z; tile[k][lc+3] = v.w;
    }
    __syncthreads();
    int wn = tid >> 4, wk = (tid & 15) * 4;
    #pragma unroll
    for (int i = 0; i < 4; i++) {
        int n = wn + i * 16;
        float v0 = tile[wk][n],   v1 = tile[wk+1][n];
        float v2 = tile[wk+2][n], v3 = tile[wk+3][n];
        uint32_t h01, l01, h23, l23;
        packsplit(v0, v1, h01, l01);
        packsplit(v2, v3, h23, l23);
        size_t o = (size_t)(n0 + n) * Kd + k0 + wk;
        *(uint2*)(Th + o) = make_uint2(h01, h23);
        *(uint2*)(Tl + o) = make_uint2(l01, l23);
    }
}

// RMSNorm over C -> bf16 hi/lo pair
__global__ void rmsnorm_kernel(const float* __restrict__ in,
                               __nv_bfloat16* __restrict__ ohi, __nv_bfloat16* __restrict__ olo) {
    int t = blockIdx.x;
    const float4* ip = (const float4*)(in + (size_t)t * C);
    __shared__ float red[8];
    float4 v = ip[threadIdx.x];
    float ss = v.x*v.x + v.y*v.y + v.z*v.z + v.w*v.w;
    #pragma unroll
    for (int o = 16; o; o >>= 1) ss += __shfl_xor_sync(0xffffffffu, ss, o);
    if ((threadIdx.x & 31) == 0) red[threadIdx.x >> 5] = ss;
    __syncthreads();
    if (threadIdx.x == 0) {
        float s = 0.f;
        #pragma unroll
        for (int w = 0; w < 8; w++) s += red[w];
        red[0] = s;
    }
    __syncthreads();
    float r = rsqrtf(red[0] / (float)C + EPS_RMS);
    float4 o = make_float4(v.x*r, v.y*r, v.z*r, v.w*r);
    __nv_bfloat16 h0,l0,h1,l1,h2,l2,h3,l3;
    bsplit(o.x,h0,l0); bsplit(o.y,h1,l1); bsplit(o.z,h2,l2); bsplit(o.w,h3,l3);
    __nv_bfloat162* hp = (__nv_bfloat162*)(ohi + (size_t)t * C);
    __nv_bfloat162* lp = (__nv_bfloat162*)(olo + (size_t)t * C);
    hp[threadIdx.x*2]   = __nv_bfloat162(h0, h1);
    hp[threadIdx.x*2+1] = __nv_bfloat162(h2, h3);
    lp[threadIdx.x*2]   = __nv_bfloat162(l0, l1);
    lp[threadIdx.x*2+1] = __nv_bfloat162(l2, l3);
}

// RMSNorm h2 = rmsnorm(x2) fp32 out, fused with router logits/softmax/argmax/aux stats
__global__ void rmsnorm_router_kernel(const float* __restrict__ in, float* __restrict__ outf,
                                      const float* __restrict__ Wr) {
    int t = blockIdx.x;
    const float4* ip = (const float4*)(in + (size_t)t * C);
    __shared__ float red[8];
    __shared__ float lred[32];
    float4 v = ip[threadIdx.x];
    float ss = v.x*v.x + v.y*v.y + v.z*v.z + v.w*v.w;
    #pragma unroll
    for (int o = 16; o; o >>= 1) ss += __shfl_xor_sync(0xffffffffu, ss, o);
    if ((threadIdx.x & 31) == 0) red[threadIdx.x >> 5] = ss;
    __syncthreads();
    if (threadIdx.x == 0) {
        float s = 0.f;
        #pragma unroll
        for (int w = 0; w < 8; w++) s += red[w];
        red[0] = s;
    }
    __syncthreads();
    float r = rsqrtf(red[0] / (float)C + EPS_RMS);
    float4 o = make_float4(v.x*r, v.y*r, v.z*r, v.w*r);
    ((float4*)(outf + (size_t)t * C))[threadIdx.x] = o;

    // router partial: channels c = threadIdx.x*4 .. +3, Wr is [C, E]
    int c0 = threadIdx.x * 4;
    float4 w0 = *(const float4*)(Wr + (size_t)(c0+0) * E);
    float4 w1 = *(const float4*)(Wr + (size_t)(c0+1) * E);
    float4 w2 = *(const float4*)(Wr + (size_t)(c0+2) * E);
    float4 w3 = *(const float4*)(Wr + (size_t)(c0+3) * E);
    float a0 = o.x*w0.x + o.y*w1.x + o.z*w2.x + o.w*w3.x;
    float a1 = o.x*w0.y + o.y*w1.y + o.z*w2.y + o.w*w3.y;
    float a2 = o.x*w0.z + o.y*w1.z + o.z*w2.z + o.w*w3.z;
    float a3 = o.x*w0.w + o.y*w1.w + o.z*w2.w + o.w*w3.w;
    #pragma unroll
    for (int off = 16; off; off >>= 1) {
        a0 += __shfl_xor_sync(0xffffffffu, a0, off);
        a1 += __shfl_xor_sync(0xffffffffu, a1, off);
        a2 += __shfl_xor_sync(0xffffffffu, a2, off);
        a3 += __shfl_xor_sync(0xffffffffu, a3, off);
    }
    if ((threadIdx.x & 31) == 0) {
        int w = threadIdx.x >> 5;
        lred[w*4+0] = a0; lred[w*4+1] = a1; lred[w*4+2] = a2; lred[w*4+3] = a3;
    }
    __syncthreads();
    if (threadIdx.x == 0) {
        float lg[4];
        #pragma unroll
        for (int e = 0; e < 4; e++) {
            float s = 0.f;
            #pragma unroll
            for (int w = 0; w < 8; w++) s += lred[w*4+e];
            lg[e] = s;
        }
        int arg = 0;
        #pragma unroll
        for (int e = 1; e < 4; e++) if (lg[e] > lg[arg]) arg = e;
        float m = fmaxf(fmaxf(lg[0], lg[1]), fmaxf(lg[2], lg[3]));
        float ez[4]; float sum = 0.f;
        #pragma unroll
        for (int e = 0; e < 4; e++) { ez[e] = expf(lg[e] - m); sum += ez[e]; }
        float p[4];
        #pragma unroll
        for (int e = 0; e < 4; e++) p[e] = ez[e] / sum;
        g_expert[t] = arg;
        atomicAdd(&g_counts[arg], 1);
        #pragma unroll
        for (int e = 0; e < 4; e++) atomicAdd(&g_expsum[e], (double)p[e]);
        float lse = m + logf(sum);
        atomicAdd(&g_zsum, (double)lse * (double)lse);
        float ent = 0.f;
        #pragma unroll
        for (int e = 0; e < 4; e++) ent -= p[e] * logf(p[e] + 1e-9f);
        atomicAdd(&g_entsum, (double)ent);
    }
}

// per-head RMSNorm + RoPE; reads qk buffer [BT, 2048]; writes bf16 hi/lo
__global__ void qk_rope_kernel(const float* __restrict__ qk,
                               __nv_bfloat16* __restrict__ qhi, __nv_bfloat16* __restrict__ qlo,
                               __nv_bfloat16* __restrict__ khi, __nv_bfloat16* __restrict__ klo) {
    int tok  = blockIdx.x;
    int head = threadIdx.x >> 5;
    int lane = threadIdx.x & 31;
    int tpos = tok % T;
    float ex  = (float)(2 * lane) / 64.0f;
    float inv = 1.0f / powf(10000.0f, ex);
    float ang = (float)tpos * inv;
    float c = cosf(ang), s = sinf(ang);
    size_t obase = (size_t)tok * C + head * D;
    #pragma unroll
    for (int m = 0; m < 2; m++) {
        const float* src = qk + (size_t)tok * 2048 + m * 1024 + head * D;
        __nv_bfloat16* dh = (m == 0 ? qhi : khi) + obase;
        __nv_bfloat16* dl = (m == 0 ? qlo : klo) + obase;
        float x1 = src[lane], x2 = src[lane + 32];
        float ss = x1*x1 + x2*x2;
        #pragma unroll
        for (int o = 16; o; o >>= 1) ss += __shfl_xor_sync(0xffffffffu, ss, o);
        float r = rsqrtf(ss / (float)D + EPS_RMS);
        x1 *= r; x2 *= r;
        float o1 =  x1 * c + x2 * s;
        float o2 = -x1 * s + x2 * c;
        __nv_bfloat16 h, l;
        bsplit(o1, h, l); dh[lane] = h;      dl[lane] = l;
        bsplit(o2, h, l); dh[lane + 32] = h; dl[lane + 32] = l;
    }
}

// ======================= HMMA flash attention (bf16x3) =======================
#define AT_QHI 0
#define AT_QLO 16384
#define AT_STG 32768
#define AT_STGSZ 32768
#define AT_KHI 0
#define AT_KLO 8192
#define AT_VHI 16384
#define AT_VLO 24576
#define ATT_SMEM (32768 + 2*32768)

__global__ void __launch_bounds__(256) attn_mma_kernel(
    const __nv_bfloat16* __restrict__ qhi, const __nv_bfloat16* __restrict__ qlo,
    const __nv_bfloat16* __restrict__ khi, const __nv_bfloat16* __restrict__ klo,
    const __nv_bfloat16* __restrict__ vhi, const __nv_bfloat16* __restrict__ vlo,
    __nv_bfloat16* __restrict__ yhi, __nv_bfloat16* __restrict__ ylo)
{
    extern __shared__ __align__(1024) char smem[];
    uint32_t sb = smem_to_u32(smem);
    int bh = blockIdx.y;
    int b = bh / H, hh = bh % H;
    int qb = blockIdx.x;
    int q0 = qb * 128;
    int tid = threadIdx.x, wid = tid >> 5, lid = tid & 31;
    int nkt = 2 * qb + 2;

    #pragma unroll
    for (int i = 0; i < 4; i++) {
        int lin = tid + i * 256;
        int r = lin >> 3, ch = lin & 7;
        uint32_t so = SMEM_SWIZZLE_128B((uint32_t)(r * 128 + ch * 16));
        size_t g = (size_t)(b*T + q0 + r) * C + hh * D + ch * 8;
        CP16(sb + AT_QHI + so, qhi + g);
        CP16(sb + AT_QLO + so, qlo + g);
    }
    asm volatile("cp.async.commit_group;" ::: "memory");
    #pragma unroll
    for (int i = 0; i < 2; i++) {
        int lin = tid + i * 256;
        int r = lin >> 3, ch = lin & 7;
        uint32_t so = SMEM_SWIZZLE_128B((uint32_t)(r * 128 + ch * 16));
        size_t g = (size_t)(b*T + r) * C + hh * D + ch * 8;
        uint32_t st = sb + AT_STG;
        CP16(st + AT_KHI + so, khi + g);
        CP16(st + AT_KLO + so, klo + g);
        CP16(st + AT_VHI + so, vhi + g);
        CP16(st + AT_VLO + so, vlo + g);
    }
    asm volatile("cp.async.commit_group;" ::: "memory");

    uint32_t qa_hi[4][4], qa_lo[4][4];
    float oac[8][4];
    #pragma unroll
    for (int j = 0; j < 8; j++)
        #pragma unroll
        for (int r = 0; r < 4; r++) oac[j][r] = 0.f;
    float m0 = -1e30f, m1 = -1e30f, l0 = 0.f, l1 = 0.f;

    int off = lid & 7, part = lid >> 3;
    int qr = lid >> 2, qc = (lid & 3) * 2;
    const float SC2 = 0.18033688011112042f;   // 0.125 * log2(e)

    for (int kt = 0; kt < nkt; kt++) {
        if (kt + 1 < nkt) {
            #pragma unroll
            for (int i = 0; i < 2; i++) {
                int lin = tid + i * 256;
                int r = lin >> 3, ch = lin & 7;
                uint32_t so = SMEM_SWIZZLE_128B((uint32_t)(r * 128 + ch * 16));
                size_t g = (size_t)(b*T + (kt + 1) * 64 + r) * C + hh * D + ch * 8;
                uint32_t st = sb + AT_STG + (uint32_t)((kt + 1) & 1) * AT_STGSZ;
                CP16(st + AT_KHI + so, khi + g);
                CP16(st + AT_KLO + so, klo + g);
                CP16(st + AT_VHI + so, vhi + g);
                CP16(st + AT_VLO + so, vlo + g);
            }
            asm volatile("cp.async.commit_group;" ::: "memory");
            asm volatile("cp.async.wait_group 1;" ::: "memory");
        } else {
            asm volatile("cp.async.wait_group 0;" ::: "memory");
        }
        __syncthreads();

        if (kt == 0) {
            #pragma unroll
            for (int kk = 0; kk < 4; kk++) {
                int row = wid * 16 + (part & 1) * 8 + off;
                int colb = kk * 32 + (part & 2) * 8;
                uint32_t so = SMEM_SWIZZLE_128B((uint32_t)(row * 128 + colb));
                ldsm4(qa_hi[kk], sb + AT_QHI + so);
                ldsm4(qa_lo[kk], sb + AT_QLO + so);
            }
        }

        uint32_t st = sb + AT_STG + (uint32_t)(kt & 1) * AT_STGSZ;

        float s[8][4];
        #pragma unroll
        for (int j = 0; j < 8; j++)
            #pragma unroll
            for (int r = 0; r < 4; r++) s[j][r] = 0.f;
        #pragma unroll
        for (int kk = 0; kk < 4; kk++) {
            #pragma unroll
            for (int jj = 0; jj < 4; jj++) {
                int row = jj * 16 + (part & 2) * 4 + off;
                int colb = kk * 32 + (part & 1) * 16;
                uint32_t so = SMEM_SWIZZLE_128B((uint32_t)(row * 128 + colb));
                uint32_t kh[4], kl[4];
                ldsm4(kh, st + AT_KHI + so);
                ldsm4(kl, st + AT_KLO + so);
                mma_bf16(s[2*jj],     qa_hi[kk], kh);
                mma_bf16(s[2*jj],     qa_hi[kk], kl);
                mma_bf16(s[2*jj],     qa_lo[kk], kh);
                mma_bf16(s[2*jj+1],   qa_hi[kk], kh + 2);
                mma_bf16(s[2*jj+1],   qa_hi[kk], kl + 2);
                mma_bf16(s[2*jj+1],   qa_lo[kk], kh + 2);
            }
        }

        bool domask = (kt >= nkt - 2);
        #pragma unroll
        for (int j = 0; j < 8; j++) {
            #pragma unroll
            for (int r = 0; r < 4; r++) {
                float v = s[j][r] * SC2;
                if (domask) {
                    int key = kt * 64 + j * 8 + qc + (r & 1);
                    int row = q0 + wid * 16 + qr + (r & 2) * 4;
                    if (key > row) v = -1e30f;
                }
                s[j][r] = v;
            }
        }

        float mx0 = -1e30f, mx1 = -1e30f;
        #pragma unroll
        for (int j = 0; j < 8; j++) {
            mx0 = fmaxf(mx0, fmaxf(s[j][0], s[j][1]));
            mx1 = fmaxf(mx1, fmaxf(s[j][2], s[j][3]));
        }
        mx0 = fmaxf(mx0, __shfl_xor_sync(0xffffffffu, mx0, 1));
        mx0 = fmaxf(mx0, __shfl_xor_sync(0xffffffffu, mx0, 2));
        mx1 = fmaxf(mx1, __shfl_xor_sync(0xffffffffu, mx1, 1));
        mx1 = fmaxf(mx1, __shfl_xor_sync(0xffffffffu, mx1, 2));
        float mn0 = fmaxf(m0, mx0), mn1 = fmaxf(m1, mx1);
        float al0 = ex2f(m0 - mn0), al1 = ex2f(m1 - mn1);
        float sm0 = 0.f, sm1 = 0.f;
        #pragma unroll
        for (int j = 0; j < 8; j++) {
            s[j][0] = ex2f(s[j][0] - mn0); sm0 += s[j][0];
            s[j][1] = ex2f(s[j][1] - mn0); sm0 += s[j][1];
            s[j][2] = ex2f(s[j][2] - mn1); sm1 += s[j][2];
            s[j][3] = ex2f(s[j][3] - mn1); sm1 += s[j][3];
        }
        sm0 += __shfl_xor_sync(0xffffffffu, sm0, 1);
        sm0 += __shfl_xor_sync(0xffffffffu, sm0, 2);
        sm1 += __shfl_xor_sync(0xffffffffu, sm1, 1);
        sm1 += __shfl_xor_sync(0xffffffffu, sm1, 2);
        l0 = l0 * al0 + sm0;  l1 = l1 * al1 + sm1;
        m0 = mn0;  m1 = mn1;
        #pragma unroll
        for (int j = 0; j < 8; j++) {
            oac[j][0] *= al0; oac[j][1] *= al0;
            oac[j][2] *= al1; oac[j][3] *= al1;
        }

        #pragma unroll
        for (int kk = 0; kk < 4; kk++) {
            uint32_t pah[4], pal[4];
            packsplit(s[2*kk][0],   s[2*kk][1],   pah[0], pal[0]);
            packsplit(s[2*kk][2],   s[2*kk][3],   pah[1], pal[1]);
            packsplit(s[2*kk+1][0], s[2*kk+1][1], pah[2], pal[2]);
            packsplit(s[2*kk+1][2], s[2*kk+1][3], pah[3], pal[3]);
            #pragma unroll
            for (int jj = 0; jj < 4; jj++) {
                int row = kk * 16 + (part & 1) * 8 + off;
                int colb = jj * 32 + (part & 2) * 8;
                uint32_t so = SMEM_SWIZZLE_128B((uint32_t)(row * 128 + colb));
                uint32_t vh[4], vl[4];
                ldsm4t(vh, st + AT_VHI + so);
                ldsm4t(vl, st + AT_VLO + so);
                mma_bf16(oac[2*jj],   pah, vh);
                mma_bf16(oac[2*jj],   pah, vl);
                mma_bf16(oac[2*jj],   pal, vh);
                mma_bf16(oac[2*jj+1], pah, vh + 2);
                mma_bf16(oac[2*jj+1], pah, vl + 2);
                mma_bf16(oac[2*jj+1], pal, vh + 2);
            }
        }
        __syncthreads();
    }

    float inv0 = 1.f / l0, inv1 = 1.f / l1;
    #pragma unroll
    for (int j = 0; j < 8; j++) {
        size_t i0 = (size_t)(b*T + q0 + wid*16 + qr) * C + hh * D + j * 8 + qc;
        size_t i1 = (size_t)(b*T + q0 + wid*16 + qr + 8) * C + hh * D + j * 8 + qc;
        uint32_t ph, pl;
        packsplit(oac[j][0] * inv0, oac[j][1] * inv0, ph, pl);
        *(uint32_t*)(yhi + i0) = ph;  *(uint32_t*)(ylo + i0) = pl;
        packsplit(oac[j][2] * inv1, oac[j][3] * inv1, ph, pl);
        *(uint32_t*)(yhi + i1) = ph;  *(uint32_t*)(ylo + i1) = pl;
    }
}

// ======================= HMMA bf16x3 GEMM =======================
// epi: 0 fp32; 1 fp32+resid; 2 relu(acc)^2 -> bf16 pair; 3 acc -> bf16 pair;
//      4 fused QKV: cols [0,2048) -> fp32 Cout stride 2048, cols [2048,3072) -> bf16 pair stride 1024
#define KTILE 64
#define OFF_AH 0
#define OFF_AL 16384
#define OFF_BH 32768
#define OFF_BL 49152
#define STAGE_BYTES 65536
#define SMEM_GEMM_BYTES (2*STAGE_BYTES)

__global__ void __launch_bounds__(256) gemm_bf16x3(
    const __nv_bfloat16* __restrict__ Ahi, const __nv_bfloat16* __restrict__ Alo,
    const __nv_bfloat16* __restrict__ Bhi, const __nv_bfloat16* __restrict__ Blo,
    size_t bstride,
    float* __restrict__ Cout,
    __nv_bfloat16* __restrict__ Ohi, __nv_bfloat16* __restrict__ Olo,
    const float* __restrict__ resid,
    const int* __restrict__ tileExpert,
    int N, int K, int epi)
{
    extern __shared__ __align__(1024) char smem[];
    int by = blockIdx.y, bx = blockIdx.x;
    int e = 0;
    if (tileExpert) { e = tileExpert[by]; if (e < 0) return; }
    const __nv_bfloat16* Bh = Bhi + (size_t)e * bstride;
    const __nv_bfloat16* Bl = Blo + (size_t)e * bstride;

    uint32_t sb = smem_to_u32(smem);
    int tid = threadIdx.x, wid = tid >> 5, lid = tid & 31;
    int wm = wid & 1, wn = wid >> 1;
    int row0 = by * 128, col0 = bx * 128;
    int nkt = K / KTILE;

    float acc[4][4][4];
    #pragma unroll
    for (int i = 0; i < 4; i++)
        #pragma unroll
        for (int j = 0; j < 4; j++)
            #pragma unroll
            for (int r = 0; r < 4; r++) acc[i][j][r] = 0.f;

    int lr = tid >> 3, lc = tid & 7;

    {
        #pragma unroll
        for (int i = 0; i < 4; i++) {
            int r = lr + i * 32;
            uint32_t so = SMEM_SWIZZLE_128B((uint32_t)(r * 128 + lc * 16));
            size_t ga = (size_t)(row0 + r) * K + lc * 8;
            size_t gb = (size_t)(col0 + r) * K + lc * 8;
            CP16(sb + OFF_AH + so, Ahi + ga);
            CP16(sb + OFF_AL + so, Alo + ga);
            CP16(sb + OFF_BH + so, Bh + gb);
            CP16(sb + OFF_BL + so, Bl + gb);
        }
        asm volatile("cp.async.commit_group;" ::: "memory");
    }

    for (int kt = 0; kt < nkt; kt++) {
        uint32_t cur = (uint32_t)(kt & 1) * STAGE_BYTES;
        if (kt + 1 < nkt) {
            uint32_t nxt = (uint32_t)((kt + 1) & 1) * STAGE_BYTES;
            int k0 = (kt + 1) * KTILE;
            #pragma unroll
            for (int i = 0; i < 4; i++) {
                int r = lr + i * 32;
                uint32_t so = SMEM_SWIZZLE_128B((uint32_t)(r * 128 + lc * 16));
                size_t ga = (size_t)(row0 + r) * K + k0 + lc * 8;
                size_t gb = (size_t)(col0 + r) * K + k0 + lc * 8;
                CP16(sb + nxt + OFF_AH + so, Ahi + ga);
                CP16(sb + nxt + OFF_AL + so, Alo + ga);
                CP16(sb + nxt + OFF_BH + so, Bh + gb);
                CP16(sb + nxt + OFF_BL + so, Bl + gb);
            }
            asm volatile("cp.async.commit_group;" ::: "memory");
            asm volatile("cp.async.wait_group 1;" ::: "memory");
        } else {
            asm volatile("cp.async.wait_group 0;" ::: "memory");
        }
        __syncthreads();

        uint32_t sAH = sb + cur + OFF_AH, sAL = sb + cur + OFF_AL;
        uint32_t sBH = sb + cur + OFF_BH, sBL = sb + cur + OFF_BL;
        #pragma unroll
        for (int kk = 0; kk < 4; kk++) {
            int colb = (kk * 16 + (lid >> 4) * 8) * 2;
            uint32_t a_hi[4][4], a_lo[4][4];
            #pragma unroll
            for (int mf = 0; mf < 4; mf++) {
                int rowm = wm * 64 + mf * 16 + (lid & 15);
                uint32_t so = SMEM_SWIZZLE_128B((uint32_t)(rowm * 128 + colb));
                ldsm4(a_hi[mf], sAH + so);
                ldsm4(a_lo[mf], sAL + so);
            }
            uint32_t b_hi[4][2], b_lo[4][2];
            #pragma unroll
            for (int g = 0; g < 2; g++) {
                int rown = wn * 32 + g * 16 + (lid & 15);
                uint32_t so = SMEM_SWIZZLE_128B((uint32_t)(rown * 128 + colb));
                uint32_t r4[4];
                ldsm4(r4, sBH + so);
                b_hi[2*g][0] = r4[0]; b_hi[2*g+1][0] = r4[1];
                b_hi[2*g][1] = r4[2]; b_hi[2*g+1][1] = r4[3];
                ldsm4(r4, sBL + so);
                b_lo[2*g][0] = r4[0]; b_lo[2*g+1][0] = r4[1];
                b_lo[2*g][1] = r4[2]; b_lo[2*g+1][1] = r4[3];
            }
            #pragma unroll
            for (int mf = 0; mf < 4; mf++)
                #pragma unroll
                for (int nf = 0; nf < 4; nf++) {
                    mma_bf16(acc[mf][nf], a_hi[mf], b_hi[nf]);
                    mma_bf16(acc[mf][nf], a_hi[mf], b_lo[nf]);
                    mma_bf16(acc[mf][nf], a_lo[mf], b_hi[nf]);
                }
        }
        __syncthreads();
    }

    int qr = lid >> 2, qc = (lid & 3) * 2;
    #pragma unroll
    for (int mf = 0; mf < 4; mf++) {
        #pragma unroll
        for (int nf = 0; nf < 4; nf++) {
            float* cc = acc[mf][nf];
            int col = col0 + wn * 32 + nf * 8 + qc;
            #pragma unroll
            for (int half = 0; half < 2; half++) {
                int row = row0 + wm * 64 + mf * 16 + qr + half * 8;
                float v0 = cc[2*half], v1 = cc[2*half + 1];
                if (epi == 0) {
                    size_t idx = (size_t)row * N + col;
                    *(float2*)(Cout + idx) = make_float2(v0, v1);
                } else if (epi == 1) {
                    size_t idx = (size_t)row * N + col;
                    float2 rr = *(const float2*)(resid + idx);
                    *(float2*)(Cout + idx) = make_float2(v0 + rr.x, v1 + rr.y);
                } else if (epi == 4) {
                    if (col < 2048) {
                        size_t idx = (size_t)row * 2048 + col;
                        *(float2*)(Cout + idx) = make_float2(v0, v1);
                    } else {
                        size_t idx = (size_t)row * 1024 + (col - 2048);
                        uint32_t ph, pl;
                        packsplit(v0, v1, ph, pl);
                        *(uint32_t*)(Ohi + idx) = ph;
                        *(uint32_t*)(Olo + idx) = pl;
                    }
                } else {
                    if (epi == 2) {
                        v0 = fmaxf(v0, 0.f); v0 *= v0;
                        v1 = fmaxf(v1, 0.f); v1 *= v1;
                    }
                    size_t idx = (size_t)row * N + col;
                    uint32_t ph, pl;
                    packsplit(v0, v1, ph, pl);
                    *(uint32_t*)(Ohi + idx) = ph;
                    *(uint32_t*)(Olo + idx) = pl;
                }
            }
        }
    }
}

// ======================= grouping / scatter / scalars =======================
__global__ void offsets_kernel() {
    if (threadIdx.x == 0 && blockIdx.x == 0) {
        int off = 0;
        for (int e = 0; e < E; e++) {
            g_segstart[e] = off;
            int padded = (g_counts[e] + 127) & ~127;
            for (int i = 0; i < padded / 128; i++)
                g_tileExpert[off / 128 + i] = e;
            off += padded;
        }
    }
}

__global__ void assign_kernel(const float* __restrict__ h2) {
    int t = blockIdx.x;
    __shared__ int slot_s;
    if (threadIdx.x == 0) {
        int e = g_expert[t];
        int slot = g_segstart[e] + atomicAdd(&g_cursor[e], 1);
        g_tokenOfRow[slot] = t;
        slot_s = slot;
    }
    __syncthreads();
    int s = slot_s;
    float4 v = ((const float4*)(h2 + (size_t)t * C))[threadIdx.x];
    __nv_bfloat16 h0,l0,h1,l1,h2b,l2,h3,l3;
    bsplit(v.x,h0,l0); bsplit(v.y,h1,l1); bsplit(v.z,h2b,l2); bsplit(v.w,h3,l3);
    __nv_bfloat162* hp = (__nv_bfloat162*)(g_h2g_hi + (size_t)s * C);
    __nv_bfloat162* lp = (__nv_bfloat162*)(g_h2g_lo + (size_t)s * C);
    hp[threadIdx.x*2]   = __nv_bfloat162(h0, h1);
    hp[threadIdx.x*2+1] = __nv_bfloat162(h2b, h3);
    lp[threadIdx.x*2]   = __nv_bfloat162(l0, l1);
    lp[threadIdx.x*2+1] = __nv_bfloat162(l2, l3);
}

__global__ void scatter_kernel(const float* __restrict__ x2, float* __restrict__ out) {
    int r = blockIdx.x;
    int t = g_tokenOfRow[r];
    if (t < 0) return;
    float4 a = ((const float4*)(x2 + (size_t)t * C))[threadIdx.x];
    float4 b = ((const float4*)(g_outg + (size_t)r * C))[threadIdx.x];
    ((float4*)(out + (size_t)t * C))[threadIdx.x] =
        make_float4(a.x + b.x, a.y + b.y, a.z + b.z, a.w + b.w);
}

__global__ void scalars_kernel(float* __restrict__ out) {
    if (threadIdx.x == 0 && blockIdx.x == 0) {
        const double NTOK = (double)BT;
        double aux = 0.0;
        for (int e = 0; e < E; e++) {
            double actual = (double)g_counts[e] / NTOK;
            double expd   = g_expsum[e] / NTOK;
            aux += actual * expd;
        }
        size_t base = (size_t)BT * C;
        out[base + 0] = (float)((double)E * aux);
        out[base + 1] = (float)(g_zsum / NTOK);
        out[base + 2] = (float)((g_entsum / NTOK) / log((double)E));
        for (int e = 0; e < E; e++)
            out[base + 3 + e] = (float)((double)g_counts[e] / NTOK);
    }
}

// ======================= launch =======================
static void* sym(const void* s) { void* p = nullptr; cudaGetSymbolAddress(&p, s); return p; }

extern "C" void kernel_launch(void* const* d_in, const int* in_sizes, int n_in,
                              void* d_out, int out_size)
{
    const float* x     = (const float*)d_in[0];
    const float* Wq    = (const float*)d_in[1];
    const float* Wk    = (const float*)d_in[2];
    const float* Wv    = (const float*)d_in[3];
    const float* Wo    = (const float*)d_in[4];
    const float* Wr    = (const float*)d_in[5];
    const float* Wfc   = (const float*)d_in[6];
    const float* Wproj = (const float*)d_in[7];
    float* out = (float*)d_out;

    static bool attr_set = false;
    if (!attr_set) {
        cudaFuncSetAttribute(gemm_bf16x3, cudaFuncAttributeMaxDynamicSharedMemorySize, SMEM_GEMM_BYTES);
        cudaFuncSetAttribute(attn_mma_kernel, cudaFuncAttributeMaxDynamicSharedMemorySize, ATT_SMEM);
        attr_set = true;
    }

    __nv_bfloat16* h1h = (__nv_bfloat16*)sym(g_h1_hi);
    __nv_bfloat16* h1l = (__nv_bfloat16*)sym(g_h1_lo);
    float* qk = (float*)sym(g_qk);
    __nv_bfloat16* qh = (__nv_bfloat16*)sym(g_qhi); __nv_bfloat16* ql = (__nv_bfloat16*)sym(g_qlo);
    __nv_bfloat16* kh = (__nv_bfloat16*)sym(g_khi); __nv_bfloat16* kl = (__nv_bfloat16*)sym(g_klo);
    __nv_bfloat16* vh = (__nv_bfloat16*)sym(g_vhi); __nv_bfloat16* vl = (__nv_bfloat16*)sym(g_vlo);
    __nv_bfloat16* yh = (__nv_bfloat16*)sym(g_y_hi);
    __nv_bfloat16* yl = (__nv_bfloat16*)sym(g_y_lo);
    float* x2 = (float*)sym(g_x2);
    float* h2 = (float*)sym(g_h2);
    __nv_bfloat16* h2gh = (__nv_bfloat16*)sym(g_h2g_hi);
    __nv_bfloat16* h2gl = (__nv_bfloat16*)sym(g_h2g_lo);
    __nv_bfloat16* hidh = (__nv_bfloat16*)sym(g_hid_hi);
    __nv_bfloat16* hidl = (__nv_bfloat16*)sym(g_hid_lo);
    float* outg = (float*)sym(g_outg);
    __nv_bfloat16* wqkvh = (__nv_bfloat16*)sym(g_wqkv_hi);
    __nv_bfloat16* wqkvl = (__nv_bfloat16*)sym(g_wqkv_lo);
    __nv_bfloat16* woh = (__nv_bfloat16*)sym(g_wo_hi); __nv_bfloat16* wol = (__nv_bfloat16*)sym(g_wo_lo);
    __nv_bfloat16* wfh = (__nv_bfloat16*)sym(g_wfc_hi); __nv_bfloat16* wfl = (__nv_bfloat16*)sym(g_wfc_lo);
    __nv_bfloat16* wph = (__nv_bfloat16*)sym(g_wpj_hi); __nv_bfloat16* wpl = (__nv_bfloat16*)sym(g_wpj_lo);
    int* tileE = (int*)sym(g_tileExpert);

    reset_kernel<<<(GROUP_CAP + 255) / 256, 256>>>();                          // 1
    rmsnorm_kernel<<<BT, 256>>>(x, h1h, h1l);                                  // 2
    wconv_kernel<<<dim3(C/64, C/64, 1), 256>>>(Wq, wqkvh,         wqkvl,         C, C); // 3
    wconv_kernel<<<dim3(C/64, C/64, 1), 256>>>(Wk, wqkvh + C*C,   wqkvl + C*C,   C, C); // 4
    wconv_kernel<<<dim3(C/64, C/64, 1), 256>>>(Wv, wqkvh + 2*C*C, wqkvl + 2*C*C, C, C); // 5
    wconv_kernel<<<dim3(C/64,  C/64,  1), 256>>>(Wo,    woh, wol, C,  C);      // 6
    wconv_kernel<<<dim3(FF/64, C/64,  E), 256>>>(Wfc,   wfh, wfl, C,  FF);     // 7
    wconv_kernel<<<dim3(C/64,  FF/64, E), 256>>>(Wproj, wph, wpl, FF, C);      // 8
    // 9: fused QKV GEMM  <-- expected ncu capture slot
    gemm_bf16x3<<<dim3(3*C/128, BT/128), 256, SMEM_GEMM_BYTES>>>(
        h1h, h1l, wqkvh, wqkvl, 0, qk, vh, vl, nullptr, nullptr, 3*C, C, 4);
    qk_rope_kernel<<<BT, 512>>>(qk, qh, ql, kh, kl);                           // 10
    attn_mma_kernel<<<dim3(T/128, Bq*H), 256, ATT_SMEM>>>(                     // 11
        qh, ql, kh, kl, vh, vl, yh, yl);
    gemm_bf16x3<<<dim3(C/128, BT/128), 256, SMEM_GEMM_BYTES>>>(                // 12
        yh, yl, woh, wol, 0, x2, nullptr, nullptr, x, nullptr, C, C, 1);
    rmsnorm_router_kernel<<<BT, 256>>>(x2, h2, Wr);                            // 13
    offsets_kernel<<<1, 32>>>();                                               // 14
    assign_kernel<<<BT, 256>>>(h2);                                            // 15
    zero_pad_kernel<<<GROUP_CAP, 256>>>();                                     // 16
    gemm_bf16x3<<<dim3(FF/128, NTILES), 256, SMEM_GEMM_BYTES>>>(               // 17
        h2gh, h2gl, wfh, wfl, (size_t)FF * C, nullptr, hidh, hidl, nullptr, tileE, FF, C, 2);
    gemm_bf16x3<<<dim3(C/128, NTILES), 256, SMEM_GEMM_BYTES>>>(                // 18
        hidh, hidl, wph, wpl, (size_t)C * FF, outg, nullptr, nullptr, nullptr, tileE, C, FF, 0);
    scatter_kernel<<<GROUP_CAP, 256>>>(x2, out);                               // 19
    scalars_kernel<<<1, 32>>>(out);                                            // 20
}

// round 8
// speedup vs baseline: 3.0561x; 1.0176x over previous
#include <cuda_runtime.h>
#include <cuda_bf16.h>
#include <cstdint>
#include <math.h>

#define Bq 2
#define T 2048
#define C 1024
#define H 16
#define D 64
#define E 4
#define BT (Bq*T)
#define FF (4*C)
#define GROUP_CAP (BT + E*128)
#define NTILES (GROUP_CAP/128)
#define EPS_RMS 1.1920929e-07f

#define SMEM_SWIZZLE_128B(b) ((b) ^ (((b) >> 3) & 0x70))

__device__ __forceinline__ uint32_t smem_to_u32(const void* p) {
    uint32_t a;
    asm("{ .reg .u64 t; cvta.to.shared.u64 t, %1; cvt.u32.u64 %0, t; }" : "=r"(a) : "l"(p));
    return a;
}
__device__ __forceinline__ void ldsm4(uint32_t* r, uint32_t addr) {
    asm volatile("ldmatrix.sync.aligned.m8n8.x4.shared.b16 {%0,%1,%2,%3}, [%4];"
                 : "=r"(r[0]), "=r"(r[1]), "=r"(r[2]), "=r"(r[3]) : "r"(addr));
}
__device__ __forceinline__ void ldsm4t(uint32_t* r, uint32_t addr) {
    asm volatile("ldmatrix.sync.aligned.m8n8.x4.trans.shared.b16 {%0,%1,%2,%3}, [%4];"
                 : "=r"(r[0]), "=r"(r[1]), "=r"(r[2]), "=r"(r[3]) : "r"(addr));
}
__device__ __forceinline__ void mma_bf16(float* c, const uint32_t* a, const uint32_t* b) {
    asm volatile("mma.sync.aligned.m16n8k16.row.col.f32.bf16.bf16.f32 "
        "{%0,%1,%2,%3}, {%4,%5,%6,%7}, {%8,%9}, {%0,%1,%2,%3};"
        : "+f"(c[0]), "+f"(c[1]), "+f"(c[2]), "+f"(c[3])
        : "r"(a[0]), "r"(a[1]), "r"(a[2]), "r"(a[3]), "r"(b[0]), "r"(b[1]));
}
__device__ __forceinline__ float ex2f(float x) {
    float y; asm("ex2.approx.ftz.f32 %0, %1;" : "=f"(y) : "f"(x)); return y;
}
#define CP16(s, g) asm volatile("cp.async.cg.shared.global [%0], [%1], 16;" \
                                :: "r"(s), "l"(g) : "memory")

// ======================= scratch (static device globals) =======================
__device__ __nv_bfloat16 g_h1_hi[BT*C], g_h1_lo[BT*C];
__device__ float g_qk[BT*2*C];
__device__ __nv_bfloat16 g_qhi[BT*C], g_qlo[BT*C];
__device__ __nv_bfloat16 g_khi[BT*C], g_klo[BT*C];
__device__ __nv_bfloat16 g_vhi[BT*C], g_vlo[BT*C];
__device__ __nv_bfloat16 g_y_hi[BT*C], g_y_lo[BT*C];
__device__ float g_x2[BT*C], g_h2[BT*C];
__device__ __nv_bfloat16 g_h2g_hi[GROUP_CAP*C], g_h2g_lo[GROUP_CAP*C];
__device__ __nv_bfloat16 g_hid_hi[(size_t)GROUP_CAP*FF], g_hid_lo[(size_t)GROUP_CAP*FF];
__device__ float g_outg[GROUP_CAP*C];
__device__ __nv_bfloat16 g_wqkv_hi[3*C*C], g_wqkv_lo[3*C*C];
__device__ __nv_bfloat16 g_wo_hi[C*C], g_wo_lo[C*C];
__device__ __nv_bfloat16 g_wfc_hi[(size_t)E*C*FF], g_wfc_lo[(size_t)E*C*FF];
__device__ __nv_bfloat16 g_wpj_hi[(size_t)E*FF*C], g_wpj_lo[(size_t)E*FF*C];
__device__ int   g_expert[BT];
__device__ int   g_counts[E];
__device__ int   g_cursor[E];
__device__ int   g_segstart[E];
__device__ int   g_tileExpert[NTILES];
__device__ int   g_tokenOfRow[GROUP_CAP];
__device__ double g_expsum[E];
__device__ double g_zsum;
__device__ double g_entsum;

__device__ __forceinline__ void bsplit(float v, __nv_bfloat16& h, __nv_bfloat16& l) {
    h = __float2bfloat16(v);
    l = __float2bfloat16(v - __bfloat162float(h));
}
__device__ __forceinline__ void packsplit(float v0, float v1, uint32_t& hi, uint32_t& lo) {
    __nv_bfloat16 h0, l0, h1, l1;
    bsplit(v0, h0, l0); bsplit(v1, h1, l1);
    __nv_bfloat162 hh(h0, h1), ll(l0, l1);
    hi = *reinterpret_cast<uint32_t*>(&hh);
    lo = *reinterpret_cast<uint32_t*>(&ll);
}

// ======================= small kernels =======================
__global__ void reset_kernel() {
    int i = blockIdx.x * blockDim.x + threadIdx.x;
    if (i < E) { g_counts[i] = 0; g_cursor[i] = 0; g_expsum[i] = 0.0; }
    if (i == 0) { g_zsum = 0.0; g_entsum = 0.0; }
    if (i < NTILES) g_tileExpert[i] = -1;
    if (i < GROUP_CAP) g_tokenOfRow[i] = -1;
}

__global__ void zero_pad_kernel() {
    int r = blockIdx.x;
    if (g_tokenOfRow[r] >= 0) return;
    uint2 z = make_uint2(0u, 0u);
    ((uint2*)(g_h2g_hi + (size_t)r * C))[threadIdx.x] = z;
    ((uint2*)(g_h2g_lo + (size_t)r * C))[threadIdx.x] = z;
}

// transpose + bf16-split weights: W [Kd, Nd] fp32 -> T [Nd, Kd] bf16 hi/lo
__global__ void __launch_bounds__(256) wconv_kernel(
    const float* __restrict__ W,
    __nv_bfloat16* __restrict__ Thi, __nv_bfloat16* __restrict__ Tlo,
    int Kd, int Nd) {
    __shared__ float tile[64][65];
    int b = blockIdx.z;
    const float* Wb = W + (size_t)b * Kd * Nd;
    __nv_bfloat16* Th = Thi + (size_t)b * Kd * Nd;
    __nv_bfloat16* Tl = Tlo + (size_t)b * Kd * Nd;
    int n0 = blockIdx.x * 64, k0 = blockIdx.y * 64;
    int tid = threadIdx.x;
    int lr = tid >> 4, lc = (tid & 15) * 4;
    #pragma unroll
    for (int i = 0; i < 4; i++) {
        int k = lr + i * 16;
        float4 v = *(const float4*)(Wb + (size_t)(k0 + k) * Nd + n0 + lc);
        tile[k][lc] = v.x; tile[k][lc+1] = v.y; tile[k][lc+2] = v.z; tile[k][lc+3] = v.w;
    }
    __syncthreads();
    int wn = tid >> 4, wk = (tid & 15) * 4;
    #pragma unroll
    for (int i = 0; i < 4; i++) {
        int n = wn + i * 16;
        float v0 = tile[wk][n],   v1 = tile[wk+1][n];
        float v2 = tile[wk+2][n], v3 = tile[wk+3][n];
        uint32_t h01, l01, h23, l23;
        packsplit(v0, v1, h01, l01);
        packsplit(v2, v3, h23, l23);
        size_t o = (size_t)(n0 + n) * Kd + k0 + wk;
        *(uint2*)(Th + o) = make_uint2(h01, h23);
        *(uint2*)(Tl + o) = make_uint2(l01, l23);
    }
}

// RMSNorm over C -> bf16 hi/lo pair
__global__ void rmsnorm_kernel(const float* __restrict__ in,
                               __nv_bfloat16* __restrict__ ohi, __nv_bfloat16* __restrict__ olo) {
    int t = blockIdx.x;
    const float4* ip = (const float4*)(in + (size_t)t * C);
    __shared__ float red[8];
    float4 v = ip[threadIdx.x];
    float ss = v.x*v.x + v.y*v.y + v.z*v.z + v.w*v.w;
    #pragma unroll
    for (int o = 16; o; o >>= 1) ss += __shfl_xor_sync(0xffffffffu, ss, o);
    if ((threadIdx.x & 31) == 0) red[threadIdx.x >> 5] = ss;
    __syncthreads();
    if (threadIdx.x == 0) {
        float s = 0.f;
        #pragma unroll
        for (int w = 0; w < 8; w++) s += red[w];
        red[0] = s;
    }
    __syncthreads();
    float r = rsqrtf(red[0] / (float)C + EPS_RMS);
    float4 o = make_float4(v.x*r, v.y*r, v.z*r, v.w*r);
    __nv_bfloat16 h0,l0,h1,l1,h2,l2,h3,l3;
    bsplit(o.x,h0,l0); bsplit(o.y,h1,l1); bsplit(o.z,h2,l2); bsplit(o.w,h3,l3);
    __nv_bfloat162* hp = (__nv_bfloat162*)(ohi + (size_t)t * C);
    __nv_bfloat162* lp = (__nv_bfloat162*)(olo + (size_t)t * C);
    hp[threadIdx.x*2]   = __nv_bfloat162(h0, h1);
    hp[threadIdx.x*2+1] = __nv_bfloat162(h2, h3);
    lp[threadIdx.x*2]   = __nv_bfloat162(l0, l1);
    lp[threadIdx.x*2+1] = __nv_bfloat162(l2, l3);
}

// RMSNorm fp32 out + fused router
__global__ void rmsnorm_router_kernel(const float* __restrict__ in, float* __restrict__ outf,
                                      const float* __restrict__ Wr) {
    int t = blockIdx.x;
    const float4* ip = (const float4*)(in + (size_t)t * C);
    __shared__ float red[8];
    __shared__ float lred[32];
    float4 v = ip[threadIdx.x];
    float ss = v.x*v.x + v.y*v.y + v.z*v.z + v.w*v.w;
    #pragma unroll
    for (int o = 16; o; o >>= 1) ss += __shfl_xor_sync(0xffffffffu, ss, o);
    if ((threadIdx.x & 31) == 0) red[threadIdx.x >> 5] = ss;
    __syncthreads();
    if (threadIdx.x == 0) {
        float s = 0.f;
        #pragma unroll
        for (int w = 0; w < 8; w++) s += red[w];
        red[0] = s;
    }
    __syncthreads();
    float r = rsqrtf(red[0] / (float)C + EPS_RMS);
    float4 o = make_float4(v.x*r, v.y*r, v.z*r, v.w*r);
    ((float4*)(outf + (size_t)t * C))[threadIdx.x] = o;

    int c0 = threadIdx.x * 4;
    float4 w0 = *(const float4*)(Wr + (size_t)(c0+0) * E);
    float4 w1 = *(const float4*)(Wr + (size_t)(c0+1) * E);
    float4 w2 = *(const float4*)(Wr + (size_t)(c0+2) * E);
    float4 w3 = *(const float4*)(Wr + (size_t)(c0+3) * E);
    float a0 = o.x*w0.x + o.y*w1.x + o.z*w2.x + o.w*w3.x;
    float a1 = o.x*w0.y + o.y*w1.y + o.z*w2.y + o.w*w3.y;
    float a2 = o.x*w0.z + o.y*w1.z + o.z*w2.z + o.w*w3.z;
    float a3 = o.x*w0.w + o.y*w1.w + o.z*w2.w + o.w*w3.w;
    #pragma unroll
    for (int off = 16; off; off >>= 1) {
        a0 += __shfl_xor_sync(0xffffffffu, a0, off);
        a1 += __shfl_xor_sync(0xffffffffu, a1, off);
        a2 += __shfl_xor_sync(0xffffffffu, a2, off);
        a3 += __shfl_xor_sync(0xffffffffu, a3, off);
    }
    if ((threadIdx.x & 31) == 0) {
        int w = threadIdx.x >> 5;
        lred[w*4+0] = a0; lred[w*4+1] = a1; lred[w*4+2] = a2; lred[w*4+3] = a3;
    }
    __syncthreads();
    if (threadIdx.x == 0) {
        float lg[4];
        #pragma unroll
        for (int e = 0; e < 4; e++) {
            float s = 0.f;
            #pragma unroll
            for (int w = 0; w < 8; w++) s += lred[w*4+e];
            lg[e] = s;
        }
        int arg = 0;
        #pragma unroll
        for (int e = 1; e < 4; e++) if (lg[e] > lg[arg]) arg = e;
        float m = fmaxf(fmaxf(lg[0], lg[1]), fmaxf(lg[2], lg[3]));
        float ez[4]; float sum = 0.f;
        #pragma unroll
        for (int e = 0; e < 4; e++) { ez[e] = expf(lg[e] - m); sum += ez[e]; }
        float p[4];
        #pragma unroll
        for (int e = 0; e < 4; e++) p[e] = ez[e] / sum;
        g_expert[t] = arg;
        atomicAdd(&g_counts[arg], 1);
        #pragma unroll
        for (int e = 0; e < 4; e++) atomicAdd(&g_expsum[e], (double)p[e]);
        float lse = m + logf(sum);
        atomicAdd(&g_zsum, (double)lse * (double)lse);
        float ent = 0.f;
        #pragma unroll
        for (int e = 0; e < 4; e++) ent -= p[e] * logf(p[e] + 1e-9f);
        atomicAdd(&g_entsum, (double)ent);
    }
}

// per-head RMSNorm + RoPE; reads qk buffer [BT, 2048]
__global__ void qk_rope_kernel(const float* __restrict__ qk,
                               __nv_bfloat16* __restrict__ qhi, __nv_bfloat16* __restrict__ qlo,
                               __nv_bfloat16* __restrict__ khi, __nv_bfloat16* __restrict__ klo) {
    int tok  = blockIdx.x;
    int head = threadIdx.x >> 5;
    int lane = threadIdx.x & 31;
    int tpos = tok % T;
    float ex  = (float)(2 * lane) / 64.0f;
    float inv = 1.0f / powf(10000.0f, ex);
    float ang = (float)tpos * inv;
    float c = cosf(ang), s = sinf(ang);
    size_t obase = (size_t)tok * C + head * D;
    #pragma unroll
    for (int m = 0; m < 2; m++) {
        const float* src = qk + (size_t)tok * 2048 + m * 1024 + head * D;
        __nv_bfloat16* dh = (m == 0 ? qhi : khi) + obase;
        __nv_bfloat16* dl = (m == 0 ? qlo : klo) + obase;
        float x1 = src[lane], x2 = src[lane + 32];
        float ss = x1*x1 + x2*x2;
        #pragma unroll
        for (int o = 16; o; o >>= 1) ss += __shfl_xor_sync(0xffffffffu, ss, o);
        float r = rsqrtf(ss / (float)D + EPS_RMS);
        x1 *= r; x2 *= r;
        float o1 =  x1 * c + x2 * s;
        float o2 = -x1 * s + x2 * c;
        __nv_bfloat16 h, l;
        bsplit(o1, h, l); dh[lane] = h;      dl[lane] = l;
        bsplit(o2, h, l); dh[lane + 32] = h; dl[lane + 32] = l;
    }
}

// ======================= HMMA flash attention (bf16x3) =======================
#define AT_QHI 0
#define AT_QLO 16384
#define AT_STG 32768
#define AT_STGSZ 32768
#define AT_KHI 0
#define AT_KLO 8192
#define AT_VHI 16384
#define AT_VLO 24576
#define ATT_SMEM (32768 + 2*32768)

__global__ void __launch_bounds__(256) attn_mma_kernel(
    const __nv_bfloat16* __restrict__ qhi, const __nv_bfloat16* __restrict__ qlo,
    const __nv_bfloat16* __restrict__ khi, const __nv_bfloat16* __restrict__ klo,
    const __nv_bfloat16* __restrict__ vhi, const __nv_bfloat16* __restrict__ vlo,
    __nv_bfloat16* __restrict__ yhi, __nv_bfloat16* __restrict__ ylo)
{
    extern __shared__ __align__(1024) char smem[];
    uint32_t sb = smem_to_u32(smem);
    int bh = blockIdx.y;
    int b = bh / H, hh = bh % H;
    int qb = blockIdx.x;
    int q0 = qb * 128;
    int tid = threadIdx.x, wid = tid >> 5, lid = tid & 31;
    int nkt = 2 * qb + 2;

    #pragma unroll
    for (int i = 0; i < 4; i++) {
        int lin = tid + i * 256;
        int r = lin >> 3, ch = lin & 7;
        uint32_t so = SMEM_SWIZZLE_128B((uint32_t)(r * 128 + ch * 16));
        size_t g = (size_t)(b*T + q0 + r) * C + hh * D + ch * 8;
        CP16(sb + AT_QHI + so, qhi + g);
        CP16(sb + AT_QLO + so, qlo + g);
    }
    asm volatile("cp.async.commit_group;" ::: "memory");
    #pragma unroll
    for (int i = 0; i < 2; i++) {
        int lin = tid + i * 256;
        int r = lin >> 3, ch = lin & 7;
        uint32_t so = SMEM_SWIZZLE_128B((uint32_t)(r * 128 + ch * 16));
        size_t g = (size_t)(b*T + r) * C + hh * D + ch * 8;
        uint32_t st = sb + AT_STG;
        CP16(st + AT_KHI + so, khi + g);
        CP16(st + AT_KLO + so, klo + g);
        CP16(st + AT_VHI + so, vhi + g);
        CP16(st + AT_VLO + so, vlo + g);
    }
    asm volatile("cp.async.commit_group;" ::: "memory");

    uint32_t qa_hi[4][4], qa_lo[4][4];
    float oac[8][4];
    #pragma unroll
    for (int j = 0; j < 8; j++)
        #pragma unroll
        for (int r = 0; r < 4; r++) oac[j][r] = 0.f;
    float m0 = -1e30f, m1 = -1e30f, l0 = 0.f, l1 = 0.f;

    int off = lid & 7, part = lid >> 3;
    int qr = lid >> 2, qc = (lid & 3) * 2;
    const float SC2 = 0.18033688011112042f;

    for (int kt = 0; kt < nkt; kt++) {
        if (kt + 1 < nkt) {
            #pragma unroll
            for (int i = 0; i < 2; i++) {
                int lin = tid + i * 256;
                int r = lin >> 3, ch = lin & 7;
                uint32_t so = SMEM_SWIZZLE_128B((uint32_t)(r * 128 + ch * 16));
                size_t g = (size_t)(b*T + (kt + 1) * 64 + r) * C + hh * D + ch * 8;
                uint32_t st = sb + AT_STG + (uint32_t)((kt + 1) & 1) * AT_STGSZ;
                CP16(st + AT_KHI + so, khi + g);
                CP16(st + AT_KLO + so, klo + g);
                CP16(st + AT_VHI + so, vhi + g);
                CP16(st + AT_VLO + so, vlo + g);
            }
            asm volatile("cp.async.commit_group;" ::: "memory");
            asm volatile("cp.async.wait_group 1;" ::: "memory");
        } else {
            asm volatile("cp.async.wait_group 0;" ::: "memory");
        }
        __syncthreads();

        if (kt == 0) {
            #pragma unroll
            for (int kk = 0; kk < 4; kk++) {
                int row = wid * 16 + (part & 1) * 8 + off;
                int colb = kk * 32 + (part & 2) * 8;
                uint32_t so = SMEM_SWIZZLE_128B((uint32_t)(row * 128 + colb));
                ldsm4(qa_hi[kk], sb + AT_QHI + so);
                ldsm4(qa_lo[kk], sb + AT_QLO + so);
            }
        }

        uint32_t st = sb + AT_STG + (uint32_t)(kt & 1) * AT_STGSZ;

        float s[8][4];
        #pragma unroll
        for (int j = 0; j < 8; j++)
            #pragma unroll
            for (int r = 0; r < 4; r++) s[j][r] = 0.f;
        #pragma unroll
        for (int kk = 0; kk < 4; kk++) {
            #pragma unroll
            for (int jj = 0; jj < 4; jj++) {
                int row = jj * 16 + (part & 2) * 4 + off;
                int colb = kk * 32 + (part & 1) * 16;
                uint32_t so = SMEM_SWIZZLE_128B((uint32_t)(row * 128 + colb));
                uint32_t kh[4], kl[4];
                ldsm4(kh, st + AT_KHI + so);
                ldsm4(kl, st + AT_KLO + so);
                mma_bf16(s[2*jj],     qa_hi[kk], kh);
                mma_bf16(s[2*jj],     qa_hi[kk], kl);
                mma_bf16(s[2*jj],     qa_lo[kk], kh);
                mma_bf16(s[2*jj+1],   qa_hi[kk], kh + 2);
                mma_bf16(s[2*jj+1],   qa_hi[kk], kl + 2);
                mma_bf16(s[2*jj+1],   qa_lo[kk], kh + 2);
            }
        }

        bool domask = (kt >= nkt - 2);
        #pragma unroll
        for (int j = 0; j < 8; j++) {
            #pragma unroll
            for (int r = 0; r < 4; r++) {
                float v = s[j][r] * SC2;
                if (domask) {
                    int key = kt * 64 + j * 8 + qc + (r & 1);
                    int row = q0 + wid * 16 + qr + (r & 2) * 4;
                    if (key > row) v = -1e30f;
                }
                s[j][r] = v;
            }
        }

        float mx0 = -1e30f, mx1 = -1e30f;
        #pragma unroll
        for (int j = 0; j < 8; j++) {
            mx0 = fmaxf(mx0, fmaxf(s[j][0], s[j][1]));
            mx1 = fmaxf(mx1, fmaxf(s[j][2], s[j][3]));
        }
        mx0 = fmaxf(mx0, __shfl_xor_sync(0xffffffffu, mx0, 1));
        mx0 = fmaxf(mx0, __shfl_xor_sync(0xffffffffu, mx0, 2));
        mx1 = fmaxf(mx1, __shfl_xor_sync(0xffffffffu, mx1, 1));
        mx1 = fmaxf(mx1, __shfl_xor_sync(0xffffffffu, mx1, 2));
        float mn0 = fmaxf(m0, mx0), mn1 = fmaxf(m1, mx1);
        float al0 = ex2f(m0 - mn0), al1 = ex2f(m1 - mn1);
        float sm0 = 0.f, sm1 = 0.f;
        #pragma unroll
        for (int j = 0; j < 8; j++) {
            s[j][0] = ex2f(s[j][0] - mn0); sm0 += s[j][0];
            s[j][1] = ex2f(s[j][1] - mn0); sm0 += s[j][1];
            s[j][2] = ex2f(s[j][2] - mn1); sm1 += s[j][2];
            s[j][3] = ex2f(s[j][3] - mn1); sm1 += s[j][3];
        }
        sm0 += __shfl_xor_sync(0xffffffffu, sm0, 1);
        sm0 += __shfl_xor_sync(0xffffffffu, sm0, 2);
        sm1 += __shfl_xor_sync(0xffffffffu, sm1, 1);
        sm1 += __shfl_xor_sync(0xffffffffu, sm1, 2);
        l0 = l0 * al0 + sm0;  l1 = l1 * al1 + sm1;
        m0 = mn0;  m1 = mn1;
        #pragma unroll
        for (int j = 0; j < 8; j++) {
            oac[j][0] *= al0; oac[j][1] *= al0;
            oac[j][2] *= al1; oac[j][3] *= al1;
        }

        #pragma unroll
        for (int kk = 0; kk < 4; kk++) {
            uint32_t pah[4], pal[4];
            packsplit(s[2*kk][0],   s[2*kk][1],   pah[0], pal[0]);
            packsplit(s[2*kk][2],   s[2*kk][3],   pah[1], pal[1]);
            packsplit(s[2*kk+1][0], s[2*kk+1][1], pah[2], pal[2]);
            packsplit(s[2*kk+1][2], s[2*kk+1][3], pah[3], pal[3]);
            #pragma unroll
            for (int jj = 0; jj < 4; jj++) {
                int row = kk * 16 + (part & 1) * 8 + off;
                int colb = jj * 32 + (part & 2) * 8;
                uint32_t so = SMEM_SWIZZLE_128B((uint32_t)(row * 128 + colb));
                uint32_t vh[4], vl[4];
                ldsm4t(vh, st + AT_VHI + so);
                ldsm4t(vl, st + AT_VLO + so);
                mma_bf16(oac[2*jj],   pah, vh);
                mma_bf16(oac[2*jj],   pah, vl);
                mma_bf16(oac[2*jj],   pal, vh);
                mma_bf16(oac[2*jj+1], pah, vh + 2);
                mma_bf16(oac[2*jj+1], pah, vl + 2);
                mma_bf16(oac[2*jj+1], pal, vh + 2);
            }
        }
        __syncthreads();
    }

    float inv0 = 1.f / l0, inv1 = 1.f / l1;
    #pragma unroll
    for (int j = 0; j < 8; j++) {
        size_t i0 = (size_t)(b*T + q0 + wid*16 + qr) * C + hh * D + j * 8 + qc;
        size_t i1 = (size_t)(b*T + q0 + wid*16 + qr + 8) * C + hh * D + j * 8 + qc;
        uint32_t ph, pl;
        packsplit(oac[j][0] * inv0, oac[j][1] * inv0, ph, pl);
        *(uint32_t*)(yhi + i0) = ph;  *(uint32_t*)(ylo + i0) = pl;
        packsplit(oac[j][2] * inv1, oac[j][3] * inv1, ph, pl);
        *(uint32_t*)(yhi + i1) = ph;  *(uint32_t*)(ylo + i1) = pl;
    }
}

// ======================= HMMA bf16x3 GEMM — 128x256 block tile =======================
// warp tile 64x64, 8 warps (2 m x 4 n). ldsm:mma = 1:6.
// epi: 0 fp32; 1 fp32+resid; 2 relu(acc)^2 -> bf16 pair; 3 acc -> bf16 pair;
//      4 fused QKV: cols [0,2048) fp32 stride 2048, cols [2048,3072) bf16 pair stride 1024
#define KTILE 64
#define W_AH 0
#define W_AL 16384
#define W_BH 32768
#define W_BL 65536
#define W_STAGE 98304
#define SMEM_GEMM_BYTES (2*W_STAGE)

__global__ void __launch_bounds__(256, 1) gemm_bf16x3(
    const __nv_bfloat16* __restrict__ Ahi, const __nv_bfloat16* __restrict__ Alo,
    const __nv_bfloat16* __restrict__ Bhi, const __nv_bfloat16* __restrict__ Blo,
    size_t bstride,
    float* __restrict__ Cout,
    __nv_bfloat16* __restrict__ Ohi, __nv_bfloat16* __restrict__ Olo,
    const float* __restrict__ resid,
    const int* __restrict__ tileExpert,
    int N, int K, int epi)
{
    extern __shared__ __align__(1024) char smem[];
    int by = blockIdx.y, bx = blockIdx.x;
    int e = 0;
    if (tileExpert) { e = tileExpert[by]; if (e < 0) return; }
    const __nv_bfloat16* Bh = Bhi + (size_t)e * bstride;
    const __nv_bfloat16* Bl = Blo + (size_t)e * bstride;

    uint32_t sb = smem_to_u32(smem);
    int tid = threadIdx.x, wid = tid >> 5, lid = tid & 31;
    int wm = wid & 1, wn = wid >> 1;
    int row0 = by * 128, col0 = bx * 256;
    int nkt = K / KTILE;

    float acc[4][8][4];
    #pragma unroll
    for (int i = 0; i < 4; i++)
        #pragma unroll
        for (int j = 0; j < 8; j++)
            #pragma unroll
            for (int r = 0; r < 4; r++) acc[i][j][r] = 0.f;

    int lr = tid >> 3, lc = tid & 7;

    // preload stage 0
    {
        #pragma unroll
        for (int i = 0; i < 4; i++) {               // A: 128 rows
            int r = lr + i * 32;
            uint32_t so = SMEM_SWIZZLE_128B((uint32_t)(r * 128 + lc * 16));
            size_t ga = (size_t)(row0 + r) * K + lc * 8;
            CP16(sb + W_AH + so, Ahi + ga);
            CP16(sb + W_AL + so, Alo + ga);
        }
        #pragma unroll
        for (int i = 0; i < 8; i++) {               // B: 256 rows
            int r = lr + i * 32;
            uint32_t so = SMEM_SWIZZLE_128B((uint32_t)(r * 128 + lc * 16));
            size_t gb = (size_t)(col0 + r) * K + lc * 8;
            CP16(sb + W_BH + so, Bh + gb);
            CP16(sb + W_BL + so, Bl + gb);
        }
        asm volatile("cp.async.commit_group;" ::: "memory");
    }

    for (int kt = 0; kt < nkt; kt++) {
        uint32_t cur = (uint32_t)(kt & 1) * W_STAGE;
        if (kt + 1 < nkt) {
            uint32_t nxt = (uint32_t)((kt + 1) & 1) * W_STAGE;
            int k0 = (kt + 1) * KTILE;
            #pragma unroll
            for (int i = 0; i < 4; i++) {
                int r = lr + i * 32;
                uint32_t so = SMEM_SWIZZLE_128B((uint32_t)(r * 128 + lc * 16));
                size_t ga = (size_t)(row0 + r) * K + k0 + lc * 8;
                CP16(sb + nxt + W_AH + so, Ahi + ga);
                CP16(sb + nxt + W_AL + so, Alo + ga);
            }
            #pragma unroll
            for (int i = 0; i < 8; i++) {
                int r = lr + i * 32;
                uint32_t so = SMEM_SWIZZLE_128B((uint32_t)(r * 128 + lc * 16));
                size_t gb = (size_t)(col0 + r) * K + k0 + lc * 8;
                CP16(sb + nxt + W_BH + so, Bh + gb);
                CP16(sb + nxt + W_BL + so, Bl + gb);
            }
            asm volatile("cp.async.commit_group;" ::: "memory");
            asm volatile("cp.async.wait_group 1;" ::: "memory");
        } else {
            asm volatile("cp.async.wait_group 0;" ::: "memory");
        }
        __syncthreads();

        uint32_t sAH = sb + cur + W_AH, sAL = sb + cur + W_AL;
        uint32_t sBH = sb + cur + W_BH, sBL = sb + cur + W_BL;
        #pragma unroll
        for (int kk = 0; kk < 4; kk++) {
            int colb = (kk * 16 + (lid >> 4) * 8) * 2;
            uint32_t a_hi[4][4], a_lo[4][4];
            #pragma unroll
            for (int mf = 0; mf < 4; mf++) {
                int rowm = wm * 64 + mf * 16 + (lid & 15);
                uint32_t so = SMEM_SWIZZLE_128B((uint32_t)(rowm * 128 + colb));
                ldsm4(a_hi[mf], sAH + so);
                ldsm4(a_lo[mf], sAL + so);
            }
            uint32_t b_hi[8][2], b_lo[8][2];
            #pragma unroll
            for (int g = 0; g < 4; g++) {
                int rown = wn * 64 + g * 16 + (lid & 15);
                uint32_t so = SMEM_SWIZZLE_128B((uint32_t)(rown * 128 + colb));
                uint32_t r4[4];
                ldsm4(r4, sBH + so);
                b_hi[2*g][0] = r4[0]; b_hi[2*g+1][0] = r4[1];
                b_hi[2*g][1] = r4[2]; b_hi[2*g+1][1] = r4[3];
                ldsm4(r4, sBL + so);
                b_lo[2*g][0] = r4[0]; b_lo[2*g+1][0] = r4[1];
                b_lo[2*g][1] = r4[2]; b_lo[2*g+1][1] = r4[3];
            }
            #pragma unroll
            for (int mf = 0; mf < 4; mf++)
                #pragma unroll
                for (int nf = 0; nf < 8; nf++) {
                    mma_bf16(acc[mf][nf], a_hi[mf], b_hi[nf]);
                    mma_bf16(acc[mf][nf], a_hi[mf], b_lo[nf]);
                    mma_bf16(acc[mf][nf], a_lo[mf], b_hi[nf]);
                }
        }
        __syncthreads();
    }

    int qr = lid >> 2, qc = (lid & 3) * 2;
    #pragma unroll
    for (int mf = 0; mf < 4; mf++) {
        #pragma unroll
        for (int nf = 0; nf < 8; nf++) {
            float* cc = acc[mf][nf];
            int col = col0 + wn * 64 + nf * 8 + qc;
            #pragma unroll
            for (int half = 0; half < 2; half++) {
                int row = row0 + wm * 64 + mf * 16 + qr + half * 8;
                float v0 = cc[2*half], v1 = cc[2*half + 1];
                if (epi == 0) {
                    size_t idx = (size_t)row * N + col;
                    *(float2*)(Cout + idx) = make_float2(v0, v1);
                } else if (epi == 1) {
                    size_t idx = (size_t)row * N + col;
                    float2 rr = *(const float2*)(resid + idx);
                    *(float2*)(Cout + idx) = make_float2(v0 + rr.x, v1 + rr.y);
                } else if (epi == 4) {
                    if (col < 2048) {
                        size_t idx = (size_t)row * 2048 + col;
                        *(float2*)(Cout + idx) = make_float2(v0, v1);
                    } else {
                        size_t idx = (size_t)row * 1024 + (col - 2048);
                        uint32_t ph, pl;
                        packsplit(v0, v1, ph, pl);
                        *(uint32_t*)(Ohi + idx) = ph;
                        *(uint32_t*)(Olo + idx) = pl;
                    }
                } else {
                    if (epi == 2) {
                        v0 = fmaxf(v0, 0.f); v0 *= v0;
                        v1 = fmaxf(v1, 0.f); v1 *= v1;
                    }
                    size_t idx = (size_t)row * N + col;
                    uint32_t ph, pl;
                    packsplit(v0, v1, ph, pl);
                    *(uint32_t*)(Ohi + idx) = ph;
                    *(uint32_t*)(Olo + idx) = pl;
                }
            }
        }
    }
}

// ======================= grouping / scatter / scalars =======================
__global__ void offsets_kernel() {
    if (threadIdx.x == 0 && blockIdx.x == 0) {
        int off = 0;
        for (int e = 0; e < E; e++) {
            g_segstart[e] = off;
            int padded = (g_counts[e] + 127) & ~127;
            for (int i = 0; i < padded / 128; i++)
                g_tileExpert[off / 128 + i] = e;
            off += padded;
        }
    }
}

__global__ void assign_kernel(const float* __restrict__ h2) {
    int t = blockIdx.x;
    __shared__ int slot_s;
    if (threadIdx.x == 0) {
        int e = g_expert[t];
        int slot = g_segstart[e] + atomicAdd(&g_cursor[e], 1);
        g_tokenOfRow[slot] = t;
        slot_s = slot;
    }
    __syncthreads();
    int s = slot_s;
    float4 v = ((const float4*)(h2 + (size_t)t * C))[threadIdx.x];
    __nv_bfloat16 h0,l0,h1,l1,h2b,l2,h3,l3;
    bsplit(v.x,h0,l0); bsplit(v.y,h1,l1); bsplit(v.z,h2b,l2); bsplit(v.w,h3,l3);
    __nv_bfloat162* hp = (__nv_bfloat162*)(g_h2g_hi + (size_t)s * C);
    __nv_bfloat162* lp = (__nv_bfloat162*)(g_h2g_lo + (size_t)s * C);
    hp[threadIdx.x*2]   = __nv_bfloat162(h0, h1);
    hp[threadIdx.x*2+1] = __nv_bfloat162(h2b, h3);
    lp[threadIdx.x*2]   = __nv_bfloat162(l0, l1);
    lp[threadIdx.x*2+1] = __nv_bfloat162(l2, l3);
}

__global__ void scatter_kernel(const float* __restrict__ x2, float* __restrict__ out) {
    int r = blockIdx.x;
    int t = g_tokenOfRow[r];
    if (t < 0) return;
    float4 a = ((const float4*)(x2 + (size_t)t * C))[threadIdx.x];
    float4 b = ((const float4*)(g_outg + (size_t)r * C))[threadIdx.x];
    ((float4*)(out + (size_t)t * C))[threadIdx.x] =
        make_float4(a.x + b.x, a.y + b.y, a.z + b.z, a.w + b.w);
}

__global__ void scalars_kernel(float* __restrict__ out) {
    if (threadIdx.x == 0 && blockIdx.x == 0) {
        const double NTOK = (double)BT;
        double aux = 0.0;
        for (int e = 0; e < E; e++) {
            double actual = (double)g_counts[e] / NTOK;
            double expd   = g_expsum[e] / NTOK;
            aux += actual * expd;
        }
        size_t base = (size_t)BT * C;
        out[base + 0] = (float)((double)E * aux);
        out[base + 1] = (float)(g_zsum / NTOK);
        out[base + 2] = (float)((g_entsum / NTOK) / log((double)E));
        for (int e = 0; e < E; e++)
            out[base + 3 + e] = (float)((double)g_counts[e] / NTOK);
    }
}

// ======================= launch =======================
static void* sym(const void* s) { void* p = nullptr; cudaGetSymbolAddress(&p, s); return p; }

extern "C" void kernel_launch(void* const* d_in, const int* in_sizes, int n_in,
                              void* d_out, int out_size)
{
    const float* x     = (const float*)d_in[0];
    const float* Wq    = (const float*)d_in[1];
    const float* Wk    = (const float*)d_in[2];
    const float* Wv    = (const float*)d_in[3];
    const float* Wo    = (const float*)d_in[4];
    const float* Wr    = (const float*)d_in[5];
    const float* Wfc   = (const float*)d_in[6];
    const float* Wproj = (const float*)d_in[7];
    float* out = (float*)d_out;

    static bool attr_set = false;
    if (!attr_set) {
        cudaFuncSetAttribute(gemm_bf16x3, cudaFuncAttributeMaxDynamicSharedMemorySize, SMEM_GEMM_BYTES);
        cudaFuncSetAttribute(attn_mma_kernel, cudaFuncAttributeMaxDynamicSharedMemorySize, ATT_SMEM);
        attr_set = true;
    }

    __nv_bfloat16* h1h = (__nv_bfloat16*)sym(g_h1_hi);
    __nv_bfloat16* h1l = (__nv_bfloat16*)sym(g_h1_lo);
    float* qk = (float*)sym(g_qk);
    __nv_bfloat16* qh = (__nv_bfloat16*)sym(g_qhi); __nv_bfloat16* ql = (__nv_bfloat16*)sym(g_qlo);
    __nv_bfloat16* kh = (__nv_bfloat16*)sym(g_khi); __nv_bfloat16* kl = (__nv_bfloat16*)sym(g_klo);
    __nv_bfloat16* vh = (__nv_bfloat16*)sym(g_vhi); __nv_bfloat16* vl = (__nv_bfloat16*)sym(g_vlo);
    __nv_bfloat16* yh = (__nv_bfloat16*)sym(g_y_hi);
    __nv_bfloat16* yl = (__nv_bfloat16*)sym(g_y_lo);
    float* x2 = (float*)sym(g_x2);
    float* h2 = (float*)sym(g_h2);
    __nv_bfloat16* h2gh = (__nv_bfloat16*)sym(g_h2g_hi);
    __nv_bfloat16* h2gl = (__nv_bfloat16*)sym(g_h2g_lo);
    __nv_bfloat16* hidh = (__nv_bfloat16*)sym(g_hid_hi);
    __nv_bfloat16* hidl = (__nv_bfloat16*)sym(g_hid_lo);
    float* outg = (float*)sym(g_outg);
    __nv_bfloat16* wqkvh = (__nv_bfloat16*)sym(g_wqkv_hi);
    __nv_bfloat16* wqkvl = (__nv_bfloat16*)sym(g_wqkv_lo);
    __nv_bfloat16* woh = (__nv_bfloat16*)sym(g_wo_hi); __nv_bfloat16* wol = (__nv_bfloat16*)sym(g_wo_lo);
    __nv_bfloat16* wfh = (__nv_bfloat16*)sym(g_wfc_hi); __nv_bfloat16* wfl = (__nv_bfloat16*)sym(g_wfc_lo);
    __nv_bfloat16* wph = (__nv_bfloat16*)sym(g_wpj_hi); __nv_bfloat16* wpl = (__nv_bfloat16*)sym(g_wpj_lo);
    int* tileE = (int*)sym(g_tileExpert);

    reset_kernel<<<(GROUP_CAP + 255) / 256, 256>>>();                          // 1
    rmsnorm_kernel<<<BT, 256>>>(x, h1h, h1l);                                  // 2
    wconv_kernel<<<dim3(C/64, C/64, 1), 256>>>(Wq, wqkvh,         wqkvl,         C, C);
    wconv_kernel<<<dim3(C/64, C/64, 1), 256>>>(Wk, wqkvh + C*C,   wqkvl + C*C,   C, C);
    wconv_kernel<<<dim3(C/64, C/64, 1), 256>>>(Wv, wqkvh + 2*C*C, wqkvl + 2*C*C, C, C);
    wconv_kernel<<<dim3(C/64,  C/64,  1), 256>>>(Wo,    woh, wol, C,  C);
    wconv_kernel<<<dim3(FF/64, C/64,  E), 256>>>(Wfc,   wfh, wfl, C,  FF);
    wconv_kernel<<<dim3(C/64,  FF/64, E), 256>>>(Wproj, wph, wpl, FF, C);
    // fused QKV GEMM (N=3072)
    gemm_bf16x3<<<dim3(3*C/256, BT/128), 256, SMEM_GEMM_BYTES>>>(
        h1h, h1l, wqkvh, wqkvl, 0, qk, vh, vl, nullptr, nullptr, 3*C, C, 4);
    qk_rope_kernel<<<BT, 512>>>(qk, qh, ql, kh, kl);
    attn_mma_kernel<<<dim3(T/128, Bq*H), 256, ATT_SMEM>>>(
        qh, ql, kh, kl, vh, vl, yh, yl);
    gemm_bf16x3<<<dim3(C/256, BT/128), 256, SMEM_GEMM_BYTES>>>(
        yh, yl, woh, wol, 0, x2, nullptr, nullptr, x, nullptr, C, C, 1);
    rmsnorm_router_kernel<<<BT, 256>>>(x2, h2, Wr);
    offsets_kernel<<<1, 32>>>();
    assign_kernel<<<BT, 256>>>(h2);
    zero_pad_kernel<<<GROUP_CAP, 256>>>();
    gemm_bf16x3<<<dim3(FF/256, NTILES), 256, SMEM_GEMM_BYTES>>>(
        h2gh, h2gl, wfh, wfl, (size_t)FF * C, nullptr, hidh, hidl, nullptr, tileE, FF, C, 2);
    gemm_bf16x3<<<dim3(C/256, NTILES), 256, SMEM_GEMM_BYTES>>>(
        hidh, hidl, wph, wpl, (size_t)C * FF, outg, nullptr, nullptr, nullptr, tileE, C, FF, 0);
    scatter_kernel<<<GROUP_CAP, 256>>>(x2, out);
    scalars_kernel<<<1, 32>>>(out);
}